// round 4
// baseline (speedup 1.0000x reference)
#include <cuda_runtime.h>
#include <math.h>

#define B_ 256
#define N_ 36
#define F_ 2048
#define L_ 26
#define A_ 512
#define E_ 1024
#define D_ 1024
#define V_ 10000
#define T_ 25
#define G_ 4096   // 4*D

// ---------------- static device scratch (no allocation allowed) ----------------
__device__ __align__(256) float g_fs[(size_t)B_ * N_ * F_];      // sorted feats
__device__ __align__(256) float g_favg[B_ * F_];
__device__ __align__(256) float g_favgW[B_ * G_];                // favg @ Wf^T + td_b
__device__ __align__(256) float g_ebd[(size_t)B_ * T_ * E_];     // gathered embeddings
__device__ __align__(256) float g_xe1[(size_t)B_ * T_ * G_];     // precomputed LSTM1 input-gate part
__device__ __align__(256) float g_imgatt[(size_t)B_ * N_ * A_];
__device__ __align__(256) float g_h1[B_ * D_], g_c1[B_ * D_], g_h2[B_ * D_], g_c2[B_ * D_];
__device__ __align__(256) float g_arh[B_ * D_], g_arc[B_ * D_], g_prevh1[B_ * D_];
__device__ __align__(256) float g_h1n[B_ * D_], g_c1n[B_ * D_], g_h2n[B_ * D_], g_c2n[B_ * D_];
__device__ __align__(256) float g_arhn[B_ * D_], g_arcn[B_ * D_];
__device__ __align__(256) float g_gates1[B_ * G_], g_gates2[B_ * G_], g_gates3[B_ * G_];
__device__ __align__(256) float g_q[B_ * A_];
__device__ __align__(256) float g_aw[B_ * F_];
__device__ __align__(256) float g_H2[(size_t)B_ * T_ * D_];
__device__ __align__(256) float g_ARHN[(size_t)B_ * T_ * D_];
__device__ __align__(256) float g_PREV[(size_t)B_ * T_ * D_];
__device__ __align__(256) float g_ARL[(size_t)B_ * T_ * D_];
__device__ __align__(256) float g_rowss[B_ * T_];
__device__ int g_order[B_];
__device__ int g_declen[B_];
__device__ unsigned char g_act[B_ * T_];

// ---------------- small helpers ----------------
__device__ __forceinline__ float sigm(float x) { return 1.f / (1.f + expf(-x)); }

// ---------------- setup kernels ----------------
__global__ void sort_k(const int* __restrict__ sizes) {
    __shared__ int s[B_];
    int i = threadIdx.x;
    s[i] = sizes[i];
    __syncthreads();
    int my = s[i];
    int rank = 0;
    for (int j = 0; j < B_; ++j) {
        int sj = s[j];
        if (sj > my || (sj == my && j < i)) rank++;
    }
    g_order[rank] = i;
    g_declen[rank] = my - 1;
}

__global__ void init_act_k() {
    int idx = blockIdx.x * blockDim.x + threadIdx.x;
    if (idx < B_ * T_) {
        int b = idx / T_, t = idx - b * T_;
        g_act[idx] = (t < g_declen[b]) ? 1 : 0;
    }
}

__global__ void zero_carries_k() {
    int idx = blockIdx.x * blockDim.x + threadIdx.x;
    if (idx < B_ * D_) {
        g_h1[idx] = 0.f; g_c1[idx] = 0.f; g_h2[idx] = 0.f; g_c2[idx] = 0.f;
        g_arh[idx] = 0.f; g_arc[idx] = 0.f; g_prevh1[idx] = 0.f;
    }
}

__global__ void gather_fs_k(const float4* __restrict__ feats) {
    const int per_b = N_ * F_ / 4;
    size_t total = (size_t)B_ * per_b;
    for (size_t i = (size_t)blockIdx.x * blockDim.x + threadIdx.x; i < total;
         i += (size_t)gridDim.x * blockDim.x) {
        int b = (int)(i / per_b);
        size_t rem = i - (size_t)b * per_b;
        ((float4*)g_fs)[i] = feats[(size_t)g_order[b] * per_b + rem];
    }
}

__global__ void favg_k() {
    int idx = blockIdx.x * blockDim.x + threadIdx.x;
    if (idx < B_ * F_) {
        int b = idx / F_, f = idx - b * F_;
        const float* base = g_fs + (size_t)b * N_ * F_ + f;
        float s = 0.f;
        #pragma unroll
        for (int n = 0; n < N_; ++n) s += base[(size_t)n * F_];
        g_favg[idx] = s * (1.f / N_);
    }
}

__global__ void gather_ebd_k(const int* __restrict__ seqs, const float4* __restrict__ emb) {
    const int per_r = E_ / 4;  // 256
    size_t total = (size_t)B_ * T_ * per_r;
    for (size_t i = (size_t)blockIdx.x * blockDim.x + threadIdx.x; i < total;
         i += (size_t)gridDim.x * blockDim.x) {
        int r = (int)(i / per_r);
        int e4 = (int)(i - (size_t)r * per_r);
        int b = r / T_, t = r - b * T_;
        int sid = seqs[g_order[b] * L_ + t];
        ((float4*)g_ebd)[i] = emb[(size_t)sid * per_r + e4];
    }
}

// xe1 += favgW[b] (td_b already folded into favgW via bias)
__global__ void add_favg_k() {
    const int per_r = G_ / 4;  // 1024
    size_t total = (size_t)B_ * T_ * per_r;
    for (size_t i = (size_t)blockIdx.x * blockDim.x + threadIdx.x; i < total;
         i += (size_t)gridDim.x * blockDim.x) {
        int r = (int)(i / per_r);
        int g4 = (int)(i - (size_t)r * per_r);
        int b = r / T_;
        float4 x = ((float4*)g_xe1)[i];
        float4 a = ((const float4*)g_favgW)[(size_t)b * per_r + g4];
        x.x += a.x; x.y += a.y; x.z += a.z; x.w += a.w;
        ((float4*)g_xe1)[i] = x;
    }
}

// ---------------- generic fp32 GEMM: C[M,N] = A[M,K] @ W[N,K]^T (+ init/bias/mask) ----------------
__global__ void gemm_k(float* __restrict__ C,
                       const float* __restrict__ Cinit, int initLd,
                       const float* __restrict__ A,
                       const float* __restrict__ W, int ldw,
                       const float* __restrict__ bias,
                       const unsigned char* __restrict__ mask,
                       int M, int N, int K, int accum) {
    __shared__ __align__(16) float As[16][64];
    __shared__ __align__(16) float Bs[16][64];
    const int bm = blockIdx.y * 64, bn = blockIdx.x * 64;
    const int tid = threadIdx.x;
    const int tx = tid & 15, ty = tid >> 4;
    const int lrow = tid >> 2, lk = (tid & 3) * 4;
    float acc[4][4] = {};
    for (int k0 = 0; k0 < K; k0 += 16) {
        float4 av = make_float4(0.f, 0.f, 0.f, 0.f);
        float4 bv = make_float4(0.f, 0.f, 0.f, 0.f);
        int am = bm + lrow;
        if (am < M) av = *(const float4*)(A + (size_t)am * K + k0 + lk);
        int wn = bn + lrow;
        if (wn < N) bv = *(const float4*)(W + (size_t)wn * ldw + k0 + lk);
        __syncthreads();
        As[lk][lrow] = av.x; As[lk + 1][lrow] = av.y; As[lk + 2][lrow] = av.z; As[lk + 3][lrow] = av.w;
        Bs[lk][lrow] = bv.x; Bs[lk + 1][lrow] = bv.y; Bs[lk + 2][lrow] = bv.z; Bs[lk + 3][lrow] = bv.w;
        __syncthreads();
        #pragma unroll
        for (int k = 0; k < 16; ++k) {
            float4 a4 = *(const float4*)(&As[k][ty * 4]);
            float4 b4 = *(const float4*)(&Bs[k][tx * 4]);
            acc[0][0] += a4.x * b4.x; acc[0][1] += a4.x * b4.y; acc[0][2] += a4.x * b4.z; acc[0][3] += a4.x * b4.w;
            acc[1][0] += a4.y * b4.x; acc[1][1] += a4.y * b4.y; acc[1][2] += a4.y * b4.z; acc[1][3] += a4.y * b4.w;
            acc[2][0] += a4.z * b4.x; acc[2][1] += a4.z * b4.y; acc[2][2] += a4.z * b4.z; acc[2][3] += a4.z * b4.w;
            acc[3][0] += a4.w * b4.x; acc[3][1] += a4.w * b4.y; acc[3][2] += a4.w * b4.z; acc[3][3] += a4.w * b4.w;
        }
    }
    #pragma unroll
    for (int i = 0; i < 4; ++i) {
        int m = bm + ty * 4 + i;
        if (m >= M) continue;
        #pragma unroll
        for (int j = 0; j < 4; ++j) {
            int n = bn + tx * 4 + j;
            if (n >= N) continue;
            size_t ci = (size_t)m * N + n;
            float v = acc[i][j];
            if (accum) {
                C[ci] += v;
            } else {
                if (bias) v += bias[n];
                if (Cinit) v += Cinit[(size_t)m * initLd + n];
                if (mask) v = mask[m] ? v : 0.f;
                C[ci] = v;
            }
        }
    }
}

// ---------------- LSTM elementwise ----------------
__device__ __forceinline__ void lstm_elem(const float* __restrict__ gates,
                                          const float* __restrict__ c_old,
                                          float* __restrict__ h_new,
                                          float* __restrict__ c_new, int idx) {
    int b = idx / D_, d = idx - b * D_;
    const float* g = gates + (size_t)b * G_;
    float ig = sigm(g[d]);
    float fg = sigm(g[D_ + d]);
    float gg = tanhf(g[2 * D_ + d]);
    float og = sigm(g[3 * D_ + d]);
    float c = fg * c_old[idx] + ig * gg;
    c_new[idx] = c;
    h_new[idx] = og * tanhf(c);
}

__global__ void lstm1_ew_k() {
    int idx = blockIdx.x * blockDim.x + threadIdx.x;
    if (idx < B_ * D_) lstm_elem(g_gates1, g_c1, g_h1n, g_c1n, idx);
}
__global__ void lstm2_ew_k(int t) {
    int idx = blockIdx.x * blockDim.x + threadIdx.x;
    if (idx < B_ * D_) {
        lstm_elem(g_gates2, g_c2, g_h2n, g_c2n, idx);
        int b = idx / D_, d = idx - b * D_;
        g_H2[((size_t)b * T_ + t) * D_ + d] = g_h2n[idx];
    }
}
__global__ void lstm3_ew_k(int t) {
    int idx = blockIdx.x * blockDim.x + threadIdx.x;
    if (idx < B_ * D_) {
        lstm_elem(g_gates3, g_arc, g_arhn, g_arcn, idx);
        int b = idx / D_, d = idx - b * D_;
        g_ARHN[((size_t)b * T_ + t) * D_ + d] = g_arhn[idx];
    }
}

// ---------------- attention: scores -> softmax -> weighted feature sum ----------------
__global__ void attn_k(const float* __restrict__ attw, const float* __restrict__ attb) {
    int b = blockIdx.x;
    int tid = threadIdx.x;
    int warp = tid >> 5, lane = tid & 31;
    __shared__ float s_q[A_];
    __shared__ float s_w[A_];
    __shared__ float s_sc[N_];
    __shared__ float s_alpha[N_];
    for (int i = tid; i < A_; i += 256) { s_q[i] = g_q[b * A_ + i]; s_w[i] = attw[i]; }
    __syncthreads();
    for (int n = warp; n < N_; n += 8) {
        const float* row = g_imgatt + ((size_t)b * N_ + n) * A_;
        float p = 0.f;
        for (int a = lane; a < A_; a += 32) {
            float v = s_q[a] + row[a];
            p += fmaxf(v, 0.f) * s_w[a];
        }
        #pragma unroll
        for (int o = 16; o; o >>= 1) p += __shfl_xor_sync(0xffffffffu, p, o);
        if (lane == 0) s_sc[n] = p + attb[0];
    }
    __syncthreads();
    if (warp == 0) {
        float v0 = s_sc[lane];
        float v1 = (lane + 32 < N_) ? s_sc[lane + 32] : -1e30f;
        float mx = fmaxf(v0, v1);
        #pragma unroll
        for (int o = 16; o; o >>= 1) mx = fmaxf(mx, __shfl_xor_sync(0xffffffffu, mx, o));
        float e0 = expf(v0 - mx);
        float e1 = (lane + 32 < N_) ? expf(v1 - mx) : 0.f;
        float s = e0 + e1;
        #pragma unroll
        for (int o = 16; o; o >>= 1) s += __shfl_xor_sync(0xffffffffu, s, o);
        s_alpha[lane] = e0 / s;
        if (lane + 32 < N_) s_alpha[lane + 32] = e1 / s;
    }
    __syncthreads();
    for (int f = tid; f < F_; f += 256) {
        float acc = 0.f;
        const float* fb = g_fs + (size_t)b * N_ * F_ + f;
        #pragma unroll
        for (int n = 0; n < N_; ++n) acc += s_alpha[n] * fb[(size_t)n * F_];
        g_aw[b * F_ + f] = acc;
    }
}

// ---------------- masked carry commit (+ record prev_h1 used this step) ----------------
__global__ void commit_k(int t) {
    int idx = blockIdx.x * blockDim.x + threadIdx.x;
    if (idx >= B_ * D_) return;
    int b = idx / D_, d = idx - b * D_;
    g_PREV[((size_t)b * T_ + t) * D_ + d] = g_prevh1[idx];
    if (g_act[b * T_ + t]) {
        g_h1[idx] = g_h1n[idx];  g_c1[idx] = g_c1n[idx];
        g_h2[idx] = g_h2n[idx];  g_c2[idx] = g_c2n[idx];
        g_arh[idx] = g_arhn[idx]; g_arc[idx] = g_arcn[idx];
        g_prevh1[idx] = g_h1n[idx];
    }
}

// ---------------- loss ----------------
__global__ void loss_rows_k() {
    int r = blockIdx.x;       // r = b*T + t
    int t = r % T_;
    int tid = threadIdx.x;
    float p = 0.f;
    if (t > 0 && g_act[r]) {
        const float* a = g_ARL + (size_t)r * D_;
        const float* pv = g_PREV + (size_t)r * D_;
        for (int d = tid; d < D_; d += 256) { float df = a[d] - pv[d]; p += df * df; }
    }
    __shared__ float sred[256];
    sred[tid] = p;
    __syncthreads();
    for (int o = 128; o; o >>= 1) { if (tid < o) sred[tid] += sred[tid + o]; __syncthreads(); }
    if (tid == 0) g_rowss[r] = sred[0];
}

__global__ void loss_final_k(float* __restrict__ out) {
    __shared__ float ss[256], sc[256];
    int tid = threadIdx.x;
    float total = 0.f;
    for (int t = 1; t < T_; ++t) {
        float s = 0.f, c = 0.f;
        for (int b = tid; b < B_; b += 256) {
            s += g_rowss[b * T_ + t];
            c += g_act[b * T_ + t] ? 1.f : 0.f;
        }
        ss[tid] = s; sc[tid] = c;
        __syncthreads();
        for (int o = 128; o; o >>= 1) { if (tid < o) { ss[tid] += ss[tid + o]; sc[tid] += sc[tid + o]; } __syncthreads(); }
        if (tid == 0) total += ss[0] / fmaxf(sc[0], 1.f) * 0.005f;
        __syncthreads();
    }
    if (tid == 0) out[(size_t)B_ * T_ * V_] = total;
}

// ---------------- host ----------------
static inline float* fsym(const void* s) { void* p = nullptr; cudaGetSymbolAddress(&p, s); return (float*)p; }

static inline void launch_gemm(float* C, const float* Cinit, int initLd,
                               const float* A, const float* W, int ldw,
                               const float* bias, const unsigned char* mask,
                               int M, int N, int K, int accum) {
    dim3 grid((N + 63) / 64, (M + 63) / 64);
    gemm_k<<<grid, 256>>>(C, Cinit, initLd, A, W, ldw, bias, mask, M, N, K, accum);
}

extern "C" void kernel_launch(void* const* d_in, const int* in_sizes, int n_in,
                              void* d_out, int out_size) {
    const float* feats     = (const float*)d_in[0];
    const int*   sequences = (const int*)d_in[1];
    const int*   sizes     = (const int*)d_in[2];
    const float* emb       = (const float*)d_in[3];
    const float* td_wih    = (const float*)d_in[4];
    const float* td_whh    = (const float*)d_in[5];
    const float* td_b      = (const float*)d_in[6];
    const float* lang_wih  = (const float*)d_in[7];
    const float* lang_whh  = (const float*)d_in[8];
    const float* lang_b    = (const float*)d_in[9];
    const float* attf_w    = (const float*)d_in[10];
    const float* attf_b    = (const float*)d_in[11];
    const float* attd_w    = (const float*)d_in[12];
    const float* attd_b    = (const float*)d_in[13];
    const float* att_w     = (const float*)d_in[14];
    const float* att_b     = (const float*)d_in[15];
    const float* out_w     = (const float*)d_in[16];
    const float* out_b     = (const float*)d_in[17];
    const float* ar_wih    = (const float*)d_in[18];
    const float* ar_whh    = (const float*)d_in[19];
    const float* ar_b      = (const float*)d_in[20];
    const float* arl_w     = (const float*)d_in[21];
    const float* arl_b     = (const float*)d_in[22];
    float* out = (float*)d_out;

    float* p_fs     = fsym(g_fs);
    float* p_favg   = fsym(g_favg);
    float* p_favgW  = fsym(g_favgW);
    float* p_ebd    = fsym(g_ebd);
    float* p_xe1    = fsym(g_xe1);
    float* p_imgatt = fsym(g_imgatt);
    float* p_h1     = fsym(g_h1);
    float* p_h2     = fsym(g_h2);
    float* p_h1n    = fsym(g_h1n);
    float* p_arh    = fsym(g_arh);
    float* p_aw     = fsym(g_aw);
    float* p_q      = fsym(g_q);
    float* p_gates1 = fsym(g_gates1);
    float* p_gates2 = fsym(g_gates2);
    float* p_gates3 = fsym(g_gates3);
    float* p_H2     = fsym(g_H2);
    float* p_ARHN   = fsym(g_ARHN);
    float* p_ARL    = fsym(g_ARL);
    void* p_act_v = nullptr; cudaGetSymbolAddress(&p_act_v, g_act);
    const unsigned char* p_act = (const unsigned char*)p_act_v;

    // ---- setup ----
    sort_k<<<1, B_>>>(sizes);
    init_act_k<<<(B_ * T_ + 255) / 256, 256>>>();
    zero_carries_k<<<(B_ * D_ + 255) / 256, 256>>>();
    gather_fs_k<<<2048, 256>>>((const float4*)feats);
    favg_k<<<(B_ * F_ + 255) / 256, 256>>>();
    gather_ebd_k<<<2048, 256>>>(sequences, (const float4*)emb);

    // favgW = favg @ Wf^T + td_b        (Wf = td_wih cols [D, D+F))
    launch_gemm(p_favgW, nullptr, 0, p_favg, td_wih + D_, G_, td_b, nullptr, B_, G_, F_, 0);
    // xe1 = ebd @ We^T                  (We = td_wih cols [D+F, D+F+E))
    launch_gemm(p_xe1, nullptr, 0, p_ebd, td_wih + D_ + F_, G_, nullptr, nullptr, B_ * T_, G_, E_, 0);
    add_favg_k<<<4096, 256>>>();
    // img_att = fs @ attf_w^T + attf_b
    launch_gemm(p_imgatt, nullptr, 0, p_fs, attf_w, F_, attf_b, nullptr, B_ * N_, A_, F_, 0);

    // ---- sequential decode steps ----
    for (int t = 0; t < T_; ++t) {
        // gates1 = xe1[:,t,:] + h2 @ W_h2^T + h1 @ td_whh^T
        launch_gemm(p_gates1, p_xe1 + (size_t)t * G_, T_ * G_, p_h2, td_wih, G_, nullptr, nullptr, B_, G_, D_, 0);
        launch_gemm(p_gates1, nullptr, 0, p_h1, td_whh, D_, nullptr, nullptr, B_, G_, D_, 1);
        lstm1_ew_k<<<(B_ * D_ + 255) / 256, 256>>>();
        // q = h1n @ attd_w^T + attd_b
        launch_gemm(p_q, nullptr, 0, p_h1n, attd_w, D_, attd_b, nullptr, B_, A_, D_, 0);
        attn_k<<<B_, 256>>>(att_w, att_b);
        // gates2 = aw @ W_aw^T + h1n @ W_h1^T + h2 @ lang_whh^T + lang_b
        launch_gemm(p_gates2, nullptr, 0, p_aw, lang_wih, F_ + D_, lang_b, nullptr, B_, G_, F_, 0);
        launch_gemm(p_gates2, nullptr, 0, p_h1n, lang_wih + F_, F_ + D_, nullptr, nullptr, B_, G_, D_, 1);
        launch_gemm(p_gates2, nullptr, 0, p_h2, lang_whh, D_, nullptr, nullptr, B_, G_, D_, 1);
        lstm2_ew_k<<<(B_ * D_ + 255) / 256, 256>>>(t);
        // gates3 = h1n @ ar_wih^T + arh @ ar_whh^T + ar_b
        launch_gemm(p_gates3, nullptr, 0, p_h1n, ar_wih, D_, ar_b, nullptr, B_, G_, D_, 0);
        launch_gemm(p_gates3, nullptr, 0, p_arh, ar_whh, D_, nullptr, nullptr, B_, G_, D_, 1);
        lstm3_ew_k<<<(B_ * D_ + 255) / 256, 256>>>(t);
        commit_k<<<(B_ * D_ + 255) / 256, 256>>>(t);
    }

    // ---- batched tail ----
    // preds = mask(H2all @ out_w^T + out_b)
    launch_gemm(out, nullptr, 0, p_H2, out_w, D_, out_b, p_act, B_ * T_, V_, D_, 0);
    // ARL = ARHNall @ arl_w^T + arl_b
    launch_gemm(p_ARL, nullptr, 0, p_ARHN, arl_w, D_, arl_b, nullptr, B_ * T_, D_, D_, 0);
    loss_rows_k<<<B_ * T_, 256>>>();
    loss_final_k<<<1, 256>>>(out);
}

// round 8
// speedup vs baseline: 1.3772x; 1.3772x over previous
#include <cuda_runtime.h>
#include <cuda_bf16.h>
#include <math.h>
#include <stdint.h>

#define B_ 256
#define N_ 36
#define F_ 2048
#define L_ 26
#define A_ 512
#define E_ 1024
#define D_ 1024
#define V_ 10000
#define T_ 25
#define G_ 4096

// ---------------- static device scratch ----------------
__device__ __align__(256) float g_fs[(size_t)B_ * N_ * F_];
__device__ __align__(256) float g_favg[B_ * F_];
__device__ __align__(256) float g_favgW[B_ * G_];
__device__ __align__(256) float g_ebd[(size_t)B_ * T_ * E_];
__device__ __align__(256) float g_xe1[(size_t)B_ * T_ * G_];
__device__ __align__(256) float g_imgatt[(size_t)B_ * N_ * A_];
__device__ __align__(256) float g_h1[B_ * D_], g_c1[B_ * D_], g_h2[B_ * D_], g_c2[B_ * D_];
__device__ __align__(256) float g_arh[B_ * D_], g_arc[B_ * D_], g_prevh1[B_ * D_];
__device__ __align__(256) float g_h1n[B_ * D_], g_c1n[B_ * D_], g_h2n[B_ * D_], g_c2n[B_ * D_];
__device__ __align__(256) float g_arhn[B_ * D_], g_arcn[B_ * D_];
__device__ __align__(256) float g_gates1[B_ * G_], g_gates2[B_ * G_], g_gates3[B_ * G_];
__device__ __align__(256) float g_q[B_ * A_];
__device__ __align__(256) float g_aw[B_ * F_];
__device__ __align__(256) float g_H2[(size_t)B_ * T_ * D_];
__device__ __align__(256) float g_ARHN[(size_t)B_ * T_ * D_];
__device__ __align__(256) float g_PREV[(size_t)B_ * T_ * D_];
__device__ __align__(256) float g_ARL[(size_t)B_ * T_ * D_];
__device__ __align__(256) float g_rowss[B_ * T_];
__device__ int g_order[B_];
__device__ int g_declen[B_];
__device__ unsigned char g_act[B_ * T_];

__device__ __forceinline__ float sigm(float x) { return 1.f / (1.f + expf(-x)); }

__device__ __forceinline__ uint32_t smem_u32(const void* p) {
    uint32_t a;
    asm("{ .reg .u64 t; cvta.to.shared.u64 t, %1; cvt.u32.u64 %0, t; }" : "=r"(a) : "l"(p));
    return a;
}
__device__ __forceinline__ uint32_t bpack(float a, float b) {
    return (uint32_t)__bfloat16_as_ushort(__float2bfloat16(b)) << 16 |
           (uint32_t)__bfloat16_as_ushort(__float2bfloat16(a));
}
__device__ __forceinline__ void ldm_x4(uint32_t& r0, uint32_t& r1, uint32_t& r2, uint32_t& r3, uint32_t addr) {
    asm volatile("ldmatrix.sync.aligned.m8n8.x4.shared.b16 {%0,%1,%2,%3}, [%4];"
                 : "=r"(r0), "=r"(r1), "=r"(r2), "=r"(r3) : "r"(addr));
}
__device__ __forceinline__ void ldm_x2(uint32_t& r0, uint32_t& r1, uint32_t addr) {
    asm volatile("ldmatrix.sync.aligned.m8n8.x2.shared.b16 {%0,%1}, [%2];"
                 : "=r"(r0), "=r"(r1) : "r"(addr));
}
__device__ __forceinline__ void mma16816(float* c, const uint32_t* a, const uint32_t* b) {
    asm volatile("mma.sync.aligned.m16n8k16.row.col.f32.bf16.bf16.f32 "
                 "{%0,%1,%2,%3},{%4,%5,%6,%7},{%8,%9},{%0,%1,%2,%3};"
                 : "+f"(c[0]), "+f"(c[1]), "+f"(c[2]), "+f"(c[3])
                 : "r"(a[0]), "r"(a[1]), "r"(a[2]), "r"(a[3]), "r"(b[0]), "r"(b[1]));
}

// ======= HMMA GEMM: C[M,N] = A[M,K] @ W[N,K]^T, bf16 hi/lo (3-pass), fp32 acc =======
#define SLD 40  // smem row stride in bf16 (32 + 8 pad)
__global__ void __launch_bounds__(256) mma_gemm_k(
    float* __restrict__ C, const float* __restrict__ Cinit, int initLd,
    const float* __restrict__ A, const float* __restrict__ W, int ldw,
    const float* __restrict__ bias, const unsigned char* __restrict__ mask,
    int M, int N, int K, int accum)
{
    __shared__ __align__(16) __nv_bfloat16 sAh[128][SLD], sAl[128][SLD], sWh[128][SLD], sWl[128][SLD];
    const int tid = threadIdx.x, wid = tid >> 5, lane = tid & 31;
    const int bm = blockIdx.y * 128, bn = blockIdx.x * 128;
    const int wm = (wid & 3) * 32, wn = (wid >> 2) * 64;

    float c[2][8][4];
    #pragma unroll
    for (int i = 0; i < 2; ++i)
        #pragma unroll
        for (int j = 0; j < 8; ++j)
            #pragma unroll
            for (int k = 0; k < 4; ++k) c[i][j][k] = 0.f;

    const int lrow = tid >> 1, lcb = (tid & 1) * 16;
    const bool aok = (bm + lrow) < M, wok = (bn + lrow) < N;
    const float* arow = A + (size_t)(bm + lrow) * K;
    const float* wrow = W + (size_t)(bn + lrow) * ldw;

    float ar[16], wr[16];
    #pragma unroll
    for (int j = 0; j < 4; ++j) {
        float4 v = aok ? *(const float4*)(arow + lcb + j * 4) : make_float4(0, 0, 0, 0);
        ar[j*4] = v.x; ar[j*4+1] = v.y; ar[j*4+2] = v.z; ar[j*4+3] = v.w;
        float4 u = wok ? *(const float4*)(wrow + lcb + j * 4) : make_float4(0, 0, 0, 0);
        wr[j*4] = u.x; wr[j*4+1] = u.y; wr[j*4+2] = u.z; wr[j*4+3] = u.w;
    }

    const int nch = K >> 5;
    for (int ch = 0; ch < nch; ++ch) {
        if (ch > 0) __syncthreads();
        uint32_t h[8], l[8];
        #pragma unroll
        for (int j = 0; j < 8; ++j) {
            float a = ar[2*j], b = ar[2*j+1];
            h[j] = bpack(a, b);
            l[j] = bpack(a - __bfloat162float(__float2bfloat16(a)),
                         b - __bfloat162float(__float2bfloat16(b)));
        }
        *(uint4*)&sAh[lrow][lcb]     = make_uint4(h[0], h[1], h[2], h[3]);
        *(uint4*)&sAh[lrow][lcb + 8] = make_uint4(h[4], h[5], h[6], h[7]);
        *(uint4*)&sAl[lrow][lcb]     = make_uint4(l[0], l[1], l[2], l[3]);
        *(uint4*)&sAl[lrow][lcb + 8] = make_uint4(l[4], l[5], l[6], l[7]);
        #pragma unroll
        for (int j = 0; j < 8; ++j) {
            float a = wr[2*j], b = wr[2*j+1];
            h[j] = bpack(a, b);
            l[j] = bpack(a - __bfloat162float(__float2bfloat16(a)),
                         b - __bfloat162float(__float2bfloat16(b)));
        }
        *(uint4*)&sWh[lrow][lcb]     = make_uint4(h[0], h[1], h[2], h[3]);
        *(uint4*)&sWh[lrow][lcb + 8] = make_uint4(h[4], h[5], h[6], h[7]);
        *(uint4*)&sWl[lrow][lcb]     = make_uint4(l[0], l[1], l[2], l[3]);
        *(uint4*)&sWl[lrow][lcb + 8] = make_uint4(l[4], l[5], l[6], l[7]);
        __syncthreads();
        if (ch + 1 < nch) {
            int k0 = (ch + 1) << 5;
            #pragma unroll
            for (int j = 0; j < 4; ++j) {
                float4 v = aok ? *(const float4*)(arow + k0 + lcb + j * 4) : make_float4(0, 0, 0, 0);
                ar[j*4] = v.x; ar[j*4+1] = v.y; ar[j*4+2] = v.z; ar[j*4+3] = v.w;
                float4 u = wok ? *(const float4*)(wrow + k0 + lcb + j * 4) : make_float4(0, 0, 0, 0);
                wr[j*4] = u.x; wr[j*4+1] = u.y; wr[j*4+2] = u.z; wr[j*4+3] = u.w;
            }
        }
        #pragma unroll
        for (int ks = 0; ks < 2; ++ks) {
            const int k0 = ks * 16;
            uint32_t Ah[2][4], Al[2][4], Bh[8][2], Bl[8][2];
            const int arw = (lane & 15), akc = k0 + ((lane >> 4) << 3);
            #pragma unroll
            for (int mf = 0; mf < 2; ++mf) {
                int r = wm + mf * 16 + arw;
                ldm_x4(Ah[mf][0], Ah[mf][1], Ah[mf][2], Ah[mf][3], smem_u32(&sAh[r][akc]));
                ldm_x4(Al[mf][0], Al[mf][1], Al[mf][2], Al[mf][3], smem_u32(&sAl[r][akc]));
            }
            const int l4 = lane & 15;
            const int brw = l4 & 7, bkc = k0 + ((l4 >> 3) & 1) * 8;
            #pragma unroll
            for (int nf = 0; nf < 8; ++nf) {
                int r = wn + nf * 8 + brw;
                ldm_x2(Bh[nf][0], Bh[nf][1], smem_u32(&sWh[r][bkc]));
                ldm_x2(Bl[nf][0], Bl[nf][1], smem_u32(&sWl[r][bkc]));
            }
            #pragma unroll
            for (int mf = 0; mf < 2; ++mf)
                #pragma unroll
                for (int nf = 0; nf < 8; ++nf) mma16816(c[mf][nf], Ah[mf], Bh[nf]);
            #pragma unroll
            for (int mf = 0; mf < 2; ++mf)
                #pragma unroll
                for (int nf = 0; nf < 8; ++nf) mma16816(c[mf][nf], Al[mf], Bh[nf]);
            #pragma unroll
            for (int mf = 0; mf < 2; ++mf)
                #pragma unroll
                for (int nf = 0; nf < 8; ++nf) mma16816(c[mf][nf], Ah[mf], Bl[nf]);
        }
    }

    #pragma unroll
    for (int mf = 0; mf < 2; ++mf) {
        #pragma unroll
        for (int half = 0; half < 2; ++half) {
            int m = bm + wm + mf * 16 + (lane >> 2) + half * 8;
            if (m >= M) continue;
            unsigned char mk = mask ? mask[m] : 1;
            #pragma unroll
            for (int nf = 0; nf < 8; ++nf) {
                #pragma unroll
                for (int e = 0; e < 2; ++e) {
                    int n = bn + wn + nf * 8 + (lane & 3) * 2 + e;
                    if (n >= N) continue;
                    size_t ci = (size_t)m * N + n;
                    float v = c[mf][nf][half * 2 + e];
                    if (accum) {
                        C[ci] += v;
                    } else {
                        if (bias) v += bias[n];
                        if (Cinit) v += Cinit[(size_t)m * initLd + n];
                        if (mask) v = mk ? v : 0.f;
                        C[ci] = v;
                    }
                }
            }
        }
    }
}

// ---------------- setup kernels ----------------
__global__ void sort_k(const int* __restrict__ sizes) {
    __shared__ int s[B_];
    int i = threadIdx.x;
    s[i] = sizes[i];
    __syncthreads();
    int my = s[i], rank = 0;
    for (int j = 0; j < B_; ++j) { int sj = s[j]; if (sj > my || (sj == my && j < i)) rank++; }
    g_order[rank] = i;
    g_declen[rank] = my - 1;
}
__global__ void init_act_k() {
    int idx = blockIdx.x * blockDim.x + threadIdx.x;
    if (idx < B_ * T_) { int b = idx / T_, t = idx - b * T_; g_act[idx] = (t < g_declen[b]) ? 1 : 0; }
}
__global__ void zero_carries_k() {
    int idx = blockIdx.x * blockDim.x + threadIdx.x;
    if (idx < B_ * D_) {
        g_h1[idx] = 0.f; g_c1[idx] = 0.f; g_h2[idx] = 0.f; g_c2[idx] = 0.f;
        g_arh[idx] = 0.f; g_arc[idx] = 0.f; g_prevh1[idx] = 0.f;
    }
}
__global__ void gather_fs_k(const float4* __restrict__ feats) {
    const int per_b = N_ * F_ / 4;
    size_t total = (size_t)B_ * per_b;
    for (size_t i = (size_t)blockIdx.x * blockDim.x + threadIdx.x; i < total; i += (size_t)gridDim.x * blockDim.x) {
        int b = (int)(i / per_b);
        ((float4*)g_fs)[i] = feats[(size_t)g_order[b] * per_b + (i - (size_t)b * per_b)];
    }
}
__global__ void favg_k() {
    int idx = blockIdx.x * blockDim.x + threadIdx.x;
    if (idx < B_ * F_) {
        int b = idx / F_, f = idx - b * F_;
        const float* base = g_fs + (size_t)b * N_ * F_ + f;
        float s = 0.f;
        #pragma unroll
        for (int n = 0; n < N_; ++n) s += base[(size_t)n * F_];
        g_favg[idx] = s * (1.f / N_);
    }
}
__global__ void gather_ebd_k(const int* __restrict__ seqs, const float4* __restrict__ emb) {
    const int per_r = E_ / 4;
    size_t total = (size_t)B_ * T_ * per_r;
    for (size_t i = (size_t)blockIdx.x * blockDim.x + threadIdx.x; i < total; i += (size_t)gridDim.x * blockDim.x) {
        int r = (int)(i / per_r);
        int e4 = (int)(i - (size_t)r * per_r);
        int b = r / T_, t = r - b * T_;
        ((float4*)g_ebd)[i] = emb[(size_t)seqs[g_order[b] * L_ + t] * per_r + e4];
    }
}
__global__ void add_favg_k() {
    const int per_r = G_ / 4;
    size_t total = (size_t)B_ * T_ * per_r;
    for (size_t i = (size_t)blockIdx.x * blockDim.x + threadIdx.x; i < total; i += (size_t)gridDim.x * blockDim.x) {
        int r = (int)(i / per_r);
        int g4 = (int)(i - (size_t)r * per_r);
        float4 x = ((float4*)g_xe1)[i];
        float4 a = ((const float4*)g_favgW)[(size_t)(r / T_) * per_r + g4];
        x.x += a.x; x.y += a.y; x.z += a.z; x.w += a.w;
        ((float4*)g_xe1)[i] = x;
    }
}

// ---------------- LSTM elementwise ----------------
__device__ __forceinline__ void lstm_elem(const float* __restrict__ gates,
                                          const float* __restrict__ c_old,
                                          float* __restrict__ h_new, float* __restrict__ c_new, int idx) {
    int b = idx / D_, d = idx - b * D_;
    const float* g = gates + (size_t)b * G_;
    float ig = sigm(g[d]);
    float fg = sigm(g[D_ + d]);
    float gg = tanhf(g[2 * D_ + d]);
    float og = sigm(g[3 * D_ + d]);
    float c = fg * c_old[idx] + ig * gg;
    c_new[idx] = c;
    h_new[idx] = og * tanhf(c);
}
__global__ void lstm1_ew_k() {
    int idx = blockIdx.x * blockDim.x + threadIdx.x;
    if (idx < B_ * D_) lstm_elem(g_gates1, g_c1, g_h1n, g_c1n, idx);
}
__global__ void lstm2_ew_k(int t) {
    int idx = blockIdx.x * blockDim.x + threadIdx.x;
    if (idx < B_ * D_) {
        lstm_elem(g_gates2, g_c2, g_h2n, g_c2n, idx);
        int b = idx / D_, d = idx - b * D_;
        g_H2[((size_t)b * T_ + t) * D_ + d] = g_h2n[idx];
    }
}
__global__ void lstm3_ew_k(int t) {
    int idx = blockIdx.x * blockDim.x + threadIdx.x;
    if (idx < B_ * D_) {
        lstm_elem(g_gates3, g_arc, g_arhn, g_arcn, idx);
        int b = idx / D_, d = idx - b * D_;
        g_ARHN[((size_t)b * T_ + t) * D_ + d] = g_arhn[idx];
    }
}

// ---------------- attention ----------------
__global__ void attn_k(const float* __restrict__ attw, const float* __restrict__ attb) {
    int b = blockIdx.x;
    int tid = threadIdx.x, warp = tid >> 5, lane = tid & 31;
    __shared__ float s_q[A_], s_w[A_], s_sc[N_], s_alpha[N_];
    for (int i = tid; i < A_; i += 256) { s_q[i] = g_q[b * A_ + i]; s_w[i] = attw[i]; }
    __syncthreads();
    for (int n = warp; n < N_; n += 8) {
        const float* row = g_imgatt + ((size_t)b * N_ + n) * A_;
        float p = 0.f;
        for (int a = lane; a < A_; a += 32) { float v = s_q[a] + row[a]; p += fmaxf(v, 0.f) * s_w[a]; }
        #pragma unroll
        for (int o = 16; o; o >>= 1) p += __shfl_xor_sync(0xffffffffu, p, o);
        if (lane == 0) s_sc[n] = p + attb[0];
    }
    __syncthreads();
    if (warp == 0) {
        float v0 = s_sc[lane];
        float v1 = (lane + 32 < N_) ? s_sc[lane + 32] : -1e30f;
        float mx = fmaxf(v0, v1);
        #pragma unroll
        for (int o = 16; o; o >>= 1) mx = fmaxf(mx, __shfl_xor_sync(0xffffffffu, mx, o));
        float e0 = expf(v0 - mx), e1 = (lane + 32 < N_) ? expf(v1 - mx) : 0.f;
        float s = e0 + e1;
        #pragma unroll
        for (int o = 16; o; o >>= 1) s += __shfl_xor_sync(0xffffffffu, s, o);
        s_alpha[lane] = e0 / s;
        if (lane + 32 < N_) s_alpha[lane + 32] = e1 / s;
    }
    __syncthreads();
    for (int f = tid; f < F_; f += 256) {
        float acc = 0.f;
        const float* fb = g_fs + (size_t)b * N_ * F_ + f;
        #pragma unroll
        for (int n = 0; n < N_; ++n) acc += s_alpha[n] * fb[(size_t)n * F_];
        g_aw[b * F_ + f] = acc;
    }
}

__global__ void commit_k(int t) {
    int idx = blockIdx.x * blockDim.x + threadIdx.x;
    if (idx >= B_ * D_) return;
    int b = idx / D_, d = idx - b * D_;
    g_PREV[((size_t)b * T_ + t) * D_ + d] = g_prevh1[idx];
    if (g_act[b * T_ + t]) {
        g_h1[idx] = g_h1n[idx];  g_c1[idx] = g_c1n[idx];
        g_h2[idx] = g_h2n[idx];  g_c2[idx] = g_c2n[idx];
        g_arh[idx] = g_arhn[idx]; g_arc[idx] = g_arcn[idx];
        g_prevh1[idx] = g_h1n[idx];
    }
}

// ---------------- loss ----------------
__global__ void loss_rows_k() {
    int r = blockIdx.x;
    int t = r % T_;
    int tid = threadIdx.x;
    float p = 0.f;
    if (t > 0 && g_act[r]) {
        const float* a = g_ARL + (size_t)r * D_;
        const float* pv = g_PREV + (size_t)r * D_;
        for (int d = tid; d < D_; d += 256) { float df = a[d] - pv[d]; p += df * df; }
    }
    __shared__ float sred[256];
    sred[tid] = p;
    __syncthreads();
    for (int o = 128; o; o >>= 1) { if (tid < o) sred[tid] += sred[tid + o]; __syncthreads(); }
    if (tid == 0) g_rowss[r] = sred[0];
}
__global__ void loss_final_k(float* __restrict__ out) {
    __shared__ float ss[256], sc[256];
    int tid = threadIdx.x;
    float total = 0.f;
    for (int t = 1; t < T_; ++t) {
        float s = 0.f, c = 0.f;
        for (int b = tid; b < B_; b += 256) {
            s += g_rowss[b * T_ + t];
            c += g_act[b * T_ + t] ? 1.f : 0.f;
        }
        ss[tid] = s; sc[tid] = c;
        __syncthreads();
        for (int o = 128; o; o >>= 1) { if (tid < o) { ss[tid] += ss[tid + o]; sc[tid] += sc[tid + o]; } __syncthreads(); }
        if (tid == 0) total += ss[0] / fmaxf(sc[0], 1.f) * 0.005f;
        __syncthreads();
    }
    if (tid == 0) out[(size_t)B_ * T_ * V_] = total;
}

// ---------------- host ----------------
static inline float* fsym(const void* s) { void* p = nullptr; cudaGetSymbolAddress(&p, s); return (float*)p; }

static inline void launch_gemm(float* C, const float* Cinit, int initLd,
                               const float* A, const float* W, int ldw,
                               const float* bias, const unsigned char* mask,
                               int M, int N, int K, int accum) {
    dim3 grid((N + 127) / 128, (M + 127) / 128);
    mma_gemm_k<<<grid, 256>>>(C, Cinit, initLd, A, W, ldw, bias, mask, M, N, K, accum);
}

extern "C" void kernel_launch(void* const* d_in, const int* in_sizes, int n_in,
                              void* d_out, int out_size) {
    const float* feats     = (const float*)d_in[0];
    const int*   sequences = (const int*)d_in[1];
    const int*   sizes     = (const int*)d_in[2];
    const float* emb       = (const float*)d_in[3];
    const float* td_wih    = (const float*)d_in[4];
    const float* td_whh    = (const float*)d_in[5];
    const float* td_b      = (const float*)d_in[6];
    const float* lang_wih  = (const float*)d_in[7];
    const float* lang_whh  = (const float*)d_in[8];
    const float* lang_b    = (const float*)d_in[9];
    const float* attf_w    = (const float*)d_in[10];
    const float* attf_b    = (const float*)d_in[11];
    const float* attd_w    = (const float*)d_in[12];
    const float* attd_b    = (const float*)d_in[13];
    const float* att_w     = (const float*)d_in[14];
    const float* att_b     = (const float*)d_in[15];
    const float* out_w     = (const float*)d_in[16];
    const float* out_b     = (const float*)d_in[17];
    const float* ar_wih    = (const float*)d_in[18];
    const float* ar_whh    = (const float*)d_in[19];
    const float* ar_b      = (const float*)d_in[20];
    const float* arl_w     = (const float*)d_in[21];
    const float* arl_b     = (const float*)d_in[22];
    float* out = (float*)d_out;

    float* p_fs     = fsym(g_fs);
    float* p_favg   = fsym(g_favg);
    float* p_favgW  = fsym(g_favgW);
    float* p_ebd    = fsym(g_ebd);
    float* p_xe1    = fsym(g_xe1);
    float* p_imgatt = fsym(g_imgatt);
    float* p_h1     = fsym(g_h1);
    float* p_h2     = fsym(g_h2);
    float* p_h1n    = fsym(g_h1n);
    float* p_arh    = fsym(g_arh);
    float* p_aw     = fsym(g_aw);
    float* p_q      = fsym(g_q);
    float* p_gates1 = fsym(g_gates1);
    float* p_gates2 = fsym(g_gates2);
    float* p_gates3 = fsym(g_gates3);
    float* p_H2     = fsym(g_H2);
    float* p_ARHN   = fsym(g_ARHN);
    float* p_ARL    = fsym(g_ARL);
    void* p_act_v = nullptr; cudaGetSymbolAddress(&p_act_v, g_act);
    const unsigned char* p_act = (const unsigned char*)p_act_v;

    // ---- setup ----
    sort_k<<<1, B_>>>(sizes);
    init_act_k<<<(B_ * T_ + 255) / 256, 256>>>();
    zero_carries_k<<<(B_ * D_ + 255) / 256, 256>>>();
    gather_fs_k<<<2048, 256>>>((const float4*)feats);
    favg_k<<<(B_ * F_ + 255) / 256, 256>>>();
    gather_ebd_k<<<2048, 256>>>(sequences, (const float4*)emb);

    launch_gemm(p_favgW, nullptr, 0, p_favg, td_wih + D_, G_, td_b, nullptr, B_, G_, F_, 0);
    launch_gemm(p_xe1, nullptr, 0, p_ebd, td_wih + D_ + F_, G_, nullptr, nullptr, B_ * T_, G_, E_, 0);
    add_favg_k<<<4096, 256>>>();
    launch_gemm(p_imgatt, nullptr, 0, p_fs, attf_w, F_, attf_b, nullptr, B_ * N_, A_, F_, 0);

    // ---- sequential decode ----
    for (int t = 0; t < T_; ++t) {
        launch_gemm(p_gates1, p_xe1 + (size_t)t * G_, T_ * G_, p_h2, td_wih, G_, nullptr, nullptr, B_, G_, D_, 0);
        launch_gemm(p_gates1, nullptr, 0, p_h1, td_whh, D_, nullptr, nullptr, B_, G_, D_, 1);
        lstm1_ew_k<<<(B_ * D_ + 255) / 256, 256>>>();
        launch_gemm(p_q, nullptr, 0, p_h1n, attd_w, D_, attd_b, nullptr, B_, A_, D_, 0);
        attn_k<<<B_, 256>>>(att_w, att_b);
        launch_gemm(p_gates2, nullptr, 0, p_aw, lang_wih, F_ + D_, lang_b, nullptr, B_, G_, F_, 0);
        launch_gemm(p_gates2, nullptr, 0, p_h1n, lang_wih + F_, F_ + D_, nullptr, nullptr, B_, G_, D_, 1);
        launch_gemm(p_gates2, nullptr, 0, p_h2, lang_whh, D_, nullptr, nullptr, B_, G_, D_, 1);
        lstm2_ew_k<<<(B_ * D_ + 255) / 256, 256>>>(t);
        launch_gemm(p_gates3, nullptr, 0, p_h1n, ar_wih, D_, ar_b, nullptr, B_, G_, D_, 0);
        launch_gemm(p_gates3, nullptr, 0, p_arh, ar_whh, D_, nullptr, nullptr, B_, G_, D_, 1);
        lstm3_ew_k<<<(B_ * D_ + 255) / 256, 256>>>(t);
        commit_k<<<(B_ * D_ + 255) / 256, 256>>>(t);
    }

    // ---- batched tail ----
    launch_gemm(out, nullptr, 0, p_H2, out_w, D_, out_b, p_act, B_ * T_, V_, D_, 0);
    launch_gemm(p_ARL, nullptr, 0, p_ARHN, arl_w, D_, arl_b, nullptr, B_ * T_, D_, D_, 0);
    loss_rows_k<<<B_ * T_, 256>>>();
    loss_final_k<<<1, 256>>>(out);
}

// round 10
// speedup vs baseline: 1.4074x; 1.0220x over previous
#include <cuda_runtime.h>
#include <cuda_bf16.h>
#include <math.h>
#include <stdint.h>

#define B_ 256
#define N_ 36
#define F_ 2048
#define L_ 26
#define A_ 512
#define E_ 1024
#define D_ 1024
#define V_ 10000
#define T_ 25
#define G_ 4096
typedef __nv_bfloat16 bf16;

// ---------------- fp32 state / scratch ----------------
__device__ __align__(256) float g_fs[(size_t)B_ * N_ * F_];
__device__ __align__(256) float g_favgW[B_ * G_];
__device__ __align__(256) float g_xe1[(size_t)B_ * T_ * G_];
__device__ __align__(256) float g_imgatt[(size_t)B_ * N_ * A_];
__device__ __align__(256) float g_c1[B_ * D_], g_c2[B_ * D_], g_arc[B_ * D_], g_prevh1[B_ * D_];
__device__ __align__(256) float g_h1n[B_ * D_], g_c1n[B_ * D_], g_h2n[B_ * D_], g_c2n[B_ * D_];
__device__ __align__(256) float g_gates1[B_ * G_], g_gates2[B_ * G_], g_g3q[B_ * 4608];
__device__ __align__(256) float g_PREV[(size_t)B_ * T_ * D_];
__device__ __align__(256) float g_ARL[(size_t)B_ * T_ * D_];
__device__ __align__(256) float g_rowss[B_ * T_];
__device__ __align__(256) float g_b3q[4608];
__device__ int g_order[B_];
__device__ int g_declen[B_];
__device__ unsigned char g_act[B_ * T_];
// ---------------- bf16 triple buffers: acts [hi|lo|hi], weights [hi|hi|lo] ----------------
__device__ __align__(256) bf16 Xfs[(size_t)B_ * N_ * 6144];
__device__ __align__(256) bf16 Xfavg[(size_t)B_ * 6144];
__device__ __align__(256) bf16 Xebd[(size_t)B_ * T_ * 3072];
__device__ __align__(256) bf16 X1[(size_t)B_ * 6144];
__device__ __align__(256) bf16 X2[(size_t)B_ * 12288];
__device__ __align__(256) bf16 X3[(size_t)B_ * 6144];
__device__ __align__(256) bf16 H2t[(size_t)B_ * T_ * 3072];
__device__ __align__(256) bf16 ARNt[(size_t)B_ * T_ * 3072];
__device__ __align__(256) bf16 Wfavg[(size_t)G_ * 6144];
__device__ __align__(256) bf16 Wxe[(size_t)G_ * 3072];
__device__ __align__(256) bf16 W1p[(size_t)G_ * 6144];
__device__ __align__(256) bf16 W2p[(size_t)G_ * 12288];
__device__ __align__(256) bf16 W3p[(size_t)4608 * 6144];
__device__ __align__(256) bf16 Wattf[(size_t)A_ * 6144];
__device__ __align__(256) bf16 Wout[(size_t)V_ * 3072];
__device__ __align__(256) bf16 Warl[(size_t)D_ * 3072];

__device__ __forceinline__ float sigm(float x) { return 1.f / (1.f + expf(-x)); }
// activation triple write: [hi | lo | hi]
__device__ __forceinline__ void wtrip(bf16* dst, size_t row, int K, int off, float v) {
    bf16 hi = __float2bfloat16(v);
    size_t b = row * (size_t)(3 * K) + off;
    dst[b] = hi;
    dst[b + K] = __float2bfloat16(v - __bfloat162float(hi));
    dst[b + 2 * K] = hi;
}
__device__ __forceinline__ uint32_t smem_u32(const void* p) {
    uint32_t a;
    asm("{ .reg .u64 t; cvta.to.shared.u64 t, %1; cvt.u32.u64 %0, t; }" : "=r"(a) : "l"(p));
    return a;
}
__device__ __forceinline__ void cp16(uint32_t d, const void* s, bool ok) {
    asm volatile("cp.async.cg.shared.global [%0], [%1], 16, %2;" :: "r"(d), "l"(s), "r"(ok ? 16 : 0));
}
__device__ __forceinline__ void ldm_x4(uint32_t& r0, uint32_t& r1, uint32_t& r2, uint32_t& r3, uint32_t a) {
    asm volatile("ldmatrix.sync.aligned.m8n8.x4.shared.b16 {%0,%1,%2,%3}, [%4];"
                 : "=r"(r0), "=r"(r1), "=r"(r2), "=r"(r3) : "r"(a));
}
__device__ __forceinline__ void ldm_x2(uint32_t& r0, uint32_t& r1, uint32_t a) {
    asm volatile("ldmatrix.sync.aligned.m8n8.x2.shared.b16 {%0,%1}, [%2];"
                 : "=r"(r0), "=r"(r1) : "r"(a));
}
__device__ __forceinline__ void mma16816(float* c, const uint32_t* a, const uint32_t* b) {
    asm volatile("mma.sync.aligned.m16n8k16.row.col.f32.bf16.bf16.f32 "
                 "{%0,%1,%2,%3},{%4,%5,%6,%7},{%8,%9},{%0,%1,%2,%3};"
                 : "+f"(c[0]), "+f"(c[1]), "+f"(c[2]), "+f"(c[3])
                 : "r"(a[0]), "r"(a[1]), "r"(a[2]), "r"(a[3]), "r"(b[0]), "r"(b[1]));
}

// ======= pipelined bf16 GEMM: C[M,N] = A[M,K3] @ W[N,K3]^T, fp32 acc =======
#define SLD 40
__global__ void __launch_bounds__(256) bgemm_k(
    float* __restrict__ C, const float* __restrict__ Cinit, int initLd,
    const bf16* __restrict__ A, int lda, const bf16* __restrict__ W, int ldw,
    const float* __restrict__ bias, const unsigned char* __restrict__ mask,
    int M, int N, int K3)
{
    __shared__ __align__(16) bf16 sA[2][128][SLD], sW[2][128][SLD];
    const int tid = threadIdx.x, wid = tid >> 5, lane = tid & 31;
    const int bm = blockIdx.y * 128, bn = blockIdx.x * 128;
    const int wm = (wid & 3) * 32, wn = (wid >> 2) * 64;
    float c[2][8][4];
    #pragma unroll
    for (int i = 0; i < 2; ++i)
        #pragma unroll
        for (int j = 0; j < 8; ++j)
            #pragma unroll
            for (int k = 0; k < 4; ++k) c[i][j][k] = 0.f;

    const int lrow = tid >> 1, lcol = (tid & 1) * 16;
    const bool aok = (bm + lrow) < M, wok = (bn + lrow) < N;
    const bf16* aptr = A + (size_t)(bm + lrow) * lda + lcol;
    const bf16* wptr = W + (size_t)(bn + lrow) * ldw + lcol;
    const int nch = K3 >> 5;

    {
        uint32_t da = smem_u32(&sA[0][lrow][lcol]), dw = smem_u32(&sW[0][lrow][lcol]);
        cp16(da, aptr, aok); cp16(da + 16, aptr + 8, aok);
        cp16(dw, wptr, wok); cp16(dw + 16, wptr + 8, wok);
        asm volatile("cp.async.commit_group;" ::: "memory");
    }
    for (int ch = 0; ch < nch; ++ch) {
        asm volatile("cp.async.wait_group 0;" ::: "memory");
        __syncthreads();
        if (ch + 1 < nch) {
            int nb = (ch + 1) & 1;
            const bf16* as = aptr + (ch + 1) * 32;
            const bf16* ws = wptr + (ch + 1) * 32;
            uint32_t da = smem_u32(&sA[nb][lrow][lcol]), dw = smem_u32(&sW[nb][lrow][lcol]);
            cp16(da, as, aok); cp16(da + 16, as + 8, aok);
            cp16(dw, ws, wok); cp16(dw + 16, ws + 8, wok);
            asm volatile("cp.async.commit_group;" ::: "memory");
        }
        const int bf = ch & 1;
        #pragma unroll
        for (int ks = 0; ks < 2; ++ks) {
            const int k0 = ks * 16;
            uint32_t Af[2][4], Bf[8][2];
            const int arw = (lane & 15), akc = k0 + ((lane >> 4) << 3);
            #pragma unroll
            for (int mf = 0; mf < 2; ++mf)
                ldm_x4(Af[mf][0], Af[mf][1], Af[mf][2], Af[mf][3], smem_u32(&sA[bf][wm + mf * 16 + arw][akc]));
            const int l4 = lane & 15, brw = l4 & 7, bkc = k0 + ((l4 >> 3) & 1) * 8;
            #pragma unroll
            for (int nf = 0; nf < 8; ++nf)
                ldm_x2(Bf[nf][0], Bf[nf][1], smem_u32(&sW[bf][wn + nf * 8 + brw][bkc]));
            #pragma unroll
            for (int mf = 0; mf < 2; ++mf)
                #pragma unroll
                for (int nf = 0; nf < 8; ++nf) mma16816(c[mf][nf], Af[mf], Bf[nf]);
        }
    }

    #pragma unroll
    for (int mf = 0; mf < 2; ++mf) {
        #pragma unroll
        for (int half = 0; half < 2; ++half) {
            int m = bm + wm + mf * 16 + (lane >> 2) + half * 8;
            if (m >= M) continue;
            unsigned char mk = mask ? mask[m] : 1;
            #pragma unroll
            for (int nf = 0; nf < 8; ++nf) {
                #pragma unroll
                for (int e = 0; e < 2; ++e) {
                    int n = bn + wn + nf * 8 + (lane & 3) * 2 + e;
                    if (n >= N) continue;
                    float v = c[mf][nf][half * 2 + e];
                    if (bias) v += bias[n];
                    if (Cinit) v += Cinit[(size_t)m * initLd + n];
                    if (mask) v = mk ? v : 0.f;
                    C[(size_t)m * N + n] = v;
                }
            }
        }
    }
}

// ---------------- weight triple conversion: [hi | hi | lo] (acts are [hi | lo | hi]) ----------------
__global__ void convw_k(bf16* __restrict__ dst, int Ktot, int dstOff, int rowOff,
                        const float* __restrict__ src, int lds, int segK, int nrows) {
    size_t total = (size_t)nrows * segK;
    for (size_t i = (size_t)blockIdx.x * blockDim.x + threadIdx.x; i < total;
         i += (size_t)gridDim.x * blockDim.x) {
        int n = (int)(i / segK), k = (int)(i - (size_t)n * segK);
        float v = src[(size_t)n * lds + k];
        bf16 hi = __float2bfloat16(v);
        size_t b = (size_t)(n + rowOff) * (3 * Ktot);
        dst[b + dstOff + k] = hi;                                            // · Ahi
        dst[b + Ktot + dstOff + k] = hi;                                     // · Alo
        dst[b + 2 * Ktot + dstOff + k] = __float2bfloat16(v - __bfloat162float(hi)); // · Ahi
    }
}
__global__ void zerobf_k(bf16* p, size_t n) {
    for (size_t i = (size_t)blockIdx.x * blockDim.x + threadIdx.x; i < n;
         i += (size_t)gridDim.x * blockDim.x) p[i] = __float2bfloat16(0.f);
}
__global__ void pack_b3q_k(const float* __restrict__ arb, const float* __restrict__ attdb) {
    int i = blockIdx.x * blockDim.x + threadIdx.x;
    if (i < G_) g_b3q[i] = arb[i];
    else if (i < 4608) g_b3q[i] = attdb[i - G_];
}

// ---------------- setup ----------------
__global__ void sort_k(const int* __restrict__ sizes) {
    __shared__ int s[B_];
    int i = threadIdx.x;
    s[i] = sizes[i];
    __syncthreads();
    int my = s[i], rank = 0;
    for (int j = 0; j < B_; ++j) { int sj = s[j]; if (sj > my || (sj == my && j < i)) rank++; }
    g_order[rank] = i;
    g_declen[rank] = my - 1;
}
__global__ void init_act_k() {
    int idx = blockIdx.x * blockDim.x + threadIdx.x;
    if (idx < B_ * T_) { int b = idx / T_, t = idx - b * T_; g_act[idx] = (t < g_declen[b]) ? 1 : 0; }
}
__global__ void zero_state_k() {
    int idx = blockIdx.x * blockDim.x + threadIdx.x;
    if (idx < B_ * D_) { g_c1[idx] = 0.f; g_c2[idx] = 0.f; g_arc[idx] = 0.f; g_prevh1[idx] = 0.f; }
}
__global__ void gather_fs_k(const float* __restrict__ feats) {
    const size_t NF = (size_t)N_ * F_;
    size_t total = (size_t)B_ * NF;
    for (size_t i = (size_t)blockIdx.x * blockDim.x + threadIdx.x; i < total;
         i += (size_t)gridDim.x * blockDim.x) {
        int b = (int)(i / NF);
        size_t rem = i - (size_t)b * NF;
        float v = feats[(size_t)g_order[b] * NF + rem];
        g_fs[i] = v;
        wtrip(Xfs, (size_t)b * N_ + rem / F_, F_, (int)(rem % F_), v);
    }
}
__global__ void favg_k() {
    int idx = blockIdx.x * blockDim.x + threadIdx.x;
    if (idx < B_ * F_) {
        int b = idx / F_, f = idx - b * F_;
        const float* base = g_fs + (size_t)b * N_ * F_ + f;
        float s = 0.f;
        #pragma unroll
        for (int n = 0; n < N_; ++n) s += base[(size_t)n * F_];
        wtrip(Xfavg, b, F_, f, s * (1.f / N_));
    }
}
__global__ void gather_ebd_k(const int* __restrict__ seqs, const float* __restrict__ emb) {
    size_t total = (size_t)B_ * T_ * E_;
    for (size_t i = (size_t)blockIdx.x * blockDim.x + threadIdx.x; i < total;
         i += (size_t)gridDim.x * blockDim.x) {
        int r = (int)(i / E_), e = (int)(i - (size_t)r * E_);
        int b = r / T_, t = r - b * T_;
        wtrip(Xebd, r, E_, e, emb[(size_t)seqs[g_order[b] * L_ + t] * E_ + e]);
    }
}
__global__ void add_favg_k() {
    const int per_r = G_ / 4;
    size_t total = (size_t)B_ * T_ * per_r;
    for (size_t i = (size_t)blockIdx.x * blockDim.x + threadIdx.x; i < total;
         i += (size_t)gridDim.x * blockDim.x) {
        int r = (int)(i / per_r), g4 = (int)(i - (size_t)r * per_r);
        float4 x = ((float4*)g_xe1)[i];
        float4 a = ((const float4*)g_favgW)[(size_t)(r / T_) * per_r + g4];
        x.x += a.x; x.y += a.y; x.z += a.z; x.w += a.w;
        ((float4*)g_xe1)[i] = x;
    }
}

// ---------------- step kernels ----------------
__global__ void lstm1_ew_k() {
    int idx = blockIdx.x * blockDim.x + threadIdx.x;
    if (idx >= B_ * D_) return;
    int b = idx / D_, d = idx - b * D_;
    const float* g = g_gates1 + (size_t)b * G_;
    float c = sigm(g[D_ + d]) * g_c1[idx] + sigm(g[d]) * tanhf(g[2 * D_ + d]);
    float h = sigm(g[3 * D_ + d]) * tanhf(c);
    g_c1n[idx] = c; g_h1n[idx] = h;
    wtrip(X2, b, G_, 2048 + d, h);
    wtrip(X3, b, 2048, d, h);
}
__global__ void attn_k(const float* __restrict__ attw, const float* __restrict__ attb) {
    int b = blockIdx.x;
    int tid = threadIdx.x, warp = tid >> 5, lane = tid & 31;
    __shared__ float s_q[A_], s_w[A_], s_sc[N_], s_alpha[N_];
    for (int i = tid; i < A_; i += 256) { s_q[i] = g_g3q[(size_t)b * 4608 + G_ + i]; s_w[i] = attw[i]; }
    __syncthreads();
    for (int n = warp; n < N_; n += 8) {
        const float* row = g_imgatt + ((size_t)b * N_ + n) * A_;
        float p = 0.f;
        for (int a = lane; a < A_; a += 32) { float v = s_q[a] + row[a]; p += fmaxf(v, 0.f) * s_w[a]; }
        #pragma unroll
        for (int o = 16; o; o >>= 1) p += __shfl_xor_sync(0xffffffffu, p, o);
        if (lane == 0) s_sc[n] = p + attb[0];
    }
    __syncthreads();
    if (warp == 0) {
        float v0 = s_sc[lane], v1 = (lane + 32 < N_) ? s_sc[lane + 32] : -1e30f;
        float mx = fmaxf(v0, v1);
        #pragma unroll
        for (int o = 16; o; o >>= 1) mx = fmaxf(mx, __shfl_xor_sync(0xffffffffu, mx, o));
        float e0 = expf(v0 - mx), e1 = (lane + 32 < N_) ? expf(v1 - mx) : 0.f;
        float s = e0 + e1;
        #pragma unroll
        for (int o = 16; o; o >>= 1) s += __shfl_xor_sync(0xffffffffu, s, o);
        s_alpha[lane] = e0 / s;
        if (lane + 32 < N_) s_alpha[lane + 32] = e1 / s;
    }
    __syncthreads();
    for (int f = tid; f < F_; f += 256) {
        float acc = 0.f;
        const float* fb = g_fs + (size_t)b * N_ * F_ + f;
        #pragma unroll
        for (int n = 0; n < N_; ++n) acc += s_alpha[n] * fb[(size_t)n * F_];
        wtrip(X2, b, G_, f, acc);
    }
}
__global__ void lstm2_ew_k(int t) {
    int idx = blockIdx.x * blockDim.x + threadIdx.x;
    if (idx >= B_ * D_) return;
    int b = idx / D_, d = idx - b * D_;
    const float* g = g_gates2 + (size_t)b * G_;
    float c = sigm(g[D_ + d]) * g_c2[idx] + sigm(g[d]) * tanhf(g[2 * D_ + d]);
    float h = sigm(g[3 * D_ + d]) * tanhf(c);
    g_c2n[idx] = c; g_h2n[idx] = h;
    wtrip(H2t, (size_t)b * T_ + t, D_, d, h);
}
__global__ void lstm3commit_k(int t) {
    int idx = blockIdx.x * blockDim.x + threadIdx.x;
    if (idx >= B_ * D_) return;
    int b = idx / D_, d = idx - b * D_;
    const float* g = g_g3q + (size_t)b * 4608;
    float c = sigm(g[D_ + d]) * g_arc[idx] + sigm(g[d]) * tanhf(g[2 * D_ + d]);
    float arhn = sigm(g[3 * D_ + d]) * tanhf(c);
    wtrip(ARNt, (size_t)b * T_ + t, D_, d, arhn);
    g_PREV[((size_t)b * T_ + t) * D_ + d] = g_prevh1[idx];
    if (g_act[b * T_ + t]) {
        float h1n = g_h1n[idx], h2n = g_h2n[idx];
        g_c1[idx] = g_c1n[idx]; g_c2[idx] = g_c2n[idx]; g_arc[idx] = c; g_prevh1[idx] = h1n;
        wtrip(X1, b, 2048, 1024 + d, h1n);
        wtrip(X1, b, 2048, d, h2n);
        wtrip(X2, b, G_, 3072 + d, h2n);
        wtrip(X3, b, 2048, 1024 + d, arhn);
    }
}

// ---------------- loss ----------------
__global__ void loss_rows_k() {
    int r = blockIdx.x, t = r % T_, tid = threadIdx.x;
    float p = 0.f;
    if (t > 0 && g_act[r]) {
        const float* a = g_ARL + (size_t)r * D_;
        const float* pv = g_PREV + (size_t)r * D_;
        for (int d = tid; d < D_; d += 256) { float df = a[d] - pv[d]; p += df * df; }
    }
    __shared__ float sred[256];
    sred[tid] = p;
    __syncthreads();
    for (int o = 128; o; o >>= 1) { if (tid < o) sred[tid] += sred[tid + o]; __syncthreads(); }
    if (tid == 0) g_rowss[r] = sred[0];
}
__global__ void loss_final_k(float* __restrict__ out) {
    __shared__ float ss[256], sc[256];
    int tid = threadIdx.x;
    float total = 0.f;
    for (int t = 1; t < T_; ++t) {
        float s = 0.f, c = 0.f;
        for (int b = tid; b < B_; b += 256) {
            s += g_rowss[b * T_ + t];
            c += g_act[b * T_ + t] ? 1.f : 0.f;
        }
        ss[tid] = s; sc[tid] = c;
        __syncthreads();
        for (int o = 128; o; o >>= 1) { if (tid < o) { ss[tid] += ss[tid + o]; sc[tid] += sc[tid + o]; } __syncthreads(); }
        if (tid == 0) total += ss[0] / fmaxf(sc[0], 1.f) * 0.005f;
        __syncthreads();
    }
    if (tid == 0) out[(size_t)B_ * T_ * V_] = total;
}

// ---------------- host ----------------
static inline float* fsym(const void* s) { void* p = nullptr; cudaGetSymbolAddress(&p, s); return (float*)p; }
static inline bf16* bsym(const void* s) { void* p = nullptr; cudaGetSymbolAddress(&p, s); return (bf16*)p; }

static inline void bgemm(float* C, const float* Cinit, int initLd,
                         const bf16* A, int lda, const bf16* W, int ldw,
                         const float* bias, const unsigned char* mask, int M, int N, int K3) {
    dim3 grid((N + 127) / 128, (M + 127) / 128);
    bgemm_k<<<grid, 256>>>(C, Cinit, initLd, A, lda, W, ldw, bias, mask, M, N, K3);
}
static inline void convw(bf16* dst, int Ktot, int dstOff, int rowOff,
                         const float* src, int lds, int segK, int nrows) {
    convw_k<<<2048, 256>>>(dst, Ktot, dstOff, rowOff, src, lds, segK, nrows);
}

extern "C" void kernel_launch(void* const* d_in, const int* in_sizes, int n_in,
                              void* d_out, int out_size) {
    const float* feats     = (const float*)d_in[0];
    const int*   sequences = (const int*)d_in[1];
    const int*   sizes     = (const int*)d_in[2];
    const float* emb       = (const float*)d_in[3];
    const float* td_wih    = (const float*)d_in[4];
    const float* td_whh    = (const float*)d_in[5];
    const float* td_b      = (const float*)d_in[6];
    const float* lang_wih  = (const float*)d_in[7];
    const float* lang_whh  = (const float*)d_in[8];
    const float* lang_b    = (const float*)d_in[9];
    const float* attf_w    = (const float*)d_in[10];
    const float* attf_b    = (const float*)d_in[11];
    const float* attd_w    = (const float*)d_in[12];
    const float* attd_b    = (const float*)d_in[13];
    const float* att_w     = (const float*)d_in[14];
    const float* att_b     = (const float*)d_in[15];
    const float* out_w     = (const float*)d_in[16];
    const float* out_b     = (const float*)d_in[17];
    const float* ar_wih    = (const float*)d_in[18];
    const float* ar_whh    = (const float*)d_in[19];
    const float* ar_b      = (const float*)d_in[20];
    const float* arl_w     = (const float*)d_in[21];
    const float* arl_b     = (const float*)d_in[22];
    float* out = (float*)d_out;

    float* p_favgW  = fsym(g_favgW);
    float* p_xe1    = fsym(g_xe1);
    float* p_imgatt = fsym(g_imgatt);
    float* p_gates1 = fsym(g_gates1);
    float* p_gates2 = fsym(g_gates2);
    float* p_g3q    = fsym(g_g3q);
    float* p_ARL    = fsym(g_ARL);
    float* p_b3q    = fsym(g_b3q);
    bf16 *pXfs = bsym(Xfs), *pXfavg = bsym(Xfavg), *pXebd = bsym(Xebd);
    bf16 *pX1 = bsym(X1), *pX2 = bsym(X2), *pX3 = bsym(X3);
    bf16 *pH2t = bsym(H2t), *pARNt = bsym(ARNt);
    bf16 *pWfavg = bsym(Wfavg), *pWxe = bsym(Wxe), *pW1 = bsym(W1p), *pW2 = bsym(W2p), *pW3 = bsym(W3p);
    bf16 *pWattf = bsym(Wattf), *pWout = bsym(Wout), *pWarl = bsym(Warl);
    void* pav = nullptr; cudaGetSymbolAddress(&pav, g_act);
    const unsigned char* p_act = (const unsigned char*)pav;

    // ---- setup: ordering, state, activations ----
    sort_k<<<1, B_>>>(sizes);
    init_act_k<<<(B_ * T_ + 255) / 256, 256>>>();
    zero_state_k<<<(B_ * D_ + 255) / 256, 256>>>();
    zerobf_k<<<2048, 256>>>(pX1, (size_t)B_ * 6144);
    zerobf_k<<<2048, 256>>>(pX2, (size_t)B_ * 12288);
    zerobf_k<<<2048, 256>>>(pX3, (size_t)B_ * 6144);
    zerobf_k<<<4096, 256>>>(pW3, (size_t)4608 * 6144);
    gather_fs_k<<<4096, 256>>>(feats);
    favg_k<<<(B_ * F_ + 255) / 256, 256>>>();
    gather_ebd_k<<<4096, 256>>>(sequences, emb);

    // ---- weight triples (once per launch) ----
    // td_wih cols: [h2 0..1023 | favg 1024..3071 | emb 3072..4095], lds 4096
    convw(pWfavg, 2048, 0, 0, td_wih + 1024, 4096, 2048, G_);
    convw(pWxe,   1024, 0, 0, td_wih + 3072, 4096, 1024, G_);
    convw(pW1, 2048, 0,    0, td_wih, 4096, 1024, G_);     // h2 seg
    convw(pW1, 2048, 1024, 0, td_whh, 1024, 1024, G_);     // h1 seg
    convw(pW2, 4096, 0,    0, lang_wih, 3072, 2048, G_);   // aw seg
    convw(pW2, 4096, 2048, 0, lang_wih + 2048, 3072, 1024, G_);  // h1n seg
    convw(pW2, 4096, 3072, 0, lang_whh, 1024, 1024, G_);   // h2 seg
    convw(pW3, 2048, 0,    0, ar_wih, 1024, 1024, G_);     // h1n seg (gates3 rows)
    convw(pW3, 2048, 1024, 0, ar_whh, 1024, 1024, G_);     // arh seg
    convw(pW3, 2048, 0, 4096, attd_w, 1024, 1024, A_);     // q rows (arh seg stays 0)
    convw(pWattf, 2048, 0, 0, attf_w, 2048, 2048, A_);
    convw(pWout, 1024, 0, 0, out_w, 1024, 1024, V_);
    convw(pWarl, 1024, 0, 0, arl_w, 1024, 1024, D_);
    pack_b3q_k<<<(4608 + 255) / 256, 256>>>(ar_b, attd_b);

    // ---- setup GEMMs ----
    bgemm(p_favgW, nullptr, 0, pXfavg, 6144, pWfavg, 6144, td_b, nullptr, B_, G_, 6144);
    bgemm(p_xe1, nullptr, 0, pXebd, 3072, pWxe, 3072, nullptr, nullptr, B_ * T_, G_, 3072);
    add_favg_k<<<4096, 256>>>();
    bgemm(p_imgatt, nullptr, 0, pXfs, 6144, pWattf, 6144, attf_b, nullptr, B_ * N_, A_, 6144);

    // ---- sequential decode: 7 launches/step ----
    for (int t = 0; t < T_; ++t) {
        bgemm(p_gates1, p_xe1 + (size_t)t * G_, T_ * G_, pX1, 6144, pW1, 6144, nullptr, nullptr, B_, G_, 6144);
        lstm1_ew_k<<<(B_ * D_ + 255) / 256, 256>>>();
        bgemm(p_g3q, nullptr, 0, pX3, 6144, pW3, 6144, p_b3q, nullptr, B_, 4608, 6144);
        attn_k<<<B_, 256>>>(att_w, att_b);
        bgemm(p_gates2, nullptr, 0, pX2, 12288, pW2, 12288, lang_b, nullptr, B_, G_, 12288);
        lstm2_ew_k<<<(B_ * D_ + 255) / 256, 256>>>(t);
        lstm3commit_k<<<(B_ * D_ + 255) / 256, 256>>>(t);
    }

    // ---- batched tail ----
    bgemm(out, nullptr, 0, pH2t, 3072, pWout, 3072, out_b, p_act, B_ * T_, V_, 3072);
    bgemm(p_ARL, nullptr, 0, pARNt, 3072, pWarl, 3072, arl_b, nullptr, B_ * T_, D_, 3072);
    loss_rows_k<<<B_ * T_, 256>>>();
    loss_final_k<<<1, 256>>>(out);
}

// round 11
// speedup vs baseline: 3.0113x; 2.1395x over previous
#include <cuda_runtime.h>
#include <cuda_fp16.h>
#include <math.h>
#include <stdint.h>

#define B_ 256
#define N_ 36
#define F_ 2048
#define L_ 26
#define A_ 512
#define E_ 1024
#define D_ 1024
#define V_ 10000
#define T_ 25
#define G_ 4096
typedef __half hf;

// ---------------- fp32 state / scratch ----------------
__device__ __align__(256) float g_fs[(size_t)B_ * N_ * F_];
__device__ __align__(256) float g_favgW[B_ * G_];
__device__ __align__(256) float g_xe1[(size_t)B_ * T_ * G_];
__device__ __align__(256) float g_imgatt[(size_t)B_ * N_ * A_];
__device__ __align__(256) float g_c1[B_ * D_], g_c2[B_ * D_], g_arc[B_ * D_], g_prevh1[B_ * D_];
__device__ __align__(256) float g_h1n[B_ * D_], g_c1n[B_ * D_], g_h2n[B_ * D_], g_c2n[B_ * D_];
__device__ __align__(256) float g_gates1[B_ * G_], g_gates2[B_ * G_], g_g3q[B_ * 4608];
__device__ __align__(256) float g_PREV[(size_t)B_ * T_ * D_];
__device__ __align__(256) float g_ARL[(size_t)B_ * T_ * D_];
__device__ __align__(256) float g_rowss[B_ * T_];
__device__ __align__(256) float g_b3q[4608];
__device__ int g_order[B_];
__device__ int g_declen[B_];
__device__ unsigned char g_act[B_ * T_];
// ---------------- fp16 operand buffers (single-pass) ----------------
__device__ __align__(256) hf Xfs[(size_t)B_ * N_ * F_];
__device__ __align__(256) hf Xfavg[(size_t)B_ * F_];
__device__ __align__(256) hf Xebd[(size_t)B_ * T_ * E_];
__device__ __align__(256) hf X1[(size_t)B_ * 2048];
__device__ __align__(256) hf X2[(size_t)B_ * 4096];
__device__ __align__(256) hf X3[(size_t)B_ * 2048];
__device__ __align__(256) hf H2t[(size_t)B_ * T_ * D_];
__device__ __align__(256) hf ARNt[(size_t)B_ * T_ * D_];
__device__ __align__(256) hf Wfavg[(size_t)G_ * F_];
__device__ __align__(256) hf Wxe[(size_t)G_ * E_];
__device__ __align__(256) hf W1p[(size_t)G_ * 2048];
__device__ __align__(256) hf W2p[(size_t)G_ * 4096];
__device__ __align__(256) hf W3p[(size_t)4608 * 2048];
__device__ __align__(256) hf Wattf[(size_t)A_ * F_];
__device__ __align__(256) hf Wout[(size_t)V_ * D_];
__device__ __align__(256) hf Warl[(size_t)D_ * D_];

__device__ __forceinline__ float sigm(float x) { return 1.f / (1.f + expf(-x)); }
__device__ __forceinline__ uint32_t smem_u32(const void* p) {
    uint32_t a;
    asm("{ .reg .u64 t; cvta.to.shared.u64 t, %1; cvt.u32.u64 %0, t; }" : "=r"(a) : "l"(p));
    return a;
}
__device__ __forceinline__ void cp16(uint32_t d, const void* s, bool ok) {
    asm volatile("cp.async.cg.shared.global [%0], [%1], 16, %2;" :: "r"(d), "l"(s), "r"(ok ? 16 : 0));
}
__device__ __forceinline__ void ldm_x4(uint32_t& r0, uint32_t& r1, uint32_t& r2, uint32_t& r3, uint32_t a) {
    asm volatile("ldmatrix.sync.aligned.m8n8.x4.shared.b16 {%0,%1,%2,%3}, [%4];"
                 : "=r"(r0), "=r"(r1), "=r"(r2), "=r"(r3) : "r"(a));
}
__device__ __forceinline__ void ldm_x2(uint32_t& r0, uint32_t& r1, uint32_t a) {
    asm volatile("ldmatrix.sync.aligned.m8n8.x2.shared.b16 {%0,%1}, [%2];"
                 : "=r"(r0), "=r"(r1) : "r"(a));
}
__device__ __forceinline__ void mma16816(float* c, const uint32_t* a, const uint32_t* b) {
    asm volatile("mma.sync.aligned.m16n8k16.row.col.f32.f16.f16.f32 "
                 "{%0,%1,%2,%3},{%4,%5,%6,%7},{%8,%9},{%0,%1,%2,%3};"
                 : "+f"(c[0]), "+f"(c[1]), "+f"(c[2]), "+f"(c[3])
                 : "r"(a[0]), "r"(a[1]), "r"(a[2]), "r"(a[3]), "r"(b[0]), "r"(b[1]));
}

// ======= pipelined fp16 GEMM: C[M,N] = A[M,K] @ W[N,K]^T, fp32 acc =======
// NF = B-fragments per warp (8 -> 128-wide N tile, 4 -> 64-wide)
#define SLD 40
template <int NF>
__global__ void __launch_bounds__(256) bgemm_k(
    float* __restrict__ C, const float* __restrict__ Cinit, int initLd,
    const hf* __restrict__ A, int lda, const hf* __restrict__ W, int ldw,
    const float* __restrict__ bias, const unsigned char* __restrict__ mask,
    int M, int N, int K)
{
    const int NT = NF * 16;  // W tile rows
    __shared__ __align__(16) hf sA[2][128][SLD];
    __shared__ __align__(16) hf sW[2][NF * 16][SLD];
    const int tid = threadIdx.x, wid = tid >> 5, lane = tid & 31;
    const int bm = blockIdx.y * 128, bn = blockIdx.x * (NF * 16);
    const int wm = (wid & 3) * 32, wn = (wid >> 2) * (NF * 8);
    float c[2][NF][4];
    #pragma unroll
    for (int i = 0; i < 2; ++i)
        #pragma unroll
        for (int j = 0; j < NF; ++j)
            #pragma unroll
            for (int k = 0; k < 4; ++k) c[i][j][k] = 0.f;

    const int lrow = tid >> 1, lcol = (tid & 1) * 16;
    const bool aok = (bm + lrow) < M;
    const bool wdo = lrow < NT;
    const bool wok = wdo && (bn + lrow) < N;
    const hf* aptr = A + (size_t)(bm + lrow) * lda + lcol;
    const hf* wptr = W + (size_t)(bn + (wdo ? lrow : 0)) * ldw + lcol;
    const int nch = K >> 5;

    {
        uint32_t da = smem_u32(&sA[0][lrow][lcol]);
        cp16(da, aptr, aok); cp16(da + 16, aptr + 8, aok);
        if (wdo) {
            uint32_t dw = smem_u32(&sW[0][lrow][lcol]);
            cp16(dw, wptr, wok); cp16(dw + 16, wptr + 8, wok);
        }
        asm volatile("cp.async.commit_group;" ::: "memory");
    }
    for (int ch = 0; ch < nch; ++ch) {
        asm volatile("cp.async.wait_group 0;" ::: "memory");
        __syncthreads();
        if (ch + 1 < nch) {
            int nb = (ch + 1) & 1;
            const hf* as = aptr + (ch + 1) * 32;
            uint32_t da = smem_u32(&sA[nb][lrow][lcol]);
            cp16(da, as, aok); cp16(da + 16, as + 8, aok);
            if (wdo) {
                const hf* ws = wptr + (ch + 1) * 32;
                uint32_t dw = smem_u32(&sW[nb][lrow][lcol]);
                cp16(dw, ws, wok); cp16(dw + 16, ws + 8, wok);
            }
            asm volatile("cp.async.commit_group;" ::: "memory");
        }
        const int bf = ch & 1;
        #pragma unroll
        for (int ks = 0; ks < 2; ++ks) {
            const int k0 = ks * 16;
            uint32_t Af[2][4], Bf[NF][2];
            const int arw = (lane & 15), akc = k0 + ((lane >> 4) << 3);
            #pragma unroll
            for (int mf = 0; mf < 2; ++mf)
                ldm_x4(Af[mf][0], Af[mf][1], Af[mf][2], Af[mf][3], smem_u32(&sA[bf][wm + mf * 16 + arw][akc]));
            const int l4 = lane & 15, brw = l4 & 7, bkc = k0 + ((l4 >> 3) & 1) * 8;
            #pragma unroll
            for (int nf = 0; nf < NF; ++nf)
                ldm_x2(Bf[nf][0], Bf[nf][1], smem_u32(&sW[bf][wn + nf * 8 + brw][bkc]));
            #pragma unroll
            for (int mf = 0; mf < 2; ++mf)
                #pragma unroll
                for (int nf = 0; nf < NF; ++nf) mma16816(c[mf][nf], Af[mf], Bf[nf]);
        }
    }

    #pragma unroll
    for (int mf = 0; mf < 2; ++mf) {
        #pragma unroll
        for (int half = 0; half < 2; ++half) {
            int m = bm + wm + mf * 16 + (lane >> 2) + half * 8;
            if (m >= M) continue;
            unsigned char mk = mask ? mask[m] : 1;
            #pragma unroll
            for (int nf = 0; nf < NF; ++nf) {
                #pragma unroll
                for (int e = 0; e < 2; ++e) {
                    int n = bn + wn + nf * 8 + (lane & 3) * 2 + e;
                    if (n >= N) continue;
                    float v = c[mf][nf][half * 2 + e];
                    if (bias) v += bias[n];
                    if (Cinit) v += Cinit[(size_t)m * initLd + n];
                    if (mask) v = mk ? v : 0.f;
                    C[(size_t)m * N + n] = v;
                }
            }
        }
    }
}

// ---------------- weight fp16 conversion ----------------
__global__ void convw_k(hf* __restrict__ dst, int Ktot, int dstOff, int rowOff,
                        const float* __restrict__ src, int lds, int segK, int nrows) {
    size_t total = (size_t)nrows * segK;
    for (size_t i = (size_t)blockIdx.x * blockDim.x + threadIdx.x; i < total;
         i += (size_t)gridDim.x * blockDim.x) {
        int n = (int)(i / segK), k = (int)(i - (size_t)n * segK);
        dst[(size_t)(n + rowOff) * Ktot + dstOff + k] = __float2half(src[(size_t)n * lds + k]);
    }
}
__global__ void zeroh_k(hf* p, size_t n) {
    for (size_t i = (size_t)blockIdx.x * blockDim.x + threadIdx.x; i < n;
         i += (size_t)gridDim.x * blockDim.x) p[i] = __float2half(0.f);
}
__global__ void pack_b3q_k(const float* __restrict__ arb, const float* __restrict__ attdb) {
    int i = blockIdx.x * blockDim.x + threadIdx.x;
    if (i < G_) g_b3q[i] = arb[i];
    else if (i < 4608) g_b3q[i] = attdb[i - G_];
}

// ---------------- setup ----------------
__global__ void sort_k(const int* __restrict__ sizes) {
    __shared__ int s[B_];
    int i = threadIdx.x;
    s[i] = sizes[i];
    __syncthreads();
    int my = s[i], rank = 0;
    for (int j = 0; j < B_; ++j) { int sj = s[j]; if (sj > my || (sj == my && j < i)) rank++; }
    g_order[rank] = i;
    g_declen[rank] = my - 1;
}
__global__ void init_act_k() {
    int idx = blockIdx.x * blockDim.x + threadIdx.x;
    if (idx < B_ * T_) { int b = idx / T_, t = idx - b * T_; g_act[idx] = (t < g_declen[b]) ? 1 : 0; }
}
__global__ void zero_state_k() {
    int idx = blockIdx.x * blockDim.x + threadIdx.x;
    if (idx < B_ * D_) { g_c1[idx] = 0.f; g_c2[idx] = 0.f; g_arc[idx] = 0.f; g_prevh1[idx] = 0.f; }
}
__global__ void gather_fs_k(const float* __restrict__ feats) {
    const size_t NF_ = (size_t)N_ * F_;
    size_t total = (size_t)B_ * NF_;
    for (size_t i = (size_t)blockIdx.x * blockDim.x + threadIdx.x; i < total;
         i += (size_t)gridDim.x * blockDim.x) {
        int b = (int)(i / NF_);
        size_t rem = i - (size_t)b * NF_;
        float v = feats[(size_t)g_order[b] * NF_ + rem];
        g_fs[i] = v;
        Xfs[i] = __float2half(v);
    }
}
__global__ void favg_k() {
    int idx = blockIdx.x * blockDim.x + threadIdx.x;
    if (idx < B_ * F_) {
        int b = idx / F_, f = idx - b * F_;
        const float* base = g_fs + (size_t)b * N_ * F_ + f;
        float s = 0.f;
        #pragma unroll
        for (int n = 0; n < N_; ++n) s += base[(size_t)n * F_];
        Xfavg[idx] = __float2half(s * (1.f / N_));
    }
}
__global__ void gather_ebd_k(const int* __restrict__ seqs, const float* __restrict__ emb) {
    size_t total = (size_t)B_ * T_ * E_;
    for (size_t i = (size_t)blockIdx.x * blockDim.x + threadIdx.x; i < total;
         i += (size_t)gridDim.x * blockDim.x) {
        int r = (int)(i / E_), e = (int)(i - (size_t)r * E_);
        int b = r / T_, t = r - b * T_;
        Xebd[i] = __float2half(emb[(size_t)seqs[g_order[b] * L_ + t] * E_ + e]);
    }
}
__global__ void add_favg_k() {
    const int per_r = G_ / 4;
    size_t total = (size_t)B_ * T_ * per_r;
    for (size_t i = (size_t)blockIdx.x * blockDim.x + threadIdx.x; i < total;
         i += (size_t)gridDim.x * blockDim.x) {
        int r = (int)(i / per_r), g4 = (int)(i - (size_t)r * per_r);
        float4 x = ((float4*)g_xe1)[i];
        float4 a = ((const float4*)g_favgW)[(size_t)(r / T_) * per_r + g4];
        x.x += a.x; x.y += a.y; x.z += a.z; x.w += a.w;
        ((float4*)g_xe1)[i] = x;
    }
}

// ---------------- step kernels ----------------
__global__ void lstm1_ew_k() {
    int idx = blockIdx.x * blockDim.x + threadIdx.x;
    if (idx >= B_ * D_) return;
    int b = idx / D_, d = idx - b * D_;
    const float* g = g_gates1 + (size_t)b * G_;
    float c = sigm(g[D_ + d]) * g_c1[idx] + sigm(g[d]) * tanhf(g[2 * D_ + d]);
    float h = sigm(g[3 * D_ + d]) * tanhf(c);
    g_c1n[idx] = c; g_h1n[idx] = h;
    hf hh = __float2half(h);
    X2[(size_t)b * 4096 + 2048 + d] = hh;
    X3[(size_t)b * 2048 + d] = hh;
}
__global__ void attn_k(const float* __restrict__ attw, const float* __restrict__ attb) {
    int b = blockIdx.x;
    int tid = threadIdx.x, warp = tid >> 5, lane = tid & 31;
    __shared__ float s_q[A_], s_w[A_], s_sc[N_], s_alpha[N_];
    for (int i = tid; i < A_; i += 256) { s_q[i] = g_g3q[(size_t)b * 4608 + G_ + i]; s_w[i] = attw[i]; }
    __syncthreads();
    for (int n = warp; n < N_; n += 8) {
        const float* row = g_imgatt + ((size_t)b * N_ + n) * A_;
        float p = 0.f;
        for (int a = lane; a < A_; a += 32) { float v = s_q[a] + row[a]; p += fmaxf(v, 0.f) * s_w[a]; }
        #pragma unroll
        for (int o = 16; o; o >>= 1) p += __shfl_xor_sync(0xffffffffu, p, o);
        if (lane == 0) s_sc[n] = p + attb[0];
    }
    __syncthreads();
    if (warp == 0) {
        float v0 = s_sc[lane], v1 = (lane + 32 < N_) ? s_sc[lane + 32] : -1e30f;
        float mx = fmaxf(v0, v1);
        #pragma unroll
        for (int o = 16; o; o >>= 1) mx = fmaxf(mx, __shfl_xor_sync(0xffffffffu, mx, o));
        float e0 = expf(v0 - mx), e1 = (lane + 32 < N_) ? expf(v1 - mx) : 0.f;
        float s = e0 + e1;
        #pragma unroll
        for (int o = 16; o; o >>= 1) s += __shfl_xor_sync(0xffffffffu, s, o);
        s_alpha[lane] = e0 / s;
        if (lane + 32 < N_) s_alpha[lane + 32] = e1 / s;
    }
    __syncthreads();
    for (int f = tid; f < F_; f += 256) {
        float acc = 0.f;
        const float* fb = g_fs + (size_t)b * N_ * F_ + f;
        #pragma unroll
        for (int n = 0; n < N_; ++n) acc += s_alpha[n] * fb[(size_t)n * F_];
        X2[(size_t)b * 4096 + f] = __float2half(acc);
    }
}
__global__ void lstm2_ew_k(int t) {
    int idx = blockIdx.x * blockDim.x + threadIdx.x;
    if (idx >= B_ * D_) return;
    int b = idx / D_, d = idx - b * D_;
    const float* g = g_gates2 + (size_t)b * G_;
    float c = sigm(g[D_ + d]) * g_c2[idx] + sigm(g[d]) * tanhf(g[2 * D_ + d]);
    float h = sigm(g[3 * D_ + d]) * tanhf(c);
    g_c2n[idx] = c; g_h2n[idx] = h;
    H2t[((size_t)b * T_ + t) * D_ + d] = __float2half(h);
}
__global__ void lstm3commit_k(int t) {
    int idx = blockIdx.x * blockDim.x + threadIdx.x;
    if (idx >= B_ * D_) return;
    int b = idx / D_, d = idx - b * D_;
    const float* g = g_g3q + (size_t)b * 4608;
    float c = sigm(g[D_ + d]) * g_arc[idx] + sigm(g[d]) * tanhf(g[2 * D_ + d]);
    float arhn = sigm(g[3 * D_ + d]) * tanhf(c);
    ARNt[((size_t)b * T_ + t) * D_ + d] = __float2half(arhn);
    g_PREV[((size_t)b * T_ + t) * D_ + d] = g_prevh1[idx];
    if (g_act[b * T_ + t]) {
        float h1n = g_h1n[idx], h2n = g_h2n[idx];
        g_c1[idx] = g_c1n[idx]; g_c2[idx] = g_c2n[idx]; g_arc[idx] = c; g_prevh1[idx] = h1n;
        X1[(size_t)b * 2048 + 1024 + d] = __float2half(h1n);
        X1[(size_t)b * 2048 + d] = __float2half(h2n);
        X2[(size_t)b * 4096 + 3072 + d] = __float2half(h2n);
        X3[(size_t)b * 2048 + 1024 + d] = __float2half(arhn);
    }
}

// ---------------- loss ----------------
__global__ void loss_rows_k() {
    int r = blockIdx.x, t = r % T_, tid = threadIdx.x;
    float p = 0.f;
    if (t > 0 && g_act[r]) {
        const float* a = g_ARL + (size_t)r * D_;
        const float* pv = g_PREV + (size_t)r * D_;
        for (int d = tid; d < D_; d += 256) { float df = a[d] - pv[d]; p += df * df; }
    }
    __shared__ float sred[256];
    sred[tid] = p;
    __syncthreads();
    for (int o = 128; o; o >>= 1) { if (tid < o) sred[tid] += sred[tid + o]; __syncthreads(); }
    if (tid == 0) g_rowss[r] = sred[0];
}
__global__ void loss_final_k(float* __restrict__ out) {
    __shared__ float ss[256], sc[256];
    int tid = threadIdx.x;
    float total = 0.f;
    for (int t = 1; t < T_; ++t) {
        float s = 0.f, c = 0.f;
        for (int b = tid; b < B_; b += 256) {
            s += g_rowss[b * T_ + t];
            c += g_act[b * T_ + t] ? 1.f : 0.f;
        }
        ss[tid] = s; sc[tid] = c;
        __syncthreads();
        for (int o = 128; o; o >>= 1) { if (tid < o) { ss[tid] += ss[tid + o]; sc[tid] += sc[tid + o]; } __syncthreads(); }
        if (tid == 0) total += ss[0] / fmaxf(sc[0], 1.f) * 0.005f;
        __syncthreads();
    }
    if (tid == 0) out[(size_t)B_ * T_ * V_] = total;
}

// ---------------- host ----------------
static inline float* fsym(const void* s) { void* p = nullptr; cudaGetSymbolAddress(&p, s); return (float*)p; }
static inline hf* hsym(const void* s) { void* p = nullptr; cudaGetSymbolAddress(&p, s); return (hf*)p; }

static inline void bgemm128(float* C, const float* Cinit, int initLd,
                            const hf* A, int lda, const hf* W, int ldw,
                            const float* bias, const unsigned char* mask, int M, int N, int K) {
    dim3 grid((N + 127) / 128, (M + 127) / 128);
    bgemm_k<8><<<grid, 256>>>(C, Cinit, initLd, A, lda, W, ldw, bias, mask, M, N, K);
}
static inline void bgemm64(float* C, const float* Cinit, int initLd,
                           const hf* A, int lda, const hf* W, int ldw,
                           const float* bias, const unsigned char* mask, int M, int N, int K) {
    dim3 grid((N + 63) / 64, (M + 127) / 128);
    bgemm_k<4><<<grid, 256>>>(C, Cinit, initLd, A, lda, W, ldw, bias, mask, M, N, K);
}
static inline void convw(hf* dst, int Ktot, int dstOff, int rowOff,
                         const float* src, int lds, int segK, int nrows) {
    convw_k<<<2048, 256>>>(dst, Ktot, dstOff, rowOff, src, lds, segK, nrows);
}

extern "C" void kernel_launch(void* const* d_in, const int* in_sizes, int n_in,
                              void* d_out, int out_size) {
    const float* feats     = (const float*)d_in[0];
    const int*   sequences = (const int*)d_in[1];
    const int*   sizes     = (const int*)d_in[2];
    const float* emb       = (const float*)d_in[3];
    const float* td_wih    = (const float*)d_in[4];
    const float* td_whh    = (const float*)d_in[5];
    const float* td_b      = (const float*)d_in[6];
    const float* lang_wih  = (const float*)d_in[7];
    const float* lang_whh  = (const float*)d_in[8];
    const float* lang_b    = (const float*)d_in[9];
    const float* attf_w    = (const float*)d_in[10];
    const float* attf_b    = (const float*)d_in[11];
    const float* attd_w    = (const float*)d_in[12];
    const float* attd_b    = (const float*)d_in[13];
    const float* att_w     = (const float*)d_in[14];
    const float* att_b     = (const float*)d_in[15];
    const float* out_w     = (const float*)d_in[16];
    const float* out_b     = (const float*)d_in[17];
    const float* ar_wih    = (const float*)d_in[18];
    const float* ar_whh    = (const float*)d_in[19];
    const float* ar_b      = (const float*)d_in[20];
    const float* arl_w     = (const float*)d_in[21];
    const float* arl_b     = (const float*)d_in[22];
    float* out = (float*)d_out;

    float* p_favgW  = fsym(g_favgW);
    float* p_xe1    = fsym(g_xe1);
    float* p_imgatt = fsym(g_imgatt);
    float* p_gates1 = fsym(g_gates1);
    float* p_gates2 = fsym(g_gates2);
    float* p_g3q    = fsym(g_g3q);
    float* p_ARL    = fsym(g_ARL);
    float* p_b3q    = fsym(g_b3q);
    hf *pXfs = hsym(Xfs), *pXfavg = hsym(Xfavg), *pXebd = hsym(Xebd);
    hf *pX1 = hsym(X1), *pX2 = hsym(X2), *pX3 = hsym(X3);
    hf *pH2t = hsym(H2t), *pARNt = hsym(ARNt);
    hf *pWfavg = hsym(Wfavg), *pWxe = hsym(Wxe), *pW1 = hsym(W1p), *pW2 = hsym(W2p), *pW3 = hsym(W3p);
    hf *pWattf = hsym(Wattf), *pWout = hsym(Wout), *pWarl = hsym(Warl);
    void* pav = nullptr; cudaGetSymbolAddress(&pav, g_act);
    const unsigned char* p_act = (const unsigned char*)pav;

    // ---- setup: ordering, state, activations ----
    sort_k<<<1, B_>>>(sizes);
    init_act_k<<<(B_ * T_ + 255) / 256, 256>>>();
    zero_state_k<<<(B_ * D_ + 255) / 256, 256>>>();
    zeroh_k<<<1024, 256>>>(pX1, (size_t)B_ * 2048);
    zeroh_k<<<1024, 256>>>(pX2, (size_t)B_ * 4096);
    zeroh_k<<<1024, 256>>>(pX3, (size_t)B_ * 2048);
    zeroh_k<<<2048, 256>>>(pW3, (size_t)4608 * 2048);
    gather_fs_k<<<4096, 256>>>(feats);
    favg_k<<<(B_ * F_ + 255) / 256, 256>>>();
    gather_ebd_k<<<4096, 256>>>(sequences, emb);

    // ---- fp16 weights (once per launch) ----
    // td_wih cols: [h2 0..1023 | favg 1024..3071 | emb 3072..4095], lds 4096
    convw(pWfavg, 2048, 0, 0, td_wih + 1024, 4096, 2048, G_);
    convw(pWxe,   1024, 0, 0, td_wih + 3072, 4096, 1024, G_);
    convw(pW1, 2048, 0,    0, td_wih, 4096, 1024, G_);          // h2 seg
    convw(pW1, 2048, 1024, 0, td_whh, 1024, 1024, G_);          // h1 seg
    convw(pW2, 4096, 0,    0, lang_wih, 3072, 2048, G_);        // aw seg
    convw(pW2, 4096, 2048, 0, lang_wih + 2048, 3072, 1024, G_); // h1n seg
    convw(pW2, 4096, 3072, 0, lang_whh, 1024, 1024, G_);        // h2 seg
    convw(pW3, 2048, 0,    0, ar_wih, 1024, 1024, G_);          // h1n seg (gates3 rows)
    convw(pW3, 2048, 1024, 0, ar_whh, 1024, 1024, G_);          // arh seg
    convw(pW3, 2048, 0, 4096, attd_w, 1024, 1024, A_);          // q rows (arh seg stays 0)
    convw(pWattf, 2048, 0, 0, attf_w, 2048, 2048, A_);
    convw(pWout, 1024, 0, 0, out_w, 1024, 1024, V_);
    convw(pWarl, 1024, 0, 0, arl_w, 1024, 1024, D_);
    pack_b3q_k<<<(4608 + 255) / 256, 256>>>(ar_b, attd_b);

    // ---- setup GEMMs ----
    bgemm128(p_favgW, nullptr, 0, pXfavg, 2048, pWfavg, 2048, td_b, nullptr, B_, G_, 2048);
    bgemm128(p_xe1, nullptr, 0, pXebd, 1024, pWxe, 1024, nullptr, nullptr, B_ * T_, G_, 1024);
    add_favg_k<<<4096, 256>>>();
    bgemm128(p_imgatt, nullptr, 0, pXfs, 2048, pWattf, 2048, attf_b, nullptr, B_ * N_, A_, 2048);

    // ---- sequential decode: 7 launches/step ----
    for (int t = 0; t < T_; ++t) {
        bgemm64(p_gates1, p_xe1 + (size_t)t * G_, T_ * G_, pX1, 2048, pW1, 2048, nullptr, nullptr, B_, G_, 2048);
        lstm1_ew_k<<<(B_ * D_ + 255) / 256, 256>>>();
        bgemm64(p_g3q, nullptr, 0, pX3, 2048, pW3, 2048, p_b3q, nullptr, B_, 4608, 2048);
        attn_k<<<B_, 256>>>(att_w, att_b);
        bgemm64(p_gates2, nullptr, 0, pX2, 4096, pW2, 4096, lang_b, nullptr, B_, G_, 4096);
        lstm2_ew_k<<<(B_ * D_ + 255) / 256, 256>>>(t);
        lstm3commit_k<<<(B_ * D_ + 255) / 256, 256>>>(t);
    }

    // ---- batched tail ----
    bgemm128(out, nullptr, 0, pH2t, 1024, pWout, 1024, out_b, p_act, B_ * T_, V_, 1024);
    bgemm128(p_ARL, nullptr, 0, pARNt, 1024, pWarl, 1024, arl_b, nullptr, B_ * T_, D_, 1024);
    loss_rows_k<<<B_ * T_, 256>>>();
    loss_final_k<<<1, 256>>>(out);
}

// round 13
// speedup vs baseline: 3.4879x; 1.1583x over previous
#include <cuda_runtime.h>
#include <cuda_fp16.h>
#include <math.h>
#include <stdint.h>

#define B_ 256
#define N_ 36
#define F_ 2048
#define L_ 26
#define A_ 512
#define E_ 1024
#define D_ 1024
#define V_ 10000
#define T_ 25
#define G_ 4096
typedef __half hf;

// ---------------- fp32 state / scratch ----------------
__device__ __align__(256) float g_fs[(size_t)B_ * N_ * F_];
__device__ __align__(256) float g_favgW[B_ * G_];
__device__ __align__(256) float g_xe1[(size_t)B_ * T_ * G_];
__device__ __align__(256) float g_imgatt[(size_t)B_ * N_ * A_];
__device__ __align__(256) float g_c1[B_ * D_], g_c2[B_ * D_], g_arc[B_ * D_], g_prevh1[B_ * D_];
__device__ __align__(256) float g_q[B_ * A_];
__device__ __align__(256) float g_PREV[(size_t)B_ * T_ * D_];
__device__ __align__(256) float g_ARL[(size_t)B_ * T_ * D_];
__device__ __align__(256) float g_rowss[B_ * T_];
__device__ __align__(256) float g_b3q[4608];
__device__ __align__(256) float g_tdb_p[G_];
__device__ __align__(256) float g_langb_p[G_];
__device__ int g_order[B_];
__device__ int g_declen[B_];
__device__ int g_actrow[B_ * T_];
__device__ int g_cidx[B_ * T_];
__device__ int g_meta[T_ + 1];
__device__ unsigned char g_act[B_ * T_];
// ---------------- fp16 operand buffers (recurrent ones double-buffered) ----------------
__device__ __align__(256) hf Xfs[(size_t)B_ * N_ * F_];
__device__ __align__(256) hf Xfavg[(size_t)B_ * F_];
__device__ __align__(256) hf Xebd[(size_t)B_ * T_ * E_];
__device__ __align__(256) hf X1b[2][(size_t)B_ * 2048];
__device__ __align__(256) hf X2b[2][(size_t)B_ * 4096];
__device__ __align__(256) hf X3b[2][(size_t)B_ * 2048];
__device__ __align__(256) hf H2c[(size_t)B_ * T_ * D_];
__device__ __align__(256) hf ARNt[(size_t)B_ * T_ * D_];
__device__ __align__(256) hf Wfavg[(size_t)G_ * F_];
__device__ __align__(256) hf Wxe[(size_t)G_ * E_];
__device__ __align__(256) hf W1p[(size_t)G_ * 2048];
__device__ __align__(256) hf W2p[(size_t)G_ * 4096];
__device__ __align__(256) hf W3p[(size_t)4608 * 2048];
__device__ __align__(256) hf Wattf[(size_t)A_ * F_];
__device__ __align__(256) hf Wout[(size_t)V_ * D_];
__device__ __align__(256) hf Warl[(size_t)D_ * D_];

__device__ __forceinline__ float sigm(float x) { return 1.f / (1.f + expf(-x)); }
__device__ __forceinline__ uint32_t smem_u32(const void* p) {
    uint32_t a;
    asm("{ .reg .u64 t; cvta.to.shared.u64 t, %1; cvt.u32.u64 %0, t; }" : "=r"(a) : "l"(p));
    return a;
}
__device__ __forceinline__ void cp16(uint32_t d, const void* s, bool ok) {
    asm volatile("cp.async.cg.shared.global [%0], [%1], 16, %2;" :: "r"(d), "l"(s), "r"(ok ? 16 : 0));
}
__device__ __forceinline__ void ldm_x4(uint32_t& r0, uint32_t& r1, uint32_t& r2, uint32_t& r3, uint32_t a) {
    asm volatile("ldmatrix.sync.aligned.m8n8.x4.shared.b16 {%0,%1,%2,%3}, [%4];"
                 : "=r"(r0), "=r"(r1), "=r"(r2), "=r"(r3) : "r"(a));
}
__device__ __forceinline__ void ldm_x2(uint32_t& r0, uint32_t& r1, uint32_t a) {
    asm volatile("ldmatrix.sync.aligned.m8n8.x2.shared.b16 {%0,%1}, [%2];"
                 : "=r"(r0), "=r"(r1) : "r"(a));
}
__device__ __forceinline__ void mma16816(float* c, const uint32_t* a, const uint32_t* b) {
    asm volatile("mma.sync.aligned.m16n8k16.row.col.f32.f16.f16.f32 "
                 "{%0,%1,%2,%3},{%4,%5,%6,%7},{%8,%9},{%0,%1,%2,%3};"
                 : "+f"(c[0]), "+f"(c[1]), "+f"(c[2]), "+f"(c[3])
                 : "r"(a[0]), "r"(a[1]), "r"(a[2]), "r"(a[3]), "r"(b[0]), "r"(b[1]));
}

// ======= pipelined fp16 GEMM with fused LSTM epilogues =======
// EPI: 0 plain (opt rowmap scatter), 1 LSTM1, 2 LSTM2, 3 LSTM3+q
#define SLD 40
template <int NF, int EPI>
__global__ void __launch_bounds__(256) bgemm_k(
    float* __restrict__ C, const float* __restrict__ Cinit, int initLd,
    const hf* __restrict__ A, int lda, const hf* __restrict__ W, int ldw,
    const float* __restrict__ bias, const int* __restrict__ rowmap,
    const int* __restrict__ cntp, int M, int N, int K, int t)
{
    const int NT = NF * 16;
    const int bm = blockIdx.y * 128, bn = blockIdx.x * (NF * 16);
    int nact = M;
    if (cntp) { nact = *cntp; if (bm >= nact) return; }
    __shared__ __align__(16) hf sA[2][128][SLD];
    __shared__ __align__(16) hf sW[2][NF * 16][SLD];
    const int tid = threadIdx.x, wid = tid >> 5, lane = tid & 31;
    const int wm = (wid & 3) * 32, wn = (wid >> 2) * (NF * 8);
    float c[2][NF][4];
    #pragma unroll
    for (int i = 0; i < 2; ++i)
        #pragma unroll
        for (int j = 0; j < NF; ++j)
            #pragma unroll
            for (int k = 0; k < 4; ++k) c[i][j][k] = 0.f;

    const int lrow = tid >> 1, lcol = (tid & 1) * 16;
    const bool aok = (bm + lrow) < M;
    const bool wdo = lrow < NT;
    const bool wok = wdo && (bn + lrow) < N;
    const hf* aptr = A + (size_t)(bm + lrow) * lda + lcol;
    const hf* wptr = W + (size_t)(bn + (wdo ? lrow : 0)) * ldw + lcol;
    const int nch = K >> 5;

    {
        uint32_t da = smem_u32(&sA[0][lrow][lcol]);
        cp16(da, aptr, aok); cp16(da + 16, aptr + 8, aok);
        if (wdo) {
            uint32_t dw = smem_u32(&sW[0][lrow][lcol]);
            cp16(dw, wptr, wok); cp16(dw + 16, wptr + 8, wok);
        }
        asm volatile("cp.async.commit_group;" ::: "memory");
    }
    for (int ch = 0; ch < nch; ++ch) {
        asm volatile("cp.async.wait_group 0;" ::: "memory");
        __syncthreads();
        if (ch + 1 < nch) {
            int nb = (ch + 1) & 1;
            const hf* as = aptr + (ch + 1) * 32;
            uint32_t da = smem_u32(&sA[nb][lrow][lcol]);
            cp16(da, as, aok); cp16(da + 16, as + 8, aok);
            if (wdo) {
                const hf* ws = wptr + (ch + 1) * 32;
                uint32_t dw = smem_u32(&sW[nb][lrow][lcol]);
                cp16(dw, ws, wok); cp16(dw + 16, ws + 8, wok);
            }
            asm volatile("cp.async.commit_group;" ::: "memory");
        }
        const int bf = ch & 1;
        #pragma unroll
        for (int ks = 0; ks < 2; ++ks) {
            const int k0 = ks * 16;
            uint32_t Af[2][4], Bf[NF][2];
            const int arw = (lane & 15), akc = k0 + ((lane >> 4) << 3);
            #pragma unroll
            for (int mf = 0; mf < 2; ++mf)
                ldm_x4(Af[mf][0], Af[mf][1], Af[mf][2], Af[mf][3], smem_u32(&sA[bf][wm + mf * 16 + arw][akc]));
            const int l4 = lane & 15, brw = l4 & 7, bkc = k0 + ((l4 >> 3) & 1) * 8;
            #pragma unroll
            for (int nf = 0; nf < NF; ++nf)
                ldm_x2(Bf[nf][0], Bf[nf][1], smem_u32(&sW[bf][wn + nf * 8 + brw][bkc]));
            #pragma unroll
            for (int mf = 0; mf < 2; ++mf)
                #pragma unroll
                for (int nf = 0; nf < NF; ++nf) mma16816(c[mf][nf], Af[mf], Bf[nf]);
        }
    }

    // ---- epilogue ----
    const int par = t & 1, nxt = par ^ 1;
    #pragma unroll
    for (int mf = 0; mf < 2; ++mf) {
        #pragma unroll
        for (int half = 0; half < 2; ++half) {
            const int m = bm + wm + mf * 16 + (lane >> 2) + half * 8;
            const bool mok = (m < M) && (m < nact);
            #pragma unroll
            for (int nf = 0; nf < NF; ++nf) {
                const int n0 = bn + wn + nf * 8 + (lane & 3) * 2;
                float v0 = c[mf][nf][half * 2 + 0];
                float v1 = c[mf][nf][half * 2 + 1];
                if (EPI == 0) {
                    if (mok) {
                        int mrow = rowmap ? rowmap[m] : m;
                        #pragma unroll
                        for (int e = 0; e < 2; ++e) {
                            int n = n0 + e;
                            if (n >= N) break;
                            float v = (e == 0) ? v0 : v1;
                            if (bias) v += bias[n];
                            if (Cinit) v += Cinit[(size_t)m * initLd + n];
                            C[(size_t)mrow * N + n] = v;
                        }
                    }
                } else {
                    if (Cinit && mok) {
                        v0 += Cinit[(size_t)m * initLd + n0];
                        v1 += Cinit[(size_t)m * initLd + n0 + 1];
                    }
                    if (bias) { v0 += bias[n0]; v1 += bias[n0 + 1]; }
                    float o0 = __shfl_xor_sync(0xffffffffu, v0, 1);
                    float o1 = __shfl_xor_sync(0xffffffffu, v1, 1);
                    if (EPI == 3 && n0 >= 4096) {
                        if (mok) {
                            g_q[(size_t)m * A_ + (n0 - 4096)] = v0;
                            g_q[(size_t)m * A_ + (n0 - 4095)] = v1;
                        }
                    } else if ((lane & 1) == 0 && mok) {
                        int d = n0 >> 2;
                        int idx = m * D_ + d;
                        int r = m * T_ + t;
                        float ig = sigm(v0), fg = sigm(v1);
                        float gg = tanhf(o0), og = sigm(o1);
                        unsigned char act = g_act[r];
                        if (EPI == 1) {
                            float cn = fg * g_c1[idx] + ig * gg;
                            float h = og * tanhf(cn);
                            hf h16 = __float2half(h);
                            // same-step consumers (later launches): current-parity buffers
                            X2b[par][(size_t)m * 4096 + 2048 + d] = h16;
                            X3b[par][(size_t)m * 2048 + d] = h16;
                            g_PREV[(size_t)r * D_ + d] = g_prevh1[idx];
                            if (act) {
                                g_c1[idx] = cn; g_prevh1[idx] = h;
                                X1b[nxt][(size_t)m * 2048 + 1024 + d] = h16;  // next step
                            }
                        } else if (EPI == 2) {
                            float cn = fg * g_c2[idx] + ig * gg;
                            float h = og * tanhf(cn);
                            hf h16 = __float2half(h);
                            if (act) {
                                g_c2[idx] = cn;
                                X1b[nxt][(size_t)m * 2048 + d] = h16;         // next step
                                X2b[nxt][(size_t)m * 4096 + 3072 + d] = h16;  // next step
                                H2c[(size_t)g_cidx[r] * D_ + d] = h16;
                            }
                        } else {  // EPI == 3
                            float cn = fg * g_arc[idx] + ig * gg;
                            float h = og * tanhf(cn);
                            hf h16 = __float2half(h);
                            ARNt[(size_t)r * D_ + d] = h16;
                            if (act) {
                                g_arc[idx] = cn;
                                X3b[nxt][(size_t)m * 2048 + 1024 + d] = h16;  // next step
                            }
                        }
                    }
                }
            }
        }
    }
}

// ---------------- weight fp16 conversion (opt gate interleave) ----------------
__global__ void convw_k(hf* __restrict__ dst, int Ktot, int dstOff, int rowOff,
                        const float* __restrict__ src, int lds, int segK, int nrows, int perm) {
    size_t total = (size_t)nrows * segK;
    for (size_t i = (size_t)blockIdx.x * blockDim.x + threadIdx.x; i < total;
         i += (size_t)gridDim.x * blockDim.x) {
        int n = (int)(i / segK), k = (int)(i - (size_t)n * segK);
        int nd = perm ? (4 * (n & 1023) + (n >> 10)) : n;
        dst[(size_t)(nd + rowOff) * Ktot + dstOff + k] = __float2half(src[(size_t)n * lds + k]);
    }
}
__global__ void zeroh_k(hf* p, size_t n) {
    for (size_t i = (size_t)blockIdx.x * blockDim.x + threadIdx.x; i < n;
         i += (size_t)gridDim.x * blockDim.x) p[i] = __float2half(0.f);
}
__global__ void zero_out_k(float* p, size_t n) {
    size_t n4 = n >> 2;
    for (size_t i = (size_t)blockIdx.x * blockDim.x + threadIdx.x; i < n4;
         i += (size_t)gridDim.x * blockDim.x) ((float4*)p)[i] = make_float4(0, 0, 0, 0);
}
__global__ void permb_k(const float* __restrict__ tdb, const float* __restrict__ langb,
                        const float* __restrict__ arb, const float* __restrict__ attdb) {
    int i = blockIdx.x * blockDim.x + threadIdx.x;
    if (i < G_) {
        int pd = 4 * (i & 1023) + (i >> 10);
        g_tdb_p[pd] = tdb[i];
        g_langb_p[pd] = langb[i];
        g_b3q[pd] = arb[i];
    } else if (i < 4608) {
        g_b3q[i] = attdb[i - G_];
    }
}

// ---------------- setup ----------------
__global__ void sort_k(const int* __restrict__ sizes) {
    __shared__ int s[B_];
    int i = threadIdx.x;
    s[i] = sizes[i];
    __syncthreads();
    int my = s[i], rank = 0;
    for (int j = 0; j < B_; ++j) { int sj = s[j]; if (sj > my || (sj == my && j < i)) rank++; }
    g_order[rank] = i;
    g_declen[rank] = my - 1;
}
__global__ void init_act_k() {
    int idx = blockIdx.x * blockDim.x + threadIdx.x;
    if (idx < B_ * T_) { int b = idx / T_, t = idx - b * T_; g_act[idx] = (t < g_declen[b]) ? 1 : 0; }
}
__global__ void scan_k() {
    if (threadIdx.x != 0) return;
    int j = 0;
    for (int r = 0; r < B_ * T_; ++r) {
        if (g_act[r]) { g_cidx[r] = j; g_actrow[j] = r; j++; }
        else g_cidx[r] = -1;
    }
    g_meta[T_] = j;
    for (int t = 0; t < T_; ++t) {
        int cnt = 0;
        for (int b = 0; b < B_; ++b) cnt += g_act[b * T_ + t];
        g_meta[t] = cnt;
    }
}
__global__ void zero_state_k() {
    int idx = blockIdx.x * blockDim.x + threadIdx.x;
    if (idx < B_ * D_) { g_c1[idx] = 0.f; g_c2[idx] = 0.f; g_arc[idx] = 0.f; g_prevh1[idx] = 0.f; }
}
__global__ void gather_fs_k(const float* __restrict__ feats) {
    const size_t NF_ = (size_t)N_ * F_;
    size_t total = (size_t)B_ * NF_;
    for (size_t i = (size_t)blockIdx.x * blockDim.x + threadIdx.x; i < total;
         i += (size_t)gridDim.x * blockDim.x) {
        int b = (int)(i / NF_);
        size_t rem = i - (size_t)b * NF_;
        float v = feats[(size_t)g_order[b] * NF_ + rem];
        g_fs[i] = v;
        Xfs[i] = __float2half(v);
    }
}
__global__ void favg_k() {
    int idx = blockIdx.x * blockDim.x + threadIdx.x;
    if (idx < B_ * F_) {
        int b = idx / F_, f = idx - b * F_;
        const float* base = g_fs + (size_t)b * N_ * F_ + f;
        float s = 0.f;
        #pragma unroll
        for (int n = 0; n < N_; ++n) s += base[(size_t)n * F_];
        Xfavg[idx] = __float2half(s * (1.f / N_));
    }
}
__global__ void gather_ebd_k(const int* __restrict__ seqs, const float* __restrict__ emb) {
    size_t total = (size_t)B_ * T_ * E_;
    for (size_t i = (size_t)blockIdx.x * blockDim.x + threadIdx.x; i < total;
         i += (size_t)gridDim.x * blockDim.x) {
        int r = (int)(i / E_), e = (int)(i - (size_t)r * E_);
        int b = r / T_, t = r - b * T_;
        Xebd[i] = __float2half(emb[(size_t)seqs[g_order[b] * L_ + t] * E_ + e]);
    }
}
__global__ void add_favg_k() {
    const int per_r = G_ / 4;
    size_t total = (size_t)B_ * T_ * per_r;
    for (size_t i = (size_t)blockIdx.x * blockDim.x + threadIdx.x; i < total;
         i += (size_t)gridDim.x * blockDim.x) {
        int r = (int)(i / per_r), g4 = (int)(i - (size_t)r * per_r);
        float4 x = ((float4*)g_xe1)[i];
        float4 a = ((const float4*)g_favgW)[(size_t)(r / T_) * per_r + g4];
        x.x += a.x; x.y += a.y; x.z += a.z; x.w += a.w;
        ((float4*)g_xe1)[i] = x;
    }
}

// ---------------- attention (writes aw into current-parity X2 buffer) ----------------
__global__ void attn_k(const float* __restrict__ attw, const float* __restrict__ attb, int t) {
    int b = blockIdx.x;
    int tid = threadIdx.x, warp = tid >> 5, lane = tid & 31;
    __shared__ float s_q[A_], s_w[A_], s_sc[N_], s_alpha[N_];
    for (int i = tid; i < A_; i += 256) { s_q[i] = g_q[b * A_ + i]; s_w[i] = attw[i]; }
    __syncthreads();
    for (int n = warp; n < N_; n += 8) {
        const float* row = g_imgatt + ((size_t)b * N_ + n) * A_;
        float p = 0.f;
        for (int a = lane; a < A_; a += 32) { float v = s_q[a] + row[a]; p += fmaxf(v, 0.f) * s_w[a]; }
        #pragma unroll
        for (int o = 16; o; o >>= 1) p += __shfl_xor_sync(0xffffffffu, p, o);
        if (lane == 0) s_sc[n] = p + attb[0];
    }
    __syncthreads();
    if (warp == 0) {
        float v0 = s_sc[lane], v1 = (lane + 32 < N_) ? s_sc[lane + 32] : -1e30f;
        float mx = fmaxf(v0, v1);
        #pragma unroll
        for (int o = 16; o; o >>= 1) mx = fmaxf(mx, __shfl_xor_sync(0xffffffffu, mx, o));
        float e0 = expf(v0 - mx), e1 = (lane + 32 < N_) ? expf(v1 - mx) : 0.f;
        float s = e0 + e1;
        #pragma unroll
        for (int o = 16; o; o >>= 1) s += __shfl_xor_sync(0xffffffffu, s, o);
        s_alpha[lane] = e0 / s;
        if (lane + 32 < N_) s_alpha[lane + 32] = e1 / s;
    }
    __syncthreads();
    hf* x2 = X2b[t & 1];
    for (int f = tid; f < F_; f += 256) {
        float acc = 0.f;
        const float* fb = g_fs + (size_t)b * N_ * F_ + f;
        #pragma unroll
        for (int n = 0; n < N_; ++n) acc += s_alpha[n] * fb[(size_t)n * F_];
        x2[(size_t)b * 4096 + f] = __float2half(acc);
    }
}

// ---------------- loss ----------------
__global__ void loss_rows_k() {
    int r = blockIdx.x, t = r % T_, tid = threadIdx.x;
    float p = 0.f;
    if (t > 0 && g_act[r]) {
        const float* a = g_ARL + (size_t)r * D_;
        const float* pv = g_PREV + (size_t)r * D_;
        for (int d = tid; d < D_; d += 256) { float df = a[d] - pv[d]; p += df * df; }
    }
    __shared__ float sred[256];
    sred[tid] = p;
    __syncthreads();
    for (int o = 128; o; o >>= 1) { if (tid < o) sred[tid] += sred[tid + o]; __syncthreads(); }
    if (tid == 0) g_rowss[r] = sred[0];
}
__global__ void loss_final_k(float* __restrict__ out) {
    __shared__ float ss[256], sc[256];
    int tid = threadIdx.x;
    float total = 0.f;
    for (int t = 1; t < T_; ++t) {
        float s = 0.f, c = 0.f;
        for (int b = tid; b < B_; b += 256) {
            s += g_rowss[b * T_ + t];
            c += g_act[b * T_ + t] ? 1.f : 0.f;
        }
        ss[tid] = s; sc[tid] = c;
        __syncthreads();
        for (int o = 128; o; o >>= 1) { if (tid < o) { ss[tid] += ss[tid + o]; sc[tid] += sc[tid + o]; } __syncthreads(); }
        if (tid == 0) total += ss[0] / fmaxf(sc[0], 1.f) * 0.005f;
        __syncthreads();
    }
    if (tid == 0) out[(size_t)B_ * T_ * V_] = total;
}

// ---------------- host ----------------
static inline float* fsym(const void* s) { void* p = nullptr; cudaGetSymbolAddress(&p, s); return (float*)p; }
static inline hf* hsym(const void* s) { void* p = nullptr; cudaGetSymbolAddress(&p, s); return (hf*)p; }
static inline int* isym(const void* s) { void* p = nullptr; cudaGetSymbolAddress(&p, s); return (int*)p; }

template <int NF, int EPI>
static inline void bgemm(float* C, const float* Cinit, int initLd,
                         const hf* A, int lda, const hf* W, int ldw,
                         const float* bias, const int* rowmap, const int* cntp,
                         int M, int N, int K, int t) {
    dim3 grid((N + NF * 16 - 1) / (NF * 16), (M + 127) / 128);
    bgemm_k<NF, EPI><<<grid, 256>>>(C, Cinit, initLd, A, lda, W, ldw, bias, rowmap, cntp, M, N, K, t);
}
static inline void convw(hf* dst, int Ktot, int dstOff, int rowOff,
                         const float* src, int lds, int segK, int nrows, int perm) {
    convw_k<<<2048, 256>>>(dst, Ktot, dstOff, rowOff, src, lds, segK, nrows, perm);
}

extern "C" void kernel_launch(void* const* d_in, const int* in_sizes, int n_in,
                              void* d_out, int out_size) {
    const float* feats     = (const float*)d_in[0];
    const int*   sequences = (const int*)d_in[1];
    const int*   sizes     = (const int*)d_in[2];
    const float* emb       = (const float*)d_in[3];
    const float* td_wih    = (const float*)d_in[4];
    const float* td_whh    = (const float*)d_in[5];
    const float* td_b      = (const float*)d_in[6];
    const float* lang_wih  = (const float*)d_in[7];
    const float* lang_whh  = (const float*)d_in[8];
    const float* lang_b    = (const float*)d_in[9];
    const float* attf_w    = (const float*)d_in[10];
    const float* attf_b    = (const float*)d_in[11];
    const float* attd_w    = (const float*)d_in[12];
    const float* attd_b    = (const float*)d_in[13];
    const float* att_w     = (const float*)d_in[14];
    const float* att_b     = (const float*)d_in[15];
    const float* out_w     = (const float*)d_in[16];
    const float* out_b     = (const float*)d_in[17];
    const float* ar_wih    = (const float*)d_in[18];
    const float* ar_whh    = (const float*)d_in[19];
    const float* ar_b      = (const float*)d_in[20];
    const float* arl_w     = (const float*)d_in[21];
    const float* arl_b     = (const float*)d_in[22];
    float* out = (float*)d_out;

    float* p_favgW  = fsym(g_favgW);
    float* p_xe1    = fsym(g_xe1);
    float* p_imgatt = fsym(g_imgatt);
    float* p_ARL    = fsym(g_ARL);
    float* p_b3q    = fsym(g_b3q);
    float* p_tdbp   = fsym(g_tdb_p);
    float* p_langbp = fsym(g_langb_p);
    hf *pXfs = hsym(Xfs), *pXfavg = hsym(Xfavg), *pXebd = hsym(Xebd);
    hf *pX1 = hsym(X1b), *pX2 = hsym(X2b), *pX3 = hsym(X3b);
    hf *pH2c = hsym(H2c), *pARNt = hsym(ARNt);
    hf *pWfavg = hsym(Wfavg), *pWxe = hsym(Wxe), *pW1 = hsym(W1p), *pW2 = hsym(W2p), *pW3 = hsym(W3p);
    hf *pWattf = hsym(Wattf), *pWout = hsym(Wout), *pWarl = hsym(Warl);
    int* p_meta   = isym(g_meta);
    int* p_actrow = isym(g_actrow);

    // ---- setup (ordered so launch #6 = imgatt GEMM for ncu) ----
    sort_k<<<1, B_>>>(sizes);                                   // 1
    gather_fs_k<<<4096, 256>>>(feats);                          // 2
    convw(pWattf, 2048, 0, 0, attf_w, 2048, 2048, A_, 0);       // 3
    init_act_k<<<(B_ * T_ + 255) / 256, 256>>>();               // 4
    zero_state_k<<<(B_ * D_ + 255) / 256, 256>>>();             // 5
    bgemm<8, 0>(p_imgatt, nullptr, 0, pXfs, 2048, pWattf, 2048, attf_b,
                nullptr, nullptr, B_ * N_, A_, 2048, 0);        // 6 (profiled)
    scan_k<<<1, 32>>>();
    zeroh_k<<<2048, 256>>>(pX1, (size_t)2 * B_ * 2048);
    zeroh_k<<<2048, 256>>>(pX2, (size_t)2 * B_ * 4096);
    zeroh_k<<<2048, 256>>>(pX3, (size_t)2 * B_ * 2048);
    zeroh_k<<<2048, 256>>>(pW3, (size_t)4608 * 2048);
    favg_k<<<(B_ * F_ + 255) / 256, 256>>>();
    gather_ebd_k<<<4096, 256>>>(sequences, emb);
    permb_k<<<(4608 + 255) / 256, 256>>>(td_b, lang_b, ar_b, attd_b);

    // weights (gate-interleaved where epilogue-fused)
    convw(pWfavg, 2048, 0, 0, td_wih + 1024, 4096, 2048, G_, 1);
    convw(pWxe,   1024, 0, 0, td_wih + 3072, 4096, 1024, G_, 1);
    convw(pW1, 2048, 0,    0, td_wih, 4096, 1024, G_, 1);
    convw(pW1, 2048, 1024, 0, td_whh, 1024, 1024, G_, 1);
    convw(pW2, 4096, 0,    0, lang_wih, 3072, 2048, G_, 1);
    convw(pW2, 4096, 2048, 0, lang_wih + 2048, 3072, 1024, G_, 1);
    convw(pW2, 4096, 3072, 0, lang_whh, 1024, 1024, G_, 1);
    convw(pW3, 2048, 0,    0, ar_wih, 1024, 1024, G_, 1);
    convw(pW3, 2048, 1024, 0, ar_whh, 1024, 1024, G_, 1);
    convw(pW3, 2048, 0, 4096, attd_w, 1024, 1024, A_, 0);
    convw(pWout, 1024, 0, 0, out_w, 1024, 1024, V_, 0);
    convw(pWarl, 1024, 0, 0, arl_w, 1024, 1024, D_, 0);

    // setup GEMMs (interleaved gate columns)
    bgemm<4, 0>(p_favgW, nullptr, 0, pXfavg, 2048, pWfavg, 2048, p_tdbp,
                nullptr, nullptr, B_, G_, 2048, 0);
    bgemm<8, 0>(p_xe1, nullptr, 0, pXebd, 1024, pWxe, 1024, nullptr,
                nullptr, nullptr, B_ * T_, G_, 1024, 0);
    add_favg_k<<<4096, 256>>>();
    zero_out_k<<<4096, 256>>>(out, (size_t)B_ * T_ * V_);

    // ---- sequential decode: 4 launches/step (ping-pong recurrent buffers) ----
    for (int t = 0; t < T_; ++t) {
        const int par = t & 1;
        bgemm<4, 1>(nullptr, p_xe1 + (size_t)t * G_, T_ * G_,
                    pX1 + (size_t)par * B_ * 2048, 2048, pW1, 2048,
                    nullptr, nullptr, p_meta + t, B_, G_, 2048, t);
        bgemm<4, 3>(nullptr, nullptr, 0,
                    pX3 + (size_t)par * B_ * 2048, 2048, pW3, 2048, p_b3q,
                    nullptr, p_meta + t, B_, 4608, 2048, t);
        attn_k<<<B_, 256>>>(att_w, att_b, t);
        bgemm<4, 2>(nullptr, nullptr, 0,
                    pX2 + (size_t)par * B_ * 4096, 4096, pW2, 4096, p_langbp,
                    nullptr, p_meta + t, B_, G_, 4096, t);
    }

    // ---- batched tail ----
    bgemm<8, 0>(out, nullptr, 0, pH2c, 1024, pWout, 1024, out_b,
                p_actrow, p_meta + T_, B_ * T_, V_, 1024, 0);
    bgemm<8, 0>(p_ARL, nullptr, 0, pARNt, 1024, pWarl, 1024, arl_b,
                nullptr, nullptr, B_ * T_, D_, 1024, 0);
    loss_rows_k<<<B_ * T_, 256>>>();
    loss_final_k<<<1, 256>>>(out);
}

// round 14
// speedup vs baseline: 3.6809x; 1.0553x over previous
#include <cuda_runtime.h>
#include <cuda_fp16.h>
#include <math.h>
#include <stdint.h>

#define B_ 256
#define N_ 36
#define F_ 2048
#define L_ 26
#define A_ 512
#define E_ 1024
#define D_ 1024
#define V_ 10000
#define T_ 25
#define G_ 4096
typedef __half hf;

// ---------------- fp32 state / scratch ----------------
__device__ __align__(256) float g_favgW[B_ * G_];
__device__ __align__(256) float g_xe1[(size_t)B_ * T_ * G_];
__device__ __align__(256) float g_imgatt[(size_t)B_ * N_ * A_];
__device__ __align__(256) float g_c1[B_ * D_], g_c2[B_ * D_], g_arc[B_ * D_], g_prevh1[B_ * D_];
__device__ __align__(256) float g_q[B_ * A_];
__device__ __align__(256) float g_PREVc[(size_t)B_ * T_ * D_];
__device__ __align__(256) float g_ARLc[(size_t)B_ * T_ * D_];
__device__ __align__(256) float g_rowss[B_ * T_];
__device__ __align__(256) float g_b3q[4608];
__device__ __align__(256) float g_tdb_p[G_];
__device__ __align__(256) float g_langb_p[G_];
__device__ int g_order[B_];
__device__ int g_declen[B_];
__device__ int g_actrow[B_ * T_];
__device__ int g_cidx[B_ * T_];
__device__ int g_meta[T_ + 1];
__device__ unsigned char g_act[B_ * T_];
// ---------------- fp16 operand buffers (recurrent ones double-buffered) ----------------
__device__ __align__(256) hf Xfs[(size_t)B_ * N_ * F_];
__device__ __align__(256) hf Xfavg[(size_t)B_ * F_];
__device__ __align__(256) hf Xebd[(size_t)B_ * T_ * E_];
__device__ __align__(256) hf X1b[2][(size_t)B_ * 2048];
__device__ __align__(256) hf X2b[2][(size_t)B_ * 4096];
__device__ __align__(256) hf X3b[2][(size_t)B_ * 2048];
__device__ __align__(256) hf H2c[(size_t)B_ * T_ * D_];
__device__ __align__(256) hf ARNc[(size_t)B_ * T_ * D_];
__device__ __align__(256) hf Wfavg[(size_t)G_ * F_];
__device__ __align__(256) hf Wxe[(size_t)G_ * E_];
__device__ __align__(256) hf W1p[(size_t)G_ * 2048];
__device__ __align__(256) hf W2p[(size_t)G_ * 4096];
__device__ __align__(256) hf W3p[(size_t)4608 * 2048];
__device__ __align__(256) hf Wattf[(size_t)A_ * F_];
__device__ __align__(256) hf Wout[(size_t)V_ * D_];
__device__ __align__(256) hf Warl[(size_t)D_ * D_];

__device__ __forceinline__ float sigm(float x) { return 1.f / (1.f + expf(-x)); }
__device__ __forceinline__ uint32_t smem_u32(const void* p) {
    uint32_t a;
    asm("{ .reg .u64 t; cvta.to.shared.u64 t, %1; cvt.u32.u64 %0, t; }" : "=r"(a) : "l"(p));
    return a;
}
__device__ __forceinline__ void cp16(uint32_t d, const void* s, bool ok) {
    asm volatile("cp.async.cg.shared.global [%0], [%1], 16, %2;" :: "r"(d), "l"(s), "r"(ok ? 16 : 0));
}
__device__ __forceinline__ void ldm_x4(uint32_t& r0, uint32_t& r1, uint32_t& r2, uint32_t& r3, uint32_t a) {
    asm volatile("ldmatrix.sync.aligned.m8n8.x4.shared.b16 {%0,%1,%2,%3}, [%4];"
                 : "=r"(r0), "=r"(r1), "=r"(r2), "=r"(r3) : "r"(a));
}
__device__ __forceinline__ void ldm_x2(uint32_t& r0, uint32_t& r1, uint32_t a) {
    asm volatile("ldmatrix.sync.aligned.m8n8.x2.shared.b16 {%0,%1}, [%2];"
                 : "=r"(r0), "=r"(r1) : "r"(a));
}
__device__ __forceinline__ void mma16816(float* c, const uint32_t* a, const uint32_t* b) {
    asm volatile("mma.sync.aligned.m16n8k16.row.col.f32.f16.f16.f32 "
                 "{%0,%1,%2,%3},{%4,%5,%6,%7},{%8,%9},{%0,%1,%2,%3};"
                 : "+f"(c[0]), "+f"(c[1]), "+f"(c[2]), "+f"(c[3])
                 : "r"(a[0]), "r"(a[1]), "r"(a[2]), "r"(a[3]), "r"(b[0]), "r"(b[1]));
}

// ======= pipelined fp16 GEMM with fused LSTM epilogues =======
// EPI: 0 plain (opt rowmap scatter), 1 LSTM1, 2 LSTM2, 3 LSTM3+q
#define SLD 40
template <int NF, int EPI>
__global__ void __launch_bounds__(256) bgemm_k(
    float* __restrict__ C, const float* __restrict__ Cinit, int initLd,
    const hf* __restrict__ A, int lda, const hf* __restrict__ W, int ldw,
    const float* __restrict__ bias, const int* __restrict__ rowmap,
    const int* __restrict__ cntp, int M, int N, int K, int t)
{
    const int NT = NF * 16;
    const int bm = blockIdx.y * 128, bn = blockIdx.x * (NF * 16);
    int nact = M;
    if (cntp) { nact = *cntp; if (bm >= nact) return; }
    __shared__ __align__(16) hf sA[2][128][SLD];
    __shared__ __align__(16) hf sW[2][NF * 16][SLD];
    const int tid = threadIdx.x, wid = tid >> 5, lane = tid & 31;
    const int wm = (wid & 3) * 32, wn = (wid >> 2) * (NF * 8);
    float c[2][NF][4];
    #pragma unroll
    for (int i = 0; i < 2; ++i)
        #pragma unroll
        for (int j = 0; j < NF; ++j)
            #pragma unroll
            for (int k = 0; k < 4; ++k) c[i][j][k] = 0.f;

    const int lrow = tid >> 1, lcol = (tid & 1) * 16;
    const bool aok = (bm + lrow) < M;
    const bool wdo = lrow < NT;
    const bool wok = wdo && (bn + lrow) < N;
    const hf* aptr = A + (size_t)(bm + lrow) * lda + lcol;
    const hf* wptr = W + (size_t)(bn + (wdo ? lrow : 0)) * ldw + lcol;
    const int nch = K >> 5;

    {
        uint32_t da = smem_u32(&sA[0][lrow][lcol]);
        cp16(da, aptr, aok); cp16(da + 16, aptr + 8, aok);
        if (wdo) {
            uint32_t dw = smem_u32(&sW[0][lrow][lcol]);
            cp16(dw, wptr, wok); cp16(dw + 16, wptr + 8, wok);
        }
        asm volatile("cp.async.commit_group;" ::: "memory");
    }
    for (int ch = 0; ch < nch; ++ch) {
        asm volatile("cp.async.wait_group 0;" ::: "memory");
        __syncthreads();
        if (ch + 1 < nch) {
            int nb = (ch + 1) & 1;
            const hf* as = aptr + (ch + 1) * 32;
            uint32_t da = smem_u32(&sA[nb][lrow][lcol]);
            cp16(da, as, aok); cp16(da + 16, as + 8, aok);
            if (wdo) {
                const hf* ws = wptr + (ch + 1) * 32;
                uint32_t dw = smem_u32(&sW[nb][lrow][lcol]);
                cp16(dw, ws, wok); cp16(dw + 16, ws + 8, wok);
            }
            asm volatile("cp.async.commit_group;" ::: "memory");
        }
        const int bf = ch & 1;
        #pragma unroll
        for (int ks = 0; ks < 2; ++ks) {
            const int k0 = ks * 16;
            uint32_t Af[2][4], Bf[NF][2];
            const int arw = (lane & 15), akc = k0 + ((lane >> 4) << 3);
            #pragma unroll
            for (int mf = 0; mf < 2; ++mf)
                ldm_x4(Af[mf][0], Af[mf][1], Af[mf][2], Af[mf][3], smem_u32(&sA[bf][wm + mf * 16 + arw][akc]));
            const int l4 = lane & 15, brw = l4 & 7, bkc = k0 + ((l4 >> 3) & 1) * 8;
            #pragma unroll
            for (int nf = 0; nf < NF; ++nf)
                ldm_x2(Bf[nf][0], Bf[nf][1], smem_u32(&sW[bf][wn + nf * 8 + brw][bkc]));
            #pragma unroll
            for (int mf = 0; mf < 2; ++mf)
                #pragma unroll
                for (int nf = 0; nf < NF; ++nf) mma16816(c[mf][nf], Af[mf], Bf[nf]);
        }
    }

    // ---- epilogue ----
    const int par = t & 1, nxt = par ^ 1;
    #pragma unroll
    for (int mf = 0; mf < 2; ++mf) {
        #pragma unroll
        for (int half = 0; half < 2; ++half) {
            const int m = bm + wm + mf * 16 + (lane >> 2) + half * 8;
            const bool mok = (m < M) && (m < nact);
            #pragma unroll
            for (int nf = 0; nf < NF; ++nf) {
                const int n0 = bn + wn + nf * 8 + (lane & 3) * 2;
                float v0 = c[mf][nf][half * 2 + 0];
                float v1 = c[mf][nf][half * 2 + 1];
                if (EPI == 0) {
                    if (mok) {
                        int mrow = rowmap ? rowmap[m] : m;
                        #pragma unroll
                        for (int e = 0; e < 2; ++e) {
                            int n = n0 + e;
                            if (n >= N) break;
                            float v = (e == 0) ? v0 : v1;
                            if (bias) v += bias[n];
                            if (Cinit) v += Cinit[(size_t)m * initLd + n];
                            C[(size_t)mrow * N + n] = v;
                        }
                    }
                } else {
                    if (Cinit && mok) {
                        v0 += Cinit[(size_t)m * initLd + n0];
                        v1 += Cinit[(size_t)m * initLd + n0 + 1];
                    }
                    if (bias) { v0 += bias[n0]; v1 += bias[n0 + 1]; }
                    float o0 = __shfl_xor_sync(0xffffffffu, v0, 1);
                    float o1 = __shfl_xor_sync(0xffffffffu, v1, 1);
                    if (EPI == 3 && n0 >= 4096) {
                        if (mok) {
                            g_q[(size_t)m * A_ + (n0 - 4096)] = v0;
                            g_q[(size_t)m * A_ + (n0 - 4095)] = v1;
                        }
                    } else if ((lane & 1) == 0 && mok) {
                        int d = n0 >> 2;
                        int idx = m * D_ + d;
                        int r = m * T_ + t;
                        float ig = sigm(v0), fg = sigm(v1);
                        float gg = tanhf(o0), og = sigm(o1);
                        unsigned char act = g_act[r];
                        if (EPI == 1) {
                            float cn = fg * g_c1[idx] + ig * gg;
                            float h = og * tanhf(cn);
                            hf h16 = __float2half(h);
                            X2b[par][(size_t)m * 4096 + 2048 + d] = h16;
                            X3b[par][(size_t)m * 2048 + d] = h16;
                            if (act) {
                                g_PREVc[(size_t)g_cidx[r] * D_ + d] = g_prevh1[idx];
                                g_c1[idx] = cn; g_prevh1[idx] = h;
                                X1b[nxt][(size_t)m * 2048 + 1024 + d] = h16;
                            }
                        } else if (EPI == 2) {
                            float cn = fg * g_c2[idx] + ig * gg;
                            float h = og * tanhf(cn);
                            hf h16 = __float2half(h);
                            if (act) {
                                g_c2[idx] = cn;
                                X1b[nxt][(size_t)m * 2048 + d] = h16;
                                X2b[nxt][(size_t)m * 4096 + 3072 + d] = h16;
                                H2c[(size_t)g_cidx[r] * D_ + d] = h16;
                            }
                        } else {  // EPI == 3
                            float cn = fg * g_arc[idx] + ig * gg;
                            float h = og * tanhf(cn);
                            hf h16 = __float2half(h);
                            if (act) {
                                g_arc[idx] = cn;
                                ARNc[(size_t)g_cidx[r] * D_ + d] = h16;
                                X3b[nxt][(size_t)m * 2048 + 1024 + d] = h16;
                            }
                        }
                    }
                }
            }
        }
    }
}

// ---------------- weight fp16 conversion (opt gate interleave) ----------------
__global__ void convw_k(hf* __restrict__ dst, int Ktot, int dstOff, int rowOff,
                        const float* __restrict__ src, int lds, int segK, int nrows, int perm) {
    size_t total = (size_t)nrows * segK;
    for (size_t i = (size_t)blockIdx.x * blockDim.x + threadIdx.x; i < total;
         i += (size_t)gridDim.x * blockDim.x) {
        int n = (int)(i / segK), k = (int)(i - (size_t)n * segK);
        int nd = perm ? (4 * (n & 1023) + (n >> 10)) : n;
        dst[(size_t)(nd + rowOff) * Ktot + dstOff + k] = __float2half(src[(size_t)n * lds + k]);
    }
}
__global__ void zeroh_k(hf* p, size_t n) {
    for (size_t i = (size_t)blockIdx.x * blockDim.x + threadIdx.x; i < n;
         i += (size_t)gridDim.x * blockDim.x) p[i] = __float2half(0.f);
}
__global__ void zero_out_k(float* p, size_t n) {
    size_t n4 = n >> 2;
    for (size_t i = (size_t)blockIdx.x * blockDim.x + threadIdx.x; i < n4;
         i += (size_t)gridDim.x * blockDim.x) ((float4*)p)[i] = make_float4(0, 0, 0, 0);
}
__global__ void permb_k(const float* __restrict__ tdb, const float* __restrict__ langb,
                        const float* __restrict__ arb, const float* __restrict__ attdb) {
    int i = blockIdx.x * blockDim.x + threadIdx.x;
    if (i < G_) {
        int pd = 4 * (i & 1023) + (i >> 10);
        g_tdb_p[pd] = tdb[i];
        g_langb_p[pd] = langb[i];
        g_b3q[pd] = arb[i];
    } else if (i < 4608) {
        g_b3q[i] = attdb[i - G_];
    }
}

// ---------------- setup ----------------
__global__ void sort_k(const int* __restrict__ sizes) {
    __shared__ int s[B_];
    int i = threadIdx.x;
    s[i] = sizes[i];
    __syncthreads();
    int my = s[i], rank = 0;
    for (int j = 0; j < B_; ++j) { int sj = s[j]; if (sj > my || (sj == my && j < i)) rank++; }
    g_order[rank] = i;
    g_declen[rank] = my - 1;
}
__global__ void init_misc_k() {
    int idx = blockIdx.x * blockDim.x + threadIdx.x;
    if (idx < B_ * T_) {
        int b = idx / T_, t = idx - b * T_;
        g_act[idx] = (t < g_declen[b]) ? 1 : 0;
        g_rowss[idx] = 0.f;
    }
    if (idx < B_ * D_) { g_c1[idx] = 0.f; g_c2[idx] = 0.f; g_arc[idx] = 0.f; g_prevh1[idx] = 0.f; }
}
__global__ void scan_k() {
    if (threadIdx.x != 0) return;
    int j = 0;
    for (int r = 0; r < B_ * T_; ++r) {
        if (g_act[r]) { g_cidx[r] = j; g_actrow[j] = r; j++; }
        else g_cidx[r] = -1;
    }
    g_meta[T_] = j;
    for (int t = 0; t < T_; ++t) {
        int cnt = 0;
        for (int b = 0; b < B_; ++b) cnt += g_act[b * T_ + t];
        g_meta[t] = cnt;
    }
}
__global__ void gather_fs_k(const float* __restrict__ feats) {
    const size_t NF_ = (size_t)N_ * F_;
    size_t total = (size_t)B_ * NF_ / 2;
    for (size_t i = (size_t)blockIdx.x * blockDim.x + threadIdx.x; i < total;
         i += (size_t)gridDim.x * blockDim.x) {
        int b = (int)(i / (NF_ / 2));
        size_t rem = i - (size_t)b * (NF_ / 2);
        const float2 v = ((const float2*)(feats + (size_t)g_order[b] * NF_))[rem];
        ((half2*)Xfs)[i] = __floats2half2_rn(v.x, v.y);
    }
}
__global__ void favg_k(const float* __restrict__ feats) {
    int idx = blockIdx.x * blockDim.x + threadIdx.x;
    if (idx < B_ * F_) {
        int b = idx / F_, f = idx - b * F_;
        const float* base = feats + (size_t)g_order[b] * N_ * F_ + f;
        float s = 0.f;
        #pragma unroll
        for (int n = 0; n < N_; ++n) s += base[(size_t)n * F_];
        Xfavg[idx] = __float2half(s * (1.f / N_));
    }
}
__global__ void gather_ebd_k(const int* __restrict__ seqs, const float* __restrict__ emb) {
    size_t total = (size_t)B_ * T_ * E_;
    for (size_t i = (size_t)blockIdx.x * blockDim.x + threadIdx.x; i < total;
         i += (size_t)gridDim.x * blockDim.x) {
        int r = (int)(i / E_), e = (int)(i - (size_t)r * E_);
        int b = r / T_, t = r - b * T_;
        Xebd[i] = __float2half(emb[(size_t)seqs[g_order[b] * L_ + t] * E_ + e]);
    }
}
__global__ void add_favg_k() {
    const int per_r = G_ / 4;
    size_t total = (size_t)B_ * T_ * per_r;
    for (size_t i = (size_t)blockIdx.x * blockDim.x + threadIdx.x; i < total;
         i += (size_t)gridDim.x * blockDim.x) {
        int r = (int)(i / per_r), g4 = (int)(i - (size_t)r * per_r);
        float4 x = ((float4*)g_xe1)[i];
        float4 a = ((const float4*)g_favgW)[(size_t)(r / T_) * per_r + g4];
        x.x += a.x; x.y += a.y; x.z += a.z; x.w += a.w;
        ((float4*)g_xe1)[i] = x;
    }
}

// ---------------- attention (fp16 feature reads, fp32 accumulate) ----------------
__global__ void attn_k(const float* __restrict__ attw, const float* __restrict__ attb, int t) {
    int b = blockIdx.x;
    int tid = threadIdx.x, warp = tid >> 5, lane = tid & 31;
    __shared__ float s_q[A_], s_w[A_], s_sc[N_], s_alpha[N_];
    for (int i = tid; i < A_; i += 256) { s_q[i] = g_q[b * A_ + i]; s_w[i] = attw[i]; }
    __syncthreads();
    for (int n = warp; n < N_; n += 8) {
        const float* row = g_imgatt + ((size_t)b * N_ + n) * A_;
        float p = 0.f;
        for (int a = lane; a < A_; a += 32) { float v = s_q[a] + row[a]; p += fmaxf(v, 0.f) * s_w[a]; }
        #pragma unroll
        for (int o = 16; o; o >>= 1) p += __shfl_xor_sync(0xffffffffu, p, o);
        if (lane == 0) s_sc[n] = p + attb[0];
    }
    __syncthreads();
    if (warp == 0) {
        float v0 = s_sc[lane], v1 = (lane + 32 < N_) ? s_sc[lane + 32] : -1e30f;
        float mx = fmaxf(v0, v1);
        #pragma unroll
        for (int o = 16; o; o >>= 1) mx = fmaxf(mx, __shfl_xor_sync(0xffffffffu, mx, o));
        float e0 = expf(v0 - mx), e1 = (lane + 32 < N_) ? expf(v1 - mx) : 0.f;
        float s = e0 + e1;
        #pragma unroll
        for (int o = 16; o; o >>= 1) s += __shfl_xor_sync(0xffffffffu, s, o);
        s_alpha[lane] = e0 / s;
        if (lane + 32 < N_) s_alpha[lane + 32] = e1 / s;
    }
    __syncthreads();
    half2* x2 = (half2*)(X2b[t & 1] + (size_t)b * 4096);
    const half2* fb = (const half2*)(Xfs + (size_t)b * N_ * F_);
    for (int f2 = tid; f2 < F_ / 2; f2 += 256) {
        float a0 = 0.f, a1 = 0.f;
        #pragma unroll
        for (int n = 0; n < N_; ++n) {
            float2 vf = __half22float2(fb[(size_t)n * (F_ / 2) + f2]);
            a0 += s_alpha[n] * vf.x;
            a1 += s_alpha[n] * vf.y;
        }
        x2[f2] = __floats2half2_rn(a0, a1);
    }
}

// ---------------- loss (compacted rows) ----------------
__global__ void loss_rows_k() {
    int j = blockIdx.x;
    if (j >= g_meta[T_]) return;
    int r = g_actrow[j], t = r % T_;
    if (t == 0) return;
    int tid = threadIdx.x;
    float p = 0.f;
    const float* a = g_ARLc + (size_t)j * D_;
    const float* pv = g_PREVc + (size_t)j * D_;
    for (int d = tid; d < D_; d += 256) { float df = a[d] - pv[d]; p += df * df; }
    __shared__ float sred[256];
    sred[tid] = p;
    __syncthreads();
    for (int o = 128; o; o >>= 1) { if (tid < o) sred[tid] += sred[tid + o]; __syncthreads(); }
    if (tid == 0) g_rowss[r] = sred[0];
}
__global__ void loss_final_k(float* __restrict__ out) {
    __shared__ float ss[256], sc[256];
    int tid = threadIdx.x;
    float total = 0.f;
    for (int t = 1; t < T_; ++t) {
        float s = 0.f, c = 0.f;
        for (int b = tid; b < B_; b += 256) {
            s += g_rowss[b * T_ + t];
            c += g_act[b * T_ + t] ? 1.f : 0.f;
        }
        ss[tid] = s; sc[tid] = c;
        __syncthreads();
        for (int o = 128; o; o >>= 1) { if (tid < o) { ss[tid] += ss[tid + o]; sc[tid] += sc[tid + o]; } __syncthreads(); }
        if (tid == 0) total += ss[0] / fmaxf(sc[0], 1.f) * 0.005f;
        __syncthreads();
    }
    if (tid == 0) out[(size_t)B_ * T_ * V_] = total;
}

// ---------------- host ----------------
static inline float* fsym(const void* s) { void* p = nullptr; cudaGetSymbolAddress(&p, s); return (float*)p; }
static inline hf* hsym(const void* s) { void* p = nullptr; cudaGetSymbolAddress(&p, s); return (hf*)p; }
static inline int* isym(const void* s) { void* p = nullptr; cudaGetSymbolAddress(&p, s); return (int*)p; }

template <int NF, int EPI>
static inline void bgemm(float* C, const float* Cinit, int initLd,
                         const hf* A, int lda, const hf* W, int ldw,
                         const float* bias, const int* rowmap, const int* cntp,
                         int M, int N, int K, int t) {
    dim3 grid((N + NF * 16 - 1) / (NF * 16), (M + 127) / 128);
    bgemm_k<NF, EPI><<<grid, 256>>>(C, Cinit, initLd, A, lda, W, ldw, bias, rowmap, cntp, M, N, K, t);
}
static inline void convw(hf* dst, int Ktot, int dstOff, int rowOff,
                         const float* src, int lds, int segK, int nrows, int perm) {
    convw_k<<<2048, 256>>>(dst, Ktot, dstOff, rowOff, src, lds, segK, nrows, perm);
}

extern "C" void kernel_launch(void* const* d_in, const int* in_sizes, int n_in,
                              void* d_out, int out_size) {
    const float* feats     = (const float*)d_in[0];
    const int*   sequences = (const int*)d_in[1];
    const int*   sizes     = (const int*)d_in[2];
    const float* emb       = (const float*)d_in[3];
    const float* td_wih    = (const float*)d_in[4];
    const float* td_whh    = (const float*)d_in[5];
    const float* td_b      = (const float*)d_in[6];
    const float* lang_wih  = (const float*)d_in[7];
    const float* lang_whh  = (const float*)d_in[8];
    const float* lang_b    = (const float*)d_in[9];
    const float* attf_w    = (const float*)d_in[10];
    const float* attf_b    = (const float*)d_in[11];
    const float* attd_w    = (const float*)d_in[12];
    const float* attd_b    = (const float*)d_in[13];
    const float* att_w     = (const float*)d_in[14];
    const float* att_b     = (const float*)d_in[15];
    const float* out_w     = (const float*)d_in[16];
    const float* out_b     = (const float*)d_in[17];
    const float* ar_wih    = (const float*)d_in[18];
    const float* ar_whh    = (const float*)d_in[19];
    const float* ar_b      = (const float*)d_in[20];
    const float* arl_w     = (const float*)d_in[21];
    const float* arl_b     = (const float*)d_in[22];
    float* out = (float*)d_out;

    float* p_favgW  = fsym(g_favgW);
    float* p_xe1    = fsym(g_xe1);
    float* p_imgatt = fsym(g_imgatt);
    float* p_ARLc   = fsym(g_ARLc);
    float* p_b3q    = fsym(g_b3q);
    float* p_tdbp   = fsym(g_tdb_p);
    float* p_langbp = fsym(g_langb_p);
    hf *pXfs = hsym(Xfs), *pXfavg = hsym(Xfavg), *pXebd = hsym(Xebd);
    hf *pX1 = hsym(X1b), *pX2 = hsym(X2b), *pX3 = hsym(X3b);
    hf *pH2c = hsym(H2c), *pARNc = hsym(ARNc);
    hf *pWfavg = hsym(Wfavg), *pWxe = hsym(Wxe), *pW1 = hsym(W1p), *pW2 = hsym(W2p), *pW3 = hsym(W3p);
    hf *pWattf = hsym(Wattf), *pWout = hsym(Wout), *pWarl = hsym(Warl);
    int* p_meta   = isym(g_meta);
    int* p_actrow = isym(g_actrow);

    // ---- setup (launch #4 = imgatt GEMM, the slot ncu captures) ----
    sort_k<<<1, B_>>>(sizes);                                   // 1
    gather_fs_k<<<4096, 256>>>(feats);                          // 2
    convw(pWattf, 2048, 0, 0, attf_w, 2048, 2048, A_, 0);       // 3
    bgemm<8, 0>(p_imgatt, nullptr, 0, pXfs, 2048, pWattf, 2048, attf_b,
                nullptr, nullptr, B_ * N_, A_, 2048, 0);        // 4 (profiled)
    init_misc_k<<<(B_ * D_ + 255) / 256, 256>>>();
    scan_k<<<1, 32>>>();
    zeroh_k<<<2048, 256>>>(pX1, (size_t)2 * B_ * 2048);
    zeroh_k<<<2048, 256>>>(pX2, (size_t)2 * B_ * 4096);
    zeroh_k<<<2048, 256>>>(pX3, (size_t)2 * B_ * 2048);
    zeroh_k<<<2048, 256>>>(pW3, (size_t)4608 * 2048);
    favg_k<<<(B_ * F_ + 255) / 256, 256>>>(feats);
    gather_ebd_k<<<4096, 256>>>(sequences, emb);
    permb_k<<<(4608 + 255) / 256, 256>>>(td_b, lang_b, ar_b, attd_b);

    // weights (gate-interleaved where epilogue-fused)
    convw(pWfavg, 2048, 0, 0, td_wih + 1024, 4096, 2048, G_, 1);
    convw(pWxe,   1024, 0, 0, td_wih + 3072, 4096, 1024, G_, 1);
    convw(pW1, 2048, 0,    0, td_wih, 4096, 1024, G_, 1);
    convw(pW1, 2048, 1024, 0, td_whh, 1024, 1024, G_, 1);
    convw(pW2, 4096, 0,    0, lang_wih, 3072, 2048, G_, 1);
    convw(pW2, 4096, 2048, 0, lang_wih + 2048, 3072, 1024, G_, 1);
    convw(pW2, 4096, 3072, 0, lang_whh, 1024, 1024, G_, 1);
    convw(pW3, 2048, 0,    0, ar_wih, 1024, 1024, G_, 1);
    convw(pW3, 2048, 1024, 0, ar_whh, 1024, 1024, G_, 1);
    convw(pW3, 2048, 0, 4096, attd_w, 1024, 1024, A_, 0);
    convw(pWout, 1024, 0, 0, out_w, 1024, 1024, V_, 0);
    convw(pWarl, 1024, 0, 0, arl_w, 1024, 1024, D_, 0);

    // setup GEMMs
    bgemm<4, 0>(p_favgW, nullptr, 0, pXfavg, 2048, pWfavg, 2048, p_tdbp,
                nullptr, nullptr, B_, G_, 2048, 0);
    bgemm<8, 0>(p_xe1, nullptr, 0, pXebd, 1024, pWxe, 1024, nullptr,
                nullptr, nullptr, B_ * T_, G_, 1024, 0);
    add_favg_k<<<4096, 256>>>();
    zero_out_k<<<4096, 256>>>(out, (size_t)B_ * T_ * V_);

    // ---- sequential decode: 4 launches/step (ping-pong recurrent buffers) ----
    for (int t = 0; t < T_; ++t) {
        const int par = t & 1;
        bgemm<4, 1>(nullptr, p_xe1 + (size_t)t * G_, T_ * G_,
                    pX1 + (size_t)par * B_ * 2048, 2048, pW1, 2048,
                    nullptr, nullptr, p_meta + t, B_, G_, 2048, t);
        bgemm<4, 3>(nullptr, nullptr, 0,
                    pX3 + (size_t)par * B_ * 2048, 2048, pW3, 2048, p_b3q,
                    nullptr, p_meta + t, B_, 4608, 2048, t);
        attn_k<<<B_, 256>>>(att_w, att_b, t);
        bgemm<4, 2>(nullptr, nullptr, 0,
                    pX2 + (size_t)par * B_ * 4096, 4096, pW2, 4096, p_langbp,
                    nullptr, p_meta + t, B_, G_, 4096, t);
    }

    // ---- batched tail (compacted rows) ----
    bgemm<8, 0>(out, nullptr, 0, pH2c, 1024, pWout, 1024, out_b,
                p_actrow, p_meta + T_, B_ * T_, V_, 1024, 0);
    bgemm<8, 0>(p_ARLc, nullptr, 0, pARNc, 1024, pWarl, 1024, arl_b,
                nullptr, p_meta + T_, B_ * T_, D_, 1024, 0);
    loss_rows_k<<<B_ * T_, 256>>>();
    loss_final_k<<<1, 256>>>(out);
}

// round 15
// speedup vs baseline: 4.5362x; 1.2324x over previous
#include <cuda_runtime.h>
#include <cuda_fp16.h>
#include <math.h>
#include <stdint.h>

#define B_ 256
#define N_ 36
#define F_ 2048
#define L_ 26
#define A_ 512
#define E_ 1024
#define D_ 1024
#define V_ 10000
#define T_ 25
#define G_ 4096
typedef __half hf;

// ---------------- fp32 state / scratch ----------------
__device__ __align__(256) float g_favgW[B_ * G_];
__device__ __align__(256) float g_xe1[(size_t)B_ * T_ * G_];
__device__ __align__(256) float g_imgatt[(size_t)B_ * N_ * A_];
__device__ __align__(256) float g_c1[B_ * D_], g_c2[B_ * D_], g_arc[B_ * D_], g_prevh1[B_ * D_];
__device__ __align__(256) float g_q[B_ * A_];
__device__ __align__(256) float g_PREVc[(size_t)B_ * T_ * D_];
__device__ __align__(256) float g_ARLc[(size_t)B_ * T_ * D_];
__device__ __align__(256) float g_rowss[B_ * T_];
__device__ __align__(256) float g_b3q[4608];
__device__ __align__(256) float g_tdb_p[G_];
__device__ __align__(256) float g_langb_p[G_];
__device__ int g_order[B_];
__device__ int g_declen[B_];
__device__ int g_actrow[B_ * T_];
__device__ int g_cidx[B_ * T_];
__device__ int g_meta[T_ + 1];
__device__ unsigned char g_act[B_ * T_];
// ---------------- fp16 operand buffers (recurrent ones double-buffered) ----------------
__device__ __align__(256) hf Xfs[(size_t)B_ * N_ * F_];
__device__ __align__(256) hf Xfavg[(size_t)B_ * F_];
__device__ __align__(256) hf Xebd[(size_t)B_ * T_ * E_];
__device__ __align__(256) hf X1b[2][(size_t)B_ * 2048];
__device__ __align__(256) hf X2b[2][(size_t)B_ * 4096];
__device__ __align__(256) hf X3b[2][(size_t)B_ * 2048];
__device__ __align__(256) hf H2c[(size_t)B_ * T_ * D_];
__device__ __align__(256) hf ARNc[(size_t)B_ * T_ * D_];
__device__ __align__(256) hf Wfavg[(size_t)G_ * F_];
__device__ __align__(256) hf Wxe[(size_t)G_ * E_];
__device__ __align__(256) hf W1p[(size_t)G_ * 2048];
__device__ __align__(256) hf W2p[(size_t)G_ * 4096];
__device__ __align__(256) hf W3p[(size_t)4608 * 2048];
__device__ __align__(256) hf Wattf[(size_t)A_ * F_];
__device__ __align__(256) hf Wout[(size_t)V_ * D_];
__device__ __align__(256) hf Warl[(size_t)D_ * D_];

__device__ __forceinline__ float sigm(float x) { return 1.f / (1.f + expf(-x)); }
__device__ __forceinline__ uint32_t smem_u32(const void* p) {
    uint32_t a;
    asm("{ .reg .u64 t; cvta.to.shared.u64 t, %1; cvt.u32.u64 %0, t; }" : "=r"(a) : "l"(p));
    return a;
}
__device__ __forceinline__ void cp16(uint32_t d, const void* s, bool ok) {
    asm volatile("cp.async.cg.shared.global [%0], [%1], 16, %2;" :: "r"(d), "l"(s), "r"(ok ? 16 : 0));
}
__device__ __forceinline__ void ldm_x4(uint32_t& r0, uint32_t& r1, uint32_t& r2, uint32_t& r3, uint32_t a) {
    asm volatile("ldmatrix.sync.aligned.m8n8.x4.shared.b16 {%0,%1,%2,%3}, [%4];"
                 : "=r"(r0), "=r"(r1), "=r"(r2), "=r"(r3) : "r"(a));
}
__device__ __forceinline__ void ldm_x2(uint32_t& r0, uint32_t& r1, uint32_t a) {
    asm volatile("ldmatrix.sync.aligned.m8n8.x2.shared.b16 {%0,%1}, [%2];"
                 : "=r"(r0), "=r"(r1) : "r"(a));
}
__device__ __forceinline__ void mma16816(float* c, const uint32_t* a, const uint32_t* b) {
    asm volatile("mma.sync.aligned.m16n8k16.row.col.f32.f16.f16.f32 "
                 "{%0,%1,%2,%3},{%4,%5,%6,%7},{%8,%9},{%0,%1,%2,%3};"
                 : "+f"(c[0]), "+f"(c[1]), "+f"(c[2]), "+f"(c[3])
                 : "r"(a[0]), "r"(a[1]), "r"(a[2]), "r"(a[3]), "r"(b[0]), "r"(b[1]));
}

// ======= 3-stage pipelined fp16 GEMM (128x64 tile) with fused LSTM epilogues =======
// EPI: 0 plain (opt rowmap scatter), 1 LSTM1, 2 LSTM2, 3 LSTM3+q
#define SLD 40
#define NFR 4   // B fragments per warp -> 64-wide N tile
template <int EPI>
__global__ void __launch_bounds__(256, 2) bgemm_k(
    float* __restrict__ C, const float* __restrict__ Cinit, int initLd,
    const hf* __restrict__ A, int lda, const hf* __restrict__ W, int ldw,
    const float* __restrict__ bias, const int* __restrict__ rowmap,
    const int* __restrict__ cntp, int M, int N, int K, int t)
{
    const int bm = blockIdx.y * 128, bn = blockIdx.x * 64;
    int nact = M;
    if (cntp) { nact = *cntp; if (bm >= nact) return; }
    __shared__ __align__(16) hf sA[3][128][SLD];   // 30.7 KB
    __shared__ __align__(16) hf sW[3][64][SLD];    // 15.4 KB
    const int tid = threadIdx.x, wid = tid >> 5, lane = tid & 31;
    const int wm = (wid & 3) * 32, wn = (wid >> 2) * 32;
    float c[2][NFR][4];
    #pragma unroll
    for (int i = 0; i < 2; ++i)
        #pragma unroll
        for (int j = 0; j < NFR; ++j)
            #pragma unroll
            for (int k = 0; k < 4; ++k) c[i][j][k] = 0.f;

    const int lrow = tid >> 1, lcol = (tid & 1) * 16;
    const bool aok = (bm + lrow) < M;
    const bool wdo = lrow < 64;
    const bool wok = wdo && (bn + lrow) < N;
    const hf* aptr = A + (size_t)(bm + lrow) * lda + lcol;
    const hf* wptr = W + (size_t)(bn + (wdo ? lrow : 0)) * ldw + lcol;
    const int nch = K >> 5;

    // prologue: prefetch chunks 0,1 into stages 0,1
    {
        uint32_t da = smem_u32(&sA[0][lrow][lcol]);
        cp16(da, aptr, aok); cp16(da + 16, aptr + 8, aok);
        if (wdo) {
            uint32_t dw = smem_u32(&sW[0][lrow][lcol]);
            cp16(dw, wptr, wok); cp16(dw + 16, wptr + 8, wok);
        }
        asm volatile("cp.async.commit_group;" ::: "memory");
    }
    if (nch > 1) {
        uint32_t da = smem_u32(&sA[1][lrow][lcol]);
        cp16(da, aptr + 32, aok); cp16(da + 16, aptr + 40, aok);
        if (wdo) {
            uint32_t dw = smem_u32(&sW[1][lrow][lcol]);
            cp16(dw, wptr + 32, wok); cp16(dw + 16, wptr + 40, wok);
        }
        asm volatile("cp.async.commit_group;" ::: "memory");
    }

    int st = 0, pf = 2;  // compute stage, prefetch stage
    for (int ch = 0; ch < nch; ++ch) {
        if (ch + 1 < nch) asm volatile("cp.async.wait_group 1;" ::: "memory");
        else              asm volatile("cp.async.wait_group 0;" ::: "memory");
        __syncthreads();
        if (ch + 2 < nch) {
            const hf* as = aptr + (ch + 2) * 32;
            uint32_t da = smem_u32(&sA[pf][lrow][lcol]);
            cp16(da, as, aok); cp16(da + 16, as + 8, aok);
            if (wdo) {
                const hf* ws = wptr + (ch + 2) * 32;
                uint32_t dw = smem_u32(&sW[pf][lrow][lcol]);
                cp16(dw, ws, wok); cp16(dw + 16, ws + 8, wok);
            }
            asm volatile("cp.async.commit_group;" ::: "memory");
        }
        #pragma unroll
        for (int ks = 0; ks < 2; ++ks) {
            const int k0 = ks * 16;
            uint32_t Af[2][4], Bf[NFR][2];
            const int arw = (lane & 15), akc = k0 + ((lane >> 4) << 3);
            #pragma unroll
            for (int mf = 0; mf < 2; ++mf)
                ldm_x4(Af[mf][0], Af[mf][1], Af[mf][2], Af[mf][3], smem_u32(&sA[st][wm + mf * 16 + arw][akc]));
            const int l4 = lane & 15, brw = l4 & 7, bkc = k0 + ((l4 >> 3) & 1) * 8;
            #pragma unroll
            for (int nf = 0; nf < NFR; ++nf)
                ldm_x2(Bf[nf][0], Bf[nf][1], smem_u32(&sW[st][wn + nf * 8 + brw][bkc]));
            #pragma unroll
            for (int mf = 0; mf < 2; ++mf)
                #pragma unroll
                for (int nf = 0; nf < NFR; ++nf) mma16816(c[mf][nf], Af[mf], Bf[nf]);
        }
        st = (st == 2) ? 0 : st + 1;
        pf = (pf == 2) ? 0 : pf + 1;
    }

    // ---- epilogue ----
    const int par = t & 1, nxt = par ^ 1;
    #pragma unroll
    for (int mf = 0; mf < 2; ++mf) {
        #pragma unroll
        for (int half = 0; half < 2; ++half) {
            const int m = bm + wm + mf * 16 + (lane >> 2) + half * 8;
            const bool mok = (m < M) && (m < nact);
            #pragma unroll
            for (int nf = 0; nf < NFR; ++nf) {
                const int n0 = bn + wn + nf * 8 + (lane & 3) * 2;
                float v0 = c[mf][nf][half * 2 + 0];
                float v1 = c[mf][nf][half * 2 + 1];
                if (EPI == 0) {
                    if (mok) {
                        int mrow = rowmap ? rowmap[m] : m;
                        #pragma unroll
                        for (int e = 0; e < 2; ++e) {
                            int n = n0 + e;
                            if (n >= N) break;
                            float v = (e == 0) ? v0 : v1;
                            if (bias) v += bias[n];
                            if (Cinit) v += Cinit[(size_t)m * initLd + n];
                            C[(size_t)mrow * N + n] = v;
                        }
                    }
                } else {
                    if (Cinit && mok) {
                        v0 += Cinit[(size_t)m * initLd + n0];
                        v1 += Cinit[(size_t)m * initLd + n0 + 1];
                    }
                    if (bias) { v0 += bias[n0]; v1 += bias[n0 + 1]; }
                    float o0 = __shfl_xor_sync(0xffffffffu, v0, 1);
                    float o1 = __shfl_xor_sync(0xffffffffu, v1, 1);
                    if (EPI == 3 && n0 >= 4096) {
                        if (mok) {
                            g_q[(size_t)m * A_ + (n0 - 4096)] = v0;
                            g_q[(size_t)m * A_ + (n0 - 4095)] = v1;
                        }
                    } else if ((lane & 1) == 0 && mok) {
                        int d = n0 >> 2;
                        int idx = m * D_ + d;
                        int r = m * T_ + t;
                        float ig = sigm(v0), fg = sigm(v1);
                        float gg = tanhf(o0), og = sigm(o1);
                        unsigned char act = g_act[r];
                        if (EPI == 1) {
                            float cn = fg * g_c1[idx] + ig * gg;
                            float h = og * tanhf(cn);
                            hf h16 = __float2half(h);
                            X2b[par][(size_t)m * 4096 + 2048 + d] = h16;
                            X3b[par][(size_t)m * 2048 + d] = h16;
                            if (act) {
                                g_PREVc[(size_t)g_cidx[r] * D_ + d] = g_prevh1[idx];
                                g_c1[idx] = cn; g_prevh1[idx] = h;
                                X1b[nxt][(size_t)m * 2048 + 1024 + d] = h16;
                            }
                        } else if (EPI == 2) {
                            float cn = fg * g_c2[idx] + ig * gg;
                            float h = og * tanhf(cn);
                            hf h16 = __float2half(h);
                            if (act) {
                                g_c2[idx] = cn;
                                X1b[nxt][(size_t)m * 2048 + d] = h16;
                                X2b[nxt][(size_t)m * 4096 + 3072 + d] = h16;
                                H2c[(size_t)g_cidx[r] * D_ + d] = h16;
                            }
                        } else {  // EPI == 3
                            float cn = fg * g_arc[idx] + ig * gg;
                            float h = og * tanhf(cn);
                            hf h16 = __float2half(h);
                            if (act) {
                                g_arc[idx] = cn;
                                ARNc[(size_t)g_cidx[r] * D_ + d] = h16;
                                X3b[nxt][(size_t)m * 2048 + 1024 + d] = h16;
                            }
                        }
                    }
                }
            }
        }
    }
}

// ---------------- weight fp16 conversion (opt gate interleave) ----------------
__global__ void convw_k(hf* __restrict__ dst, int Ktot, int dstOff, int rowOff,
                        const float* __restrict__ src, int lds, int segK, int nrows, int perm) {
    size_t total = (size_t)nrows * segK;
    for (size_t i = (size_t)blockIdx.x * blockDim.x + threadIdx.x; i < total;
         i += (size_t)gridDim.x * blockDim.x) {
        int n = (int)(i / segK), k = (int)(i - (size_t)n * segK);
        int nd = perm ? (4 * (n & 1023) + (n >> 10)) : n;
        dst[(size_t)(nd + rowOff) * Ktot + dstOff + k] = __float2half(src[(size_t)n * lds + k]);
    }
}
__global__ void zeroh_k(hf* p, size_t n) {
    for (size_t i = (size_t)blockIdx.x * blockDim.x + threadIdx.x; i < n;
         i += (size_t)gridDim.x * blockDim.x) p[i] = __float2half(0.f);
}
__global__ void zero_out_k(float* p, size_t n) {
    size_t n4 = n >> 2;
    for (size_t i = (size_t)blockIdx.x * blockDim.x + threadIdx.x; i < n4;
         i += (size_t)gridDim.x * blockDim.x) ((float4*)p)[i] = make_float4(0, 0, 0, 0);
}
__global__ void permb_k(const float* __restrict__ tdb, const float* __restrict__ langb,
                        const float* __restrict__ arb, const float* __restrict__ attdb) {
    int i = blockIdx.x * blockDim.x + threadIdx.x;
    if (i < G_) {
        int pd = 4 * (i & 1023) + (i >> 10);
        g_tdb_p[pd] = tdb[i];
        g_langb_p[pd] = langb[i];
        g_b3q[pd] = arb[i];
    } else if (i < 4608) {
        g_b3q[i] = attdb[i - G_];
    }
}

// ---------------- setup ----------------
__global__ void sort_k(const int* __restrict__ sizes) {
    __shared__ int s[B_];
    int i = threadIdx.x;
    s[i] = sizes[i];
    __syncthreads();
    int my = s[i], rank = 0;
    for (int j = 0; j < B_; ++j) { int sj = s[j]; if (sj > my || (sj == my && j < i)) rank++; }
    g_order[rank] = i;
    g_declen[rank] = my - 1;
}
__global__ void init_misc_k() {
    int idx = blockIdx.x * blockDim.x + threadIdx.x;
    if (idx < B_ * T_) {
        int b = idx / T_, t = idx - b * T_;
        g_act[idx] = (t < g_declen[b]) ? 1 : 0;
        g_rowss[idx] = 0.f;
    }
    if (idx < B_ * D_) { g_c1[idx] = 0.f; g_c2[idx] = 0.f; g_arc[idx] = 0.f; g_prevh1[idx] = 0.f; }
}
__global__ void scan_k() {
    if (threadIdx.x != 0) return;
    int j = 0;
    for (int r = 0; r < B_ * T_; ++r) {
        if (g_act[r]) { g_cidx[r] = j; g_actrow[j] = r; j++; }
        else g_cidx[r] = -1;
    }
    g_meta[T_] = j;
    for (int t = 0; t < T_; ++t) {
        int cnt = 0;
        for (int b = 0; b < B_; ++b) cnt += g_act[b * T_ + t];
        g_meta[t] = cnt;
    }
}
__global__ void gather_fs_k(const float* __restrict__ feats) {
    const size_t NF_ = (size_t)N_ * F_;
    size_t total = (size_t)B_ * NF_ / 2;
    for (size_t i = (size_t)blockIdx.x * blockDim.x + threadIdx.x; i < total;
         i += (size_t)gridDim.x * blockDim.x) {
        int b = (int)(i / (NF_ / 2));
        size_t rem = i - (size_t)b * (NF_ / 2);
        const float2 v = ((const float2*)(feats + (size_t)g_order[b] * NF_))[rem];
        ((half2*)Xfs)[i] = __floats2half2_rn(v.x, v.y);
    }
}
__global__ void favg_k(const float* __restrict__ feats) {
    int idx = blockIdx.x * blockDim.x + threadIdx.x;
    if (idx < B_ * F_) {
        int b = idx / F_, f = idx - b * F_;
        const float* base = feats + (size_t)g_order[b] * N_ * F_ + f;
        float s = 0.f;
        #pragma unroll
        for (int n = 0; n < N_; ++n) s += base[(size_t)n * F_];
        Xfavg[idx] = __float2half(s * (1.f / N_));
    }
}
__global__ void gather_ebd_k(const int* __restrict__ seqs, const float* __restrict__ emb) {
    size_t total = (size_t)B_ * T_ * E_;
    for (size_t i = (size_t)blockIdx.x * blockDim.x + threadIdx.x; i < total;
         i += (size_t)gridDim.x * blockDim.x) {
        int r = (int)(i / E_), e = (int)(i - (size_t)r * E_);
        int b = r / T_, t = r - b * T_;
        Xebd[i] = __float2half(emb[(size_t)seqs[g_order[b] * L_ + t] * E_ + e]);
    }
}
__global__ void add_favg_k() {
    const int per_r = G_ / 4;
    size_t total = (size_t)B_ * T_ * per_r;
    for (size_t i = (size_t)blockIdx.x * blockDim.x + threadIdx.x; i < total;
         i += (size_t)gridDim.x * blockDim.x) {
        int r = (int)(i / per_r), g4 = (int)(i - (size_t)r * per_r);
        float4 x = ((float4*)g_xe1)[i];
        float4 a = ((const float4*)g_favgW)[(size_t)(r / T_) * per_r + g4];
        x.x += a.x; x.y += a.y; x.z += a.z; x.w += a.w;
        ((float4*)g_xe1)[i] = x;
    }
}

// ---------------- attention (fp16 feature reads, fp32 accumulate) ----------------
__global__ void attn_k(const float* __restrict__ attw, const float* __restrict__ attb, int t) {
    int b = blockIdx.x;
    int tid = threadIdx.x, warp = tid >> 5, lane = tid & 31;
    __shared__ float s_q[A_], s_w[A_], s_sc[N_], s_alpha[N_];
    for (int i = tid; i < A_; i += 256) { s_q[i] = g_q[b * A_ + i]; s_w[i] = attw[i]; }
    __syncthreads();
    for (int n = warp; n < N_; n += 8) {
        const float* row = g_imgatt + ((size_t)b * N_ + n) * A_;
        float p = 0.f;
        for (int a = lane; a < A_; a += 32) { float v = s_q[a] + row[a]; p += fmaxf(v, 0.f) * s_w[a]; }
        #pragma unroll
        for (int o = 16; o; o >>= 1) p += __shfl_xor_sync(0xffffffffu, p, o);
        if (lane == 0) s_sc[n] = p + attb[0];
    }
    __syncthreads();
    if (warp == 0) {
        float v0 = s_sc[lane], v1 = (lane + 32 < N_) ? s_sc[lane + 32] : -1e30f;
        float mx = fmaxf(v0, v1);
        #pragma unroll
        for (int o = 16; o; o >>= 1) mx = fmaxf(mx, __shfl_xor_sync(0xffffffffu, mx, o));
        float e0 = expf(v0 - mx), e1 = (lane + 32 < N_) ? expf(v1 - mx) : 0.f;
        float s = e0 + e1;
        #pragma unroll
        for (int o = 16; o; o >>= 1) s += __shfl_xor_sync(0xffffffffu, s, o);
        s_alpha[lane] = e0 / s;
        if (lane + 32 < N_) s_alpha[lane + 32] = e1 / s;
    }
    __syncthreads();
    half2* x2 = (half2*)(X2b[t & 1] + (size_t)b * 4096);
    const half2* fb = (const half2*)(Xfs + (size_t)b * N_ * F_);
    for (int f2 = tid; f2 < F_ / 2; f2 += 256) {
        float a0 = 0.f, a1 = 0.f;
        #pragma unroll
        for (int n = 0; n < N_; ++n) {
            float2 vf = __half22float2(fb[(size_t)n * (F_ / 2) + f2]);
            a0 += s_alpha[n] * vf.x;
            a1 += s_alpha[n] * vf.y;
        }
        x2[f2] = __floats2half2_rn(a0, a1);
    }
}

// ---------------- loss (compacted rows) ----------------
__global__ void loss_rows_k() {
    int j = blockIdx.x;
    if (j >= g_meta[T_]) return;
    int r = g_actrow[j], t = r % T_;
    if (t == 0) return;
    int tid = threadIdx.x;
    float p = 0.f;
    const float* a = g_ARLc + (size_t)j * D_;
    const float* pv = g_PREVc + (size_t)j * D_;
    for (int d = tid; d < D_; d += 256) { float df = a[d] - pv[d]; p += df * df; }
    __shared__ float sred[256];
    sred[tid] = p;
    __syncthreads();
    for (int o = 128; o; o >>= 1) { if (tid < o) sred[tid] += sred[tid + o]; __syncthreads(); }
    if (tid == 0) g_rowss[r] = sred[0];
}
__global__ void loss_final_k(float* __restrict__ out) {
    __shared__ float ss[256], sc[256];
    int tid = threadIdx.x;
    float total = 0.f;
    for (int t = 1; t < T_; ++t) {
        float s = 0.f, c = 0.f;
        for (int b = tid; b < B_; b += 256) {
            s += g_rowss[b * T_ + t];
            c += g_act[b * T_ + t] ? 1.f : 0.f;
        }
        ss[tid] = s; sc[tid] = c;
        __syncthreads();
        for (int o = 128; o; o >>= 1) { if (tid < o) { ss[tid] += ss[tid + o]; sc[tid] += sc[tid + o]; } __syncthreads(); }
        if (tid == 0) total += ss[0] / fmaxf(sc[0], 1.f) * 0.005f;
        __syncthreads();
    }
    if (tid == 0) out[(size_t)B_ * T_ * V_] = total;
}

// ---------------- host ----------------
static inline float* fsym(const void* s) { void* p = nullptr; cudaGetSymbolAddress(&p, s); return (float*)p; }
static inline hf* hsym(const void* s) { void* p = nullptr; cudaGetSymbolAddress(&p, s); return (hf*)p; }
static inline int* isym(const void* s) { void* p = nullptr; cudaGetSymbolAddress(&p, s); return (int*)p; }

template <int EPI>
static inline void bgemm(float* C, const float* Cinit, int initLd,
                         const hf* A, int lda, const hf* W, int ldw,
                         const float* bias, const int* rowmap, const int* cntp,
                         int M, int N, int K, int t) {
    dim3 grid((N + 63) / 64, (M + 127) / 128);
    bgemm_k<EPI><<<grid, 256>>>(C, Cinit, initLd, A, lda, W, ldw, bias, rowmap, cntp, M, N, K, t);
}
static inline void convw(hf* dst, int Ktot, int dstOff, int rowOff,
                         const float* src, int lds, int segK, int nrows, int perm) {
    convw_k<<<2048, 256>>>(dst, Ktot, dstOff, rowOff, src, lds, segK, nrows, perm);
}

extern "C" void kernel_launch(void* const* d_in, const int* in_sizes, int n_in,
                              void* d_out, int out_size) {
    const float* feats     = (const float*)d_in[0];
    const int*   sequences = (const int*)d_in[1];
    const int*   sizes     = (const int*)d_in[2];
    const float* emb       = (const float*)d_in[3];
    const float* td_wih    = (const float*)d_in[4];
    const float* td_whh    = (const float*)d_in[5];
    const float* td_b      = (const float*)d_in[6];
    const float* lang_wih  = (const float*)d_in[7];
    const float* lang_whh  = (const float*)d_in[8];
    const float* lang_b    = (const float*)d_in[9];
    const float* attf_w    = (const float*)d_in[10];
    const float* attf_b    = (const float*)d_in[11];
    const float* attd_w    = (const float*)d_in[12];
    const float* attd_b    = (const float*)d_in[13];
    const float* att_w     = (const float*)d_in[14];
    const float* att_b     = (const float*)d_in[15];
    const float* out_w     = (const float*)d_in[16];
    const float* out_b     = (const float*)d_in[17];
    const float* ar_wih    = (const float*)d_in[18];
    const float* ar_whh    = (const float*)d_in[19];
    const float* ar_b      = (const float*)d_in[20];
    const float* arl_w     = (const float*)d_in[21];
    const float* arl_b     = (const float*)d_in[22];
    float* out = (float*)d_out;

    float* p_favgW  = fsym(g_favgW);
    float* p_xe1    = fsym(g_xe1);
    float* p_imgatt = fsym(g_imgatt);
    float* p_ARLc   = fsym(g_ARLc);
    float* p_b3q    = fsym(g_b3q);
    float* p_tdbp   = fsym(g_tdb_p);
    float* p_langbp = fsym(g_langb_p);
    hf *pXfs = hsym(Xfs), *pXfavg = hsym(Xfavg), *pXebd = hsym(Xebd);
    hf *pX1 = hsym(X1b), *pX2 = hsym(X2b), *pX3 = hsym(X3b);
    hf *pH2c = hsym(H2c), *pARNc = hsym(ARNc);
    hf *pWfavg = hsym(Wfavg), *pWxe = hsym(Wxe), *pW1 = hsym(W1p), *pW2 = hsym(W2p), *pW3 = hsym(W3p);
    hf *pWattf = hsym(Wattf), *pWout = hsym(Wout), *pWarl = hsym(Warl);
    int* p_meta   = isym(g_meta);
    int* p_actrow = isym(g_actrow);

    // ---- setup (launch #4 = imgatt GEMM, the slot ncu captures) ----
    sort_k<<<1, B_>>>(sizes);                                   // 1
    gather_fs_k<<<4096, 256>>>(feats);                          // 2
    convw(pWattf, 2048, 0, 0, attf_w, 2048, 2048, A_, 0);       // 3
    bgemm<0>(p_imgatt, nullptr, 0, pXfs, 2048, pWattf, 2048, attf_b,
             nullptr, nullptr, B_ * N_, A_, 2048, 0);           // 4 (profiled)
    init_misc_k<<<(B_ * D_ + 255) / 256, 256>>>();
    scan_k<<<1, 32>>>();
    zeroh_k<<<2048, 256>>>(pX1, (size_t)2 * B_ * 2048);
    zeroh_k<<<2048, 256>>>(pX2, (size_t)2 * B_ * 4096);
    zeroh_k<<<2048, 256>>>(pX3, (size_t)2 * B_ * 2048);
    zeroh_k<<<2048, 256>>>(pW3, (size_t)4608 * 2048);
    favg_k<<<(B_ * F_ + 255) / 256, 256>>>(feats);
    gather_ebd_k<<<4096, 256>>>(sequences, emb);
    permb_k<<<(4608 + 255) / 256, 256>>>(td_b, lang_b, ar_b, attd_b);

    // weights (gate-interleaved where epilogue-fused)
    convw(pWfavg, 2048, 0, 0, td_wih + 1024, 4096, 2048, G_, 1);
    convw(pWxe,   1024, 0, 0, td_wih + 3072, 4096, 1024, G_, 1);
    convw(pW1, 2048, 0,    0, td_wih, 4096, 1024, G_, 1);
    convw(pW1, 2048, 1024, 0, td_whh, 1024, 1024, G_, 1);
    convw(pW2, 4096, 0,    0, lang_wih, 3072, 2048, G_, 1);
    convw(pW2, 4096, 2048, 0, lang_wih + 2048, 3072, 1024, G_, 1);
    convw(pW2, 4096, 3072, 0, lang_whh, 1024, 1024, G_, 1);
    convw(pW3, 2048, 0,    0, ar_wih, 1024, 1024, G_, 1);
    convw(pW3, 2048, 1024, 0, ar_whh, 1024, 1024, G_, 1);
    convw(pW3, 2048, 0, 4096, attd_w, 1024, 1024, A_, 0);
    convw(pWout, 1024, 0, 0, out_w, 1024, 1024, V_, 0);
    convw(pWarl, 1024, 0, 0, arl_w, 1024, 1024, D_, 0);

    // setup GEMMs
    bgemm<0>(p_favgW, nullptr, 0, pXfavg, 2048, pWfavg, 2048, p_tdbp,
             nullptr, nullptr, B_, G_, 2048, 0);
    bgemm<0>(p_xe1, nullptr, 0, pXebd, 1024, pWxe, 1024, nullptr,
             nullptr, nullptr, B_ * T_, G_, 1024, 0);
    add_favg_k<<<4096, 256>>>();
    zero_out_k<<<4096, 256>>>(out, (size_t)B_ * T_ * V_);

    // ---- sequential decode: 4 launches/step (ping-pong recurrent buffers) ----
    for (int t = 0; t < T_; ++t) {
        const int par = t & 1;
        bgemm<1>(nullptr, p_xe1 + (size_t)t * G_, T_ * G_,
                 pX1 + (size_t)par * B_ * 2048, 2048, pW1, 2048,
                 nullptr, nullptr, p_meta + t, B_, G_, 2048, t);
        bgemm<3>(nullptr, nullptr, 0,
                 pX3 + (size_t)par * B_ * 2048, 2048, pW3, 2048, p_b3q,
                 nullptr, p_meta + t, B_, 4608, 2048, t);
        attn_k<<<B_, 256>>>(att_w, att_b, t);
        bgemm<2>(nullptr, nullptr, 0,
                 pX2 + (size_t)par * B_ * 4096, 4096, pW2, 4096, p_langbp,
                 nullptr, p_meta + t, B_, G_, 4096, t);
    }

    // ---- batched tail (compacted rows) ----
    bgemm<0>(out, nullptr, 0, pH2c, 1024, pWout, 1024, out_b,
             p_actrow, p_meta + T_, B_ * T_, V_, 1024, 0);
    bgemm<0>(p_ARLc, nullptr, 0, pARNc, 1024, pWarl, 1024, arl_b,
             nullptr, p_meta + T_, B_ * T_, D_, 1024, 0);
    loss_rows_k<<<B_ * T_, 256>>>();
    loss_final_k<<<1, 256>>>(out);
}

// round 16
// speedup vs baseline: 4.6757x; 1.0308x over previous
#include <cuda_runtime.h>
#include <cuda_fp16.h>
#include <math.h>
#include <stdint.h>

#define B_ 256
#define N_ 36
#define F_ 2048
#define L_ 26
#define A_ 512
#define E_ 1024
#define D_ 1024
#define V_ 10000
#define T_ 25
#define G_ 4096
typedef __half hf;

// ---------------- fp32 state / scratch ----------------
__device__ __align__(256) float g_favgW[B_ * G_];
__device__ __align__(256) float g_xe1[(size_t)B_ * T_ * G_];
__device__ __align__(256) float g_imgatt[(size_t)B_ * N_ * A_];
__device__ __align__(256) float g_c1[B_ * D_], g_c2[B_ * D_], g_arc[B_ * D_], g_prevh1[B_ * D_];
__device__ __align__(256) float g_q[B_ * A_];
__device__ __align__(256) float g_PREVc[(size_t)B_ * T_ * D_];
__device__ __align__(256) float g_ARLc[(size_t)B_ * T_ * D_];
__device__ __align__(256) float g_rowss[B_ * T_];
__device__ __align__(256) float g_b3q[4608];
__device__ __align__(256) float g_tdb_p[G_];
__device__ __align__(256) float g_langb_p[G_];
__device__ int g_order[B_];
__device__ int g_declen[B_];
__device__ int g_actrow[B_ * T_];
__device__ int g_cidx[B_ * T_];
__device__ int g_meta[T_ + 1];
__device__ unsigned char g_act[B_ * T_];
// ---------------- fp16 operand buffers (recurrent ones double-buffered) ----------------
__device__ __align__(256) hf Xfs[(size_t)B_ * N_ * F_];
__device__ __align__(256) hf Xfavg[(size_t)B_ * F_];
__device__ __align__(256) hf Xebd[(size_t)B_ * T_ * E_];
__device__ __align__(256) hf X1b[2][(size_t)B_ * 2048];
__device__ __align__(256) hf X2b[2][(size_t)B_ * 4096];
__device__ __align__(256) hf X3b[2][(size_t)B_ * 2048];
__device__ __align__(256) hf H2c[(size_t)B_ * T_ * D_];
__device__ __align__(256) hf ARNc[(size_t)B_ * T_ * D_];
__device__ __align__(256) hf Wfavg[(size_t)G_ * F_];
__device__ __align__(256) hf Wxe[(size_t)G_ * E_];
__device__ __align__(256) hf W1p[(size_t)G_ * 2048];
__device__ __align__(256) hf W2p[(size_t)G_ * 4096];
__device__ __align__(256) hf W3p[(size_t)4608 * 2048];
__device__ __align__(256) hf Wattf[(size_t)A_ * F_];
__device__ __align__(256) hf Wout[(size_t)V_ * D_];
__device__ __align__(256) hf Warl[(size_t)D_ * D_];

__device__ __forceinline__ float sigm(float x) { return 1.f / (1.f + expf(-x)); }
__device__ __forceinline__ uint32_t smem_u32(const void* p) {
    uint32_t a;
    asm("{ .reg .u64 t; cvta.to.shared.u64 t, %1; cvt.u32.u64 %0, t; }" : "=r"(a) : "l"(p));
    return a;
}
__device__ __forceinline__ void cp16(uint32_t d, const void* s, bool ok) {
    asm volatile("cp.async.cg.shared.global [%0], [%1], 16, %2;" :: "r"(d), "l"(s), "r"(ok ? 16 : 0));
}
__device__ __forceinline__ void ldm_x4(uint32_t& r0, uint32_t& r1, uint32_t& r2, uint32_t& r3, uint32_t a) {
    asm volatile("ldmatrix.sync.aligned.m8n8.x4.shared.b16 {%0,%1,%2,%3}, [%4];"
                 : "=r"(r0), "=r"(r1), "=r"(r2), "=r"(r3) : "r"(a));
}
__device__ __forceinline__ void mma16816(float* c, const uint32_t* a, const uint32_t* b) {
    asm volatile("mma.sync.aligned.m16n8k16.row.col.f32.f16.f16.f32 "
                 "{%0,%1,%2,%3},{%4,%5,%6,%7},{%8,%9},{%0,%1,%2,%3};"
                 : "+f"(c[0]), "+f"(c[1]), "+f"(c[2]), "+f"(c[3])
                 : "r"(a[0]), "r"(a[1]), "r"(a[2]), "r"(a[3]), "r"(b[0]), "r"(b[1]));
}

// ======= 3-stage pipelined fp16 GEMM (128x64 tile) with fused LSTM epilogues =======
// EPI: 0 plain (opt rowmap scatter), 1 LSTM1, 2 LSTM2, 3 LSTM3+q
#define SLD 40
#define NFR 4   // B fragments per warp -> 64-wide N tile
template <int EPI>
__global__ void __launch_bounds__(256, 2) bgemm_k(
    float* __restrict__ C, const float* __restrict__ Cinit, int initLd,
    const hf* __restrict__ A, int lda, const hf* __restrict__ W, int ldw,
    const float* __restrict__ bias, const int* __restrict__ rowmap,
    const int* __restrict__ cntp, int M, int N, int K, int t)
{
    const int bm = blockIdx.y * 128, bn = blockIdx.x * 64;
    int nact = M;
    if (cntp) { nact = *cntp; if (bm >= nact) return; }
    __shared__ __align__(16) hf sA[3][128][SLD];   // 30.7 KB
    __shared__ __align__(16) hf sW[3][64][SLD];    // 15.4 KB
    const int tid = threadIdx.x, wid = tid >> 5, lane = tid & 31;
    const int wm = (wid & 3) * 32, wn = (wid >> 2) * 32;
    float c[2][NFR][4];
    #pragma unroll
    for (int i = 0; i < 2; ++i)
        #pragma unroll
        for (int j = 0; j < NFR; ++j)
            #pragma unroll
            for (int k = 0; k < 4; ++k) c[i][j][k] = 0.f;

    const int lrow = tid >> 1, lcol = (tid & 1) * 16;
    const bool aok = (bm + lrow) < M;
    const bool wdo = lrow < 64;
    const bool wok = wdo && (bn + lrow) < N;
    const hf* aptr = A + (size_t)(bm + lrow) * lda + lcol;
    const hf* wptr = W + (size_t)(bn + (wdo ? lrow : 0)) * ldw + lcol;
    const int nch = K >> 5;

    // prologue: prefetch chunks 0,1 into stages 0,1
    {
        uint32_t da = smem_u32(&sA[0][lrow][lcol]);
        cp16(da, aptr, aok); cp16(da + 16, aptr + 8, aok);
        if (wdo) {
            uint32_t dw = smem_u32(&sW[0][lrow][lcol]);
            cp16(dw, wptr, wok); cp16(dw + 16, wptr + 8, wok);
        }
        asm volatile("cp.async.commit_group;" ::: "memory");
    }
    if (nch > 1) {
        uint32_t da = smem_u32(&sA[1][lrow][lcol]);
        cp16(da, aptr + 32, aok); cp16(da + 16, aptr + 40, aok);
        if (wdo) {
            uint32_t dw = smem_u32(&sW[1][lrow][lcol]);
            cp16(dw, wptr + 32, wok); cp16(dw + 16, wptr + 40, wok);
        }
        asm volatile("cp.async.commit_group;" ::: "memory");
    }

    int st = 0, pf = 2;  // compute stage, prefetch stage
    for (int ch = 0; ch < nch; ++ch) {
        if (ch + 1 < nch) asm volatile("cp.async.wait_group 1;" ::: "memory");
        else              asm volatile("cp.async.wait_group 0;" ::: "memory");
        __syncthreads();
        if (ch + 2 < nch) {
            const hf* as = aptr + (ch + 2) * 32;
            uint32_t da = smem_u32(&sA[pf][lrow][lcol]);
            cp16(da, as, aok); cp16(da + 16, as + 8, aok);
            if (wdo) {
                const hf* ws = wptr + (ch + 2) * 32;
                uint32_t dw = smem_u32(&sW[pf][lrow][lcol]);
                cp16(dw, ws, wok); cp16(dw + 16, ws + 8, wok);
            }
            asm volatile("cp.async.commit_group;" ::: "memory");
        }
        #pragma unroll
        for (int ks = 0; ks < 2; ++ks) {
            const int k0 = ks * 16;
            uint32_t Af[2][4], Bf[NFR][2];
            const int arw = (lane & 15), akc = k0 + ((lane >> 4) << 3);
            #pragma unroll
            for (int mf = 0; mf < 2; ++mf)
                ldm_x4(Af[mf][0], Af[mf][1], Af[mf][2], Af[mf][3], smem_u32(&sA[st][wm + mf * 16 + arw][akc]));
            // B pairs via x4: lanes 0-7 (nfp,k0), 8-15 (nfp,k0+8), 16-23 (nfp+1,k0), 24-31 (nfp+1,k0+8)
            const int bnf = (lane >> 4) & 1, bkh = (lane >> 3) & 1, brw2 = lane & 7;
            #pragma unroll
            for (int nfp = 0; nfp < NFR; nfp += 2) {
                int r = wn + (nfp + bnf) * 8 + brw2;
                int kc = k0 + bkh * 8;
                ldm_x4(Bf[nfp][0], Bf[nfp][1], Bf[nfp + 1][0], Bf[nfp + 1][1],
                       smem_u32(&sW[st][r][kc]));
            }
            #pragma unroll
            for (int mf = 0; mf < 2; ++mf)
                #pragma unroll
                for (int nf = 0; nf < NFR; ++nf) mma16816(c[mf][nf], Af[mf], Bf[nf]);
        }
        st = (st == 2) ? 0 : st + 1;
        pf = (pf == 2) ? 0 : pf + 1;
    }

    // ---- epilogue ----
    const int par = t & 1, nxt = par ^ 1;
    #pragma unroll
    for (int mf = 0; mf < 2; ++mf) {
        #pragma unroll
        for (int half = 0; half < 2; ++half) {
            const int m = bm + wm + mf * 16 + (lane >> 2) + half * 8;
            const bool mok = (m < M) && (m < nact);
            #pragma unroll
            for (int nf = 0; nf < NFR; ++nf) {
                const int n0 = bn + wn + nf * 8 + (lane & 3) * 2;
                float v0 = c[mf][nf][half * 2 + 0];
                float v1 = c[mf][nf][half * 2 + 1];
                if (EPI == 0) {
                    if (mok) {
                        int mrow = rowmap ? rowmap[m] : m;
                        #pragma unroll
                        for (int e = 0; e < 2; ++e) {
                            int n = n0 + e;
                            if (n >= N) break;
                            float v = (e == 0) ? v0 : v1;
                            if (bias) v += bias[n];
                            if (Cinit) v += Cinit[(size_t)m * initLd + n];
                            C[(size_t)mrow * N + n] = v;
                        }
                    }
                } else {
                    if (Cinit && mok) {
                        v0 += Cinit[(size_t)m * initLd + n0];
                        v1 += Cinit[(size_t)m * initLd + n0 + 1];
                    }
                    if (bias) { v0 += bias[n0]; v1 += bias[n0 + 1]; }
                    float o0 = __shfl_xor_sync(0xffffffffu, v0, 1);
                    float o1 = __shfl_xor_sync(0xffffffffu, v1, 1);
                    if (EPI == 3 && n0 >= 4096) {
                        if (mok) {
                            g_q[(size_t)m * A_ + (n0 - 4096)] = v0;
                            g_q[(size_t)m * A_ + (n0 - 4095)] = v1;
                        }
                    } else if ((lane & 1) == 0 && mok) {
                        int d = n0 >> 2;
                        int idx = m * D_ + d;
                        int r = m * T_ + t;
                        float ig = sigm(v0), fg = sigm(v1);
                        float gg = tanhf(o0), og = sigm(o1);
                        unsigned char act = g_act[r];
                        if (EPI == 1) {
                            float cn = fg * g_c1[idx] + ig * gg;
                            float h = og * tanhf(cn);
                            hf h16 = __float2half(h);
                            X2b[par][(size_t)m * 4096 + 2048 + d] = h16;
                            X3b[par][(size_t)m * 2048 + d] = h16;
                            if (act) {
                                g_PREVc[(size_t)g_cidx[r] * D_ + d] = g_prevh1[idx];
                                g_c1[idx] = cn; g_prevh1[idx] = h;
                                X1b[nxt][(size_t)m * 2048 + 1024 + d] = h16;
                            }
                        } else if (EPI == 2) {
                            float cn = fg * g_c2[idx] + ig * gg;
                            float h = og * tanhf(cn);
                            hf h16 = __float2half(h);
                            if (act) {
                                g_c2[idx] = cn;
                                X1b[nxt][(size_t)m * 2048 + d] = h16;
                                X2b[nxt][(size_t)m * 4096 + 3072 + d] = h16;
                                H2c[(size_t)g_cidx[r] * D_ + d] = h16;
                            }
                        } else {  // EPI == 3
                            float cn = fg * g_arc[idx] + ig * gg;
                            float h = og * tanhf(cn);
                            hf h16 = __float2half(h);
                            if (act) {
                                g_arc[idx] = cn;
                                ARNc[(size_t)g_cidx[r] * D_ + d] = h16;
                                X3b[nxt][(size_t)m * 2048 + 1024 + d] = h16;
                            }
                        }
                    }
                }
            }
        }
    }
}

// ---------------- weight fp16 conversion (opt gate interleave) ----------------
__global__ void convw_k(hf* __restrict__ dst, int Ktot, int dstOff, int rowOff,
                        const float* __restrict__ src, int lds, int segK, int nrows, int perm) {
    size_t total = (size_t)nrows * segK;
    for (size_t i = (size_t)blockIdx.x * blockDim.x + threadIdx.x; i < total;
         i += (size_t)gridDim.x * blockDim.x) {
        int n = (int)(i / segK), k = (int)(i - (size_t)n * segK);
        int nd = perm ? (4 * (n & 1023) + (n >> 10)) : n;
        dst[(size_t)(nd + rowOff) * Ktot + dstOff + k] = __float2half(src[(size_t)n * lds + k]);
    }
}
__global__ void zeroh_k(hf* p, size_t n) {
    for (size_t i = (size_t)blockIdx.x * blockDim.x + threadIdx.x; i < n;
         i += (size_t)gridDim.x * blockDim.x) p[i] = __float2half(0.f);
}
__global__ void zero_out_k(float* p, size_t n) {
    size_t n4 = n >> 2;
    for (size_t i = (size_t)blockIdx.x * blockDim.x + threadIdx.x; i < n4;
         i += (size_t)gridDim.x * blockDim.x) ((float4*)p)[i] = make_float4(0, 0, 0, 0);
}
__global__ void permb_k(const float* __restrict__ tdb, const float* __restrict__ langb,
                        const float* __restrict__ arb, const float* __restrict__ attdb) {
    int i = blockIdx.x * blockDim.x + threadIdx.x;
    if (i < G_) {
        int pd = 4 * (i & 1023) + (i >> 10);
        g_tdb_p[pd] = tdb[i];
        g_langb_p[pd] = langb[i];
        g_b3q[pd] = arb[i];
    } else if (i < 4608) {
        g_b3q[i] = attdb[i - G_];
    }
}

// ---------------- setup ----------------
__global__ void sort_k(const int* __restrict__ sizes) {
    __shared__ int s[B_];
    int i = threadIdx.x;
    s[i] = sizes[i];
    __syncthreads();
    int my = s[i], rank = 0;
    for (int j = 0; j < B_; ++j) { int sj = s[j]; if (sj > my || (sj == my && j < i)) rank++; }
    g_order[rank] = i;
    g_declen[rank] = my - 1;
}
__global__ void init_misc_k() {
    int idx = blockIdx.x * blockDim.x + threadIdx.x;
    if (idx < B_ * T_) {
        int b = idx / T_, t = idx - b * T_;
        g_act[idx] = (t < g_declen[b]) ? 1 : 0;
        g_rowss[idx] = 0.f;
    }
    if (idx < B_ * D_) { g_c1[idx] = 0.f; g_c2[idx] = 0.f; g_arc[idx] = 0.f; g_prevh1[idx] = 0.f; }
}
__global__ void scan_k() {
    if (threadIdx.x != 0) return;
    int j = 0;
    for (int r = 0; r < B_ * T_; ++r) {
        if (g_act[r]) { g_cidx[r] = j; g_actrow[j] = r; j++; }
        else g_cidx[r] = -1;
    }
    g_meta[T_] = j;
    for (int t = 0; t < T_; ++t) {
        int cnt = 0;
        for (int b = 0; b < B_; ++b) cnt += g_act[b * T_ + t];
        g_meta[t] = cnt;
    }
}
__global__ void gather_fs_k(const float* __restrict__ feats) {
    const size_t NF_ = (size_t)N_ * F_;
    size_t total = (size_t)B_ * NF_ / 2;
    for (size_t i = (size_t)blockIdx.x * blockDim.x + threadIdx.x; i < total;
         i += (size_t)gridDim.x * blockDim.x) {
        int b = (int)(i / (NF_ / 2));
        size_t rem = i - (size_t)b * (NF_ / 2);
        const float2 v = ((const float2*)(feats + (size_t)g_order[b] * NF_))[rem];
        ((half2*)Xfs)[i] = __floats2half2_rn(v.x, v.y);
    }
}
__global__ void favg_k(const float* __restrict__ feats) {
    int idx = blockIdx.x * blockDim.x + threadIdx.x;
    if (idx < B_ * F_) {
        int b = idx / F_, f = idx - b * F_;
        const float* base = feats + (size_t)g_order[b] * N_ * F_ + f;
        float s = 0.f;
        #pragma unroll
        for (int n = 0; n < N_; ++n) s += base[(size_t)n * F_];
        Xfavg[idx] = __float2half(s * (1.f / N_));
    }
}
__global__ void gather_ebd_k(const int* __restrict__ seqs, const float* __restrict__ emb) {
    size_t total = (size_t)B_ * T_ * E_;
    for (size_t i = (size_t)blockIdx.x * blockDim.x + threadIdx.x; i < total;
         i += (size_t)gridDim.x * blockDim.x) {
        int r = (int)(i / E_), e = (int)(i - (size_t)r * E_);
        int b = r / T_, t = r - b * T_;
        Xebd[i] = __float2half(emb[(size_t)seqs[g_order[b] * L_ + t] * E_ + e]);
    }
}
__global__ void add_favg_k() {
    const int per_r = G_ / 4;
    size_t total = (size_t)B_ * T_ * per_r;
    for (size_t i = (size_t)blockIdx.x * blockDim.x + threadIdx.x; i < total;
         i += (size_t)gridDim.x * blockDim.x) {
        int r = (int)(i / per_r), g4 = (int)(i - (size_t)r * per_r);
        float4 x = ((float4*)g_xe1)[i];
        float4 a = ((const float4*)g_favgW)[(size_t)(r / T_) * per_r + g4];
        x.x += a.x; x.y += a.y; x.z += a.z; x.w += a.w;
        ((float4*)g_xe1)[i] = x;
    }
}

// ---------------- attention (fp16 feature reads, fp32 accumulate) ----------------
__global__ void attn_k(const float* __restrict__ attw, const float* __restrict__ attb, int t) {
    int b = blockIdx.x;
    int tid = threadIdx.x, warp = tid >> 5, lane = tid & 31;
    __shared__ float s_q[A_], s_w[A_], s_sc[N_], s_alpha[N_];
    for (int i = tid; i < A_; i += 256) { s_q[i] = g_q[b * A_ + i]; s_w[i] = attw[i]; }
    __syncthreads();
    for (int n = warp; n < N_; n += 8) {
        const float* row = g_imgatt + ((size_t)b * N_ + n) * A_;
        float p = 0.f;
        for (int a = lane; a < A_; a += 32) { float v = s_q[a] + row[a]; p += fmaxf(v, 0.f) * s_w[a]; }
        #pragma unroll
        for (int o = 16; o; o >>= 1) p += __shfl_xor_sync(0xffffffffu, p, o);
        if (lane == 0) s_sc[n] = p + attb[0];
    }
    __syncthreads();
    if (warp == 0) {
        float v0 = s_sc[lane], v1 = (lane + 32 < N_) ? s_sc[lane + 32] : -1e30f;
        float mx = fmaxf(v0, v1);
        #pragma unroll
        for (int o = 16; o; o >>= 1) mx = fmaxf(mx, __shfl_xor_sync(0xffffffffu, mx, o));
        float e0 = expf(v0 - mx), e1 = (lane + 32 < N_) ? expf(v1 - mx) : 0.f;
        float s = e0 + e1;
        #pragma unroll
        for (int o = 16; o; o >>= 1) s += __shfl_xor_sync(0xffffffffu, s, o);
        s_alpha[lane] = e0 / s;
        if (lane + 32 < N_) s_alpha[lane + 32] = e1 / s;
    }
    __syncthreads();
    half2* x2 = (half2*)(X2b[t & 1] + (size_t)b * 4096);
    const half2* fb = (const half2*)(Xfs + (size_t)b * N_ * F_);
    for (int f2 = tid; f2 < F_ / 2; f2 += 256) {
        float a0 = 0.f, a1 = 0.f;
        #pragma unroll
        for (int n = 0; n < N_; ++n) {
            float2 vf = __half22float2(fb[(size_t)n * (F_ / 2) + f2]);
            a0 += s_alpha[n] * vf.x;
            a1 += s_alpha[n] * vf.y;
        }
        x2[f2] = __floats2half2_rn(a0, a1);
    }
}

// ---------------- loss (compacted rows) ----------------
__global__ void loss_rows_k() {
    int j = blockIdx.x;
    if (j >= g_meta[T_]) return;
    int r = g_actrow[j], t = r % T_;
    if (t == 0) return;
    int tid = threadIdx.x;
    float p = 0.f;
    const float* a = g_ARLc + (size_t)j * D_;
    const float* pv = g_PREVc + (size_t)j * D_;
    for (int d = tid; d < D_; d += 256) { float df = a[d] - pv[d]; p += df * df; }
    __shared__ float sred[256];
    sred[tid] = p;
    __syncthreads();
    for (int o = 128; o; o >>= 1) { if (tid < o) sred[tid] += sred[tid + o]; __syncthreads(); }
    if (tid == 0) g_rowss[r] = sred[0];
}
__global__ void loss_final_k(float* __restrict__ out) {
    __shared__ float ss[256], sc[256];
    int tid = threadIdx.x;
    float total = 0.f;
    for (int t = 1; t < T_; ++t) {
        float s = 0.f, c = 0.f;
        for (int b = tid; b < B_; b += 256) {
            s += g_rowss[b * T_ + t];
            c += g_act[b * T_ + t] ? 1.f : 0.f;
        }
        ss[tid] = s; sc[tid] = c;
        __syncthreads();
        for (int o = 128; o; o >>= 1) { if (tid < o) { ss[tid] += ss[tid + o]; sc[tid] += sc[tid + o]; } __syncthreads(); }
        if (tid == 0) total += ss[0] / fmaxf(sc[0], 1.f) * 0.005f;
        __syncthreads();
    }
    if (tid == 0) out[(size_t)B_ * T_ * V_] = total;
}

// ---------------- host ----------------
static inline float* fsym(const void* s) { void* p = nullptr; cudaGetSymbolAddress(&p, s); return (float*)p; }
static inline hf* hsym(const void* s) { void* p = nullptr; cudaGetSymbolAddress(&p, s); return (hf*)p; }
static inline int* isym(const void* s) { void* p = nullptr; cudaGetSymbolAddress(&p, s); return (int*)p; }

template <int EPI>
static inline void bgemm(float* C, const float* Cinit, int initLd,
                         const hf* A, int lda, const hf* W, int ldw,
                         const float* bias, const int* rowmap, const int* cntp,
                         int M, int N, int K, int t) {
    dim3 grid((N + 63) / 64, (M + 127) / 128);
    bgemm_k<EPI><<<grid, 256>>>(C, Cinit, initLd, A, lda, W, ldw, bias, rowmap, cntp, M, N, K, t);
}
static inline void convw(hf* dst, int Ktot, int dstOff, int rowOff,
                         const float* src, int lds, int segK, int nrows, int perm) {
    convw_k<<<2048, 256>>>(dst, Ktot, dstOff, rowOff, src, lds, segK, nrows, perm);
}

extern "C" void kernel_launch(void* const* d_in, const int* in_sizes, int n_in,
                              void* d_out, int out_size) {
    const float* feats     = (const float*)d_in[0];
    const int*   sequences = (const int*)d_in[1];
    const int*   sizes     = (const int*)d_in[2];
    const float* emb       = (const float*)d_in[3];
    const float* td_wih    = (const float*)d_in[4];
    const float* td_whh    = (const float*)d_in[5];
    const float* td_b      = (const float*)d_in[6];
    const float* lang_wih  = (const float*)d_in[7];
    const float* lang_whh  = (const float*)d_in[8];
    const float* lang_b    = (const float*)d_in[9];
    const float* attf_w    = (const float*)d_in[10];
    const float* attf_b    = (const float*)d_in[11];
    const float* attd_w    = (const float*)d_in[12];
    const float* attd_b    = (const float*)d_in[13];
    const float* att_w     = (const float*)d_in[14];
    const float* att_b     = (const float*)d_in[15];
    const float* out_w     = (const float*)d_in[16];
    const float* out_b     = (const float*)d_in[17];
    const float* ar_wih    = (const float*)d_in[18];
    const float* ar_whh    = (const float*)d_in[19];
    const float* ar_b      = (const float*)d_in[20];
    const float* arl_w     = (const float*)d_in[21];
    const float* arl_b     = (const float*)d_in[22];
    float* out = (float*)d_out;

    float* p_favgW  = fsym(g_favgW);
    float* p_xe1    = fsym(g_xe1);
    float* p_imgatt = fsym(g_imgatt);
    float* p_ARLc   = fsym(g_ARLc);
    float* p_b3q    = fsym(g_b3q);
    float* p_tdbp   = fsym(g_tdb_p);
    float* p_langbp = fsym(g_langb_p);
    hf *pXfs = hsym(Xfs), *pXfavg = hsym(Xfavg), *pXebd = hsym(Xebd);
    hf *pX1 = hsym(X1b), *pX2 = hsym(X2b), *pX3 = hsym(X3b);
    hf *pH2c = hsym(H2c), *pARNc = hsym(ARNc);
    hf *pWfavg = hsym(Wfavg), *pWxe = hsym(Wxe), *pW1 = hsym(W1p), *pW2 = hsym(W2p), *pW3 = hsym(W3p);
    hf *pWattf = hsym(Wattf), *pWout = hsym(Wout), *pWarl = hsym(Warl);
    int* p_meta   = isym(g_meta);
    int* p_actrow = isym(g_actrow);

    // ---- setup (launch #4 = imgatt GEMM, the slot ncu captures) ----
    sort_k<<<1, B_>>>(sizes);                                   // 1
    gather_fs_k<<<4096, 256>>>(feats);                          // 2
    convw(pWattf, 2048, 0, 0, attf_w, 2048, 2048, A_, 0);       // 3
    bgemm<0>(p_imgatt, nullptr, 0, pXfs, 2048, pWattf, 2048, attf_b,
             nullptr, nullptr, B_ * N_, A_, 2048, 0);           // 4 (profiled)
    init_misc_k<<<(B_ * D_ + 255) / 256, 256>>>();
    scan_k<<<1, 32>>>();
    zeroh_k<<<2048, 256>>>(pX1, (size_t)2 * B_ * 2048);
    zeroh_k<<<2048, 256>>>(pX2, (size_t)2 * B_ * 4096);
    zeroh_k<<<2048, 256>>>(pX3, (size_t)2 * B_ * 2048);
    zeroh_k<<<2048, 256>>>(pW3, (size_t)4608 * 2048);
    favg_k<<<(B_ * F_ + 255) / 256, 256>>>(feats);
    gather_ebd_k<<<4096, 256>>>(sequences, emb);
    permb_k<<<(4608 + 255) / 256, 256>>>(td_b, lang_b, ar_b, attd_b);

    // weights (gate-interleaved where epilogue-fused)
    convw(pWfavg, 2048, 0, 0, td_wih + 1024, 4096, 2048, G_, 1);
    convw(pWxe,   1024, 0, 0, td_wih + 3072, 4096, 1024, G_, 1);
    convw(pW1, 2048, 0,    0, td_wih, 4096, 1024, G_, 1);
    convw(pW1, 2048, 1024, 0, td_whh, 1024, 1024, G_, 1);
    convw(pW2, 4096, 0,    0, lang_wih, 3072, 2048, G_, 1);
    convw(pW2, 4096, 2048, 0, lang_wih + 2048, 3072, 1024, G_, 1);
    convw(pW2, 4096, 3072, 0, lang_whh, 1024, 1024, G_, 1);
    convw(pW3, 2048, 0,    0, ar_wih, 1024, 1024, G_, 1);
    convw(pW3, 2048, 1024, 0, ar_whh, 1024, 1024, G_, 1);
    convw(pW3, 2048, 0, 4096, attd_w, 1024, 1024, A_, 0);
    convw(pWout, 1024, 0, 0, out_w, 1024, 1024, V_, 0);
    convw(pWarl, 1024, 0, 0, arl_w, 1024, 1024, D_, 0);

    // setup GEMMs
    bgemm<0>(p_favgW, nullptr, 0, pXfavg, 2048, pWfavg, 2048, p_tdbp,
             nullptr, nullptr, B_, G_, 2048, 0);
    bgemm<0>(p_xe1, nullptr, 0, pXebd, 1024, pWxe, 1024, nullptr,
             nullptr, nullptr, B_ * T_, G_, 1024, 0);
    add_favg_k<<<4096, 256>>>();
    zero_out_k<<<4096, 256>>>(out, (size_t)B_ * T_ * V_);

    // ---- sequential decode: 4 launches/step (ping-pong recurrent buffers) ----
    for (int t = 0; t < T_; ++t) {
        const int par = t & 1;
        bgemm<1>(nullptr, p_xe1 + (size_t)t * G_, T_ * G_,
                 pX1 + (size_t)par * B_ * 2048, 2048, pW1, 2048,
                 nullptr, nullptr, p_meta + t, B_, G_, 2048, t);
        bgemm<3>(nullptr, nullptr, 0,
                 pX3 + (size_t)par * B_ * 2048, 2048, pW3, 2048, p_b3q,
                 nullptr, p_meta + t, B_, 4608, 2048, t);
        attn_k<<<B_, 256>>>(att_w, att_b, t);
        bgemm<2>(nullptr, nullptr, 0,
                 pX2 + (size_t)par * B_ * 4096, 4096, pW2, 4096, p_langbp,
                 nullptr, p_meta + t, B_, G_, 4096, t);
    }

    // ---- batched tail (compacted rows) ----
    bgemm<0>(out, nullptr, 0, pH2c, 1024, pWout, 1024, out_b,
             p_actrow, p_meta + T_, B_ * T_, V_, 1024, 0);
    bgemm<0>(p_ARLc, nullptr, 0, pARNc, 1024, pWarl, 1024, arl_b,
             nullptr, p_meta + T_, B_ * T_, D_, 1024, 0);
    loss_rows_k<<<B_ * T_, 256>>>();
    loss_final_k<<<1, 256>>>(out);
}

// round 17
// speedup vs baseline: 4.7149x; 1.0084x over previous
#include <cuda_runtime.h>
#include <cuda_fp16.h>
#include <math.h>
#include <stdint.h>

#define B_ 256
#define N_ 36
#define F_ 2048
#define L_ 26
#define A_ 512
#define E_ 1024
#define D_ 1024
#define V_ 10000
#define T_ 25
#define G_ 4096
typedef __half hf;

// ---------------- fp32 state / scratch ----------------
__device__ __align__(256) float g_favgW[B_ * G_];
__device__ __align__(256) float g_xe1[(size_t)B_ * T_ * G_];
__device__ __align__(256) float g_imgatt[(size_t)B_ * N_ * A_];
__device__ __align__(256) float g_c1[B_ * D_], g_c2[B_ * D_], g_arc[B_ * D_], g_prevh1[B_ * D_];
__device__ __align__(256) float g_q[B_ * A_];
__device__ __align__(256) float g_PREVc[(size_t)B_ * T_ * D_];
__device__ __align__(256) float g_ARLc[(size_t)B_ * T_ * D_];
__device__ __align__(256) float g_rowss[B_ * T_];
__device__ __align__(256) float g_b3q[4608];
__device__ __align__(256) float g_tdb_p[G_];
__device__ __align__(256) float g_langb_p[G_];
__device__ int g_order[B_];
__device__ int g_declen[B_];
__device__ int g_actrow[B_ * T_];
__device__ int g_cidx[B_ * T_];
__device__ int g_meta[T_ + 1];
__device__ unsigned char g_act[B_ * T_];
// ---------------- fp16 operand buffers (recurrent ones double-buffered) ----------------
__device__ __align__(256) hf Xfs[(size_t)B_ * N_ * F_];
__device__ __align__(256) hf Xfavg[(size_t)B_ * F_];
__device__ __align__(256) hf Xebd[(size_t)B_ * T_ * E_];
__device__ __align__(256) hf X1b[2][(size_t)B_ * 2048];
__device__ __align__(256) hf X2b[2][(size_t)B_ * 4096];
__device__ __align__(256) hf X3b[2][(size_t)B_ * 2048];
__device__ __align__(256) hf H2c[(size_t)B_ * T_ * D_];
__device__ __align__(256) hf ARNc[(size_t)B_ * T_ * D_];
__device__ __align__(256) hf Wfavg[(size_t)G_ * F_];
__device__ __align__(256) hf Wxe[(size_t)G_ * E_];
__device__ __align__(256) hf W1p[(size_t)G_ * 2048];
__device__ __align__(256) hf W2p[(size_t)G_ * 4096];
__device__ __align__(256) hf W3p[(size_t)4608 * 2048];
__device__ __align__(256) hf Wattf[(size_t)A_ * F_];
__device__ __align__(256) hf Wout[(size_t)V_ * D_];
__device__ __align__(256) hf Warl[(size_t)D_ * D_];

__device__ __forceinline__ float sigm(float x) { return 1.f / (1.f + expf(-x)); }
__device__ __forceinline__ uint32_t smem_u32(const void* p) {
    uint32_t a;
    asm("{ .reg .u64 t; cvta.to.shared.u64 t, %1; cvt.u32.u64 %0, t; }" : "=r"(a) : "l"(p));
    return a;
}
__device__ __forceinline__ void cp16(uint32_t d, const void* s, bool ok) {
    asm volatile("cp.async.cg.shared.global [%0], [%1], 16, %2;" :: "r"(d), "l"(s), "r"(ok ? 16 : 0));
}
__device__ __forceinline__ void ldm_x4(uint32_t& r0, uint32_t& r1, uint32_t& r2, uint32_t& r3, uint32_t a) {
    asm volatile("ldmatrix.sync.aligned.m8n8.x4.shared.b16 {%0,%1,%2,%3}, [%4];"
                 : "=r"(r0), "=r"(r1), "=r"(r2), "=r"(r3) : "r"(a));
}
__device__ __forceinline__ void mma16816(float* c, const uint32_t* a, const uint32_t* b) {
    asm volatile("mma.sync.aligned.m16n8k16.row.col.f32.f16.f16.f32 "
                 "{%0,%1,%2,%3},{%4,%5,%6,%7},{%8,%9},{%0,%1,%2,%3};"
                 : "+f"(c[0]), "+f"(c[1]), "+f"(c[2]), "+f"(c[3])
                 : "r"(a[0]), "r"(a[1]), "r"(a[2]), "r"(a[3]), "r"(b[0]), "r"(b[1]));
}

// ======= 3-stage pipelined fp16 GEMM (128x64 tile, occ 3) with fused LSTM epilogues =======
// EPI: 0 plain (opt rowmap scatter), 1 LSTM1, 2 LSTM2, 3 LSTM3+q
#define SLD 40
#define NFR 4
template <int EPI>
__global__ void __launch_bounds__(256, 3) bgemm_k(
    float* __restrict__ C, const float* __restrict__ Cinit, int initLd,
    const hf* __restrict__ A, int lda, const hf* __restrict__ W, int ldw,
    const float* __restrict__ bias, const int* __restrict__ rowmap,
    const int* __restrict__ cntp, int M, int N, int K, int t)
{
    const int bm = blockIdx.y * 128, bn = blockIdx.x * 64;
    int nact = M;
    if (cntp) { nact = *cntp; if (bm >= nact) return; }
    __shared__ __align__(16) hf sA[3][128][SLD];
    __shared__ __align__(16) hf sW[3][64][SLD];
    const int tid = threadIdx.x, wid = tid >> 5, lane = tid & 31;
    const int wm = (wid & 3) * 32, wn = (wid >> 2) * 32;
    float c[2][NFR][4];
    #pragma unroll
    for (int i = 0; i < 2; ++i)
        #pragma unroll
        for (int j = 0; j < NFR; ++j)
            #pragma unroll
            for (int k = 0; k < 4; ++k) c[i][j][k] = 0.f;

    const int lrow = tid >> 1, lcol = (tid & 1) * 16;
    const bool aok = (bm + lrow) < M;
    const bool wdo = lrow < 64;
    const bool wok = wdo && (bn + lrow) < N;
    const hf* aptr = A + (size_t)(bm + lrow) * lda + lcol;
    const hf* wptr = W + (size_t)(bn + (wdo ? lrow : 0)) * ldw + lcol;
    const int nch = K >> 5;

    {
        uint32_t da = smem_u32(&sA[0][lrow][lcol]);
        cp16(da, aptr, aok); cp16(da + 16, aptr + 8, aok);
        if (wdo) {
            uint32_t dw = smem_u32(&sW[0][lrow][lcol]);
            cp16(dw, wptr, wok); cp16(dw + 16, wptr + 8, wok);
        }
        asm volatile("cp.async.commit_group;" ::: "memory");
    }
    if (nch > 1) {
        uint32_t da = smem_u32(&sA[1][lrow][lcol]);
        cp16(da, aptr + 32, aok); cp16(da + 16, aptr + 40, aok);
        if (wdo) {
            uint32_t dw = smem_u32(&sW[1][lrow][lcol]);
            cp16(dw, wptr + 32, wok); cp16(dw + 16, wptr + 40, wok);
        }
        asm volatile("cp.async.commit_group;" ::: "memory");
    }

    int st = 0, pf = 2;
    for (int ch = 0; ch < nch; ++ch) {
        if (ch + 1 < nch) asm volatile("cp.async.wait_group 1;" ::: "memory");
        else              asm volatile("cp.async.wait_group 0;" ::: "memory");
        __syncthreads();
        if (ch + 2 < nch) {
            const hf* as = aptr + (ch + 2) * 32;
            uint32_t da = smem_u32(&sA[pf][lrow][lcol]);
            cp16(da, as, aok); cp16(da + 16, as + 8, aok);
            if (wdo) {
                const hf* ws = wptr + (ch + 2) * 32;
                uint32_t dw = smem_u32(&sW[pf][lrow][lcol]);
                cp16(dw, ws, wok); cp16(dw + 16, ws + 8, wok);
            }
            asm volatile("cp.async.commit_group;" ::: "memory");
        }
        #pragma unroll
        for (int ks = 0; ks < 2; ++ks) {
            const int k0 = ks * 16;
            uint32_t Af[2][4], Bf[NFR][2];
            const int arw = (lane & 15), akc = k0 + ((lane >> 4) << 3);
            #pragma unroll
            for (int mf = 0; mf < 2; ++mf)
                ldm_x4(Af[mf][0], Af[mf][1], Af[mf][2], Af[mf][3], smem_u32(&sA[st][wm + mf * 16 + arw][akc]));
            const int bnf = (lane >> 4) & 1, bkh = (lane >> 3) & 1, brw2 = lane & 7;
            #pragma unroll
            for (int nfp = 0; nfp < NFR; nfp += 2) {
                int r = wn + (nfp + bnf) * 8 + brw2;
                int kc = k0 + bkh * 8;
                ldm_x4(Bf[nfp][0], Bf[nfp][1], Bf[nfp + 1][0], Bf[nfp + 1][1],
                       smem_u32(&sW[st][r][kc]));
            }
            #pragma unroll
            for (int mf = 0; mf < 2; ++mf)
                #pragma unroll
                for (int nf = 0; nf < NFR; ++nf) mma16816(c[mf][nf], Af[mf], Bf[nf]);
        }
        st = (st == 2) ? 0 : st + 1;
        pf = (pf == 2) ? 0 : pf + 1;
    }

    // ---- epilogue ----
    const int par = t & 1, nxt = par ^ 1;
    #pragma unroll
    for (int mf = 0; mf < 2; ++mf) {
        #pragma unroll
        for (int half = 0; half < 2; ++half) {
            const int m = bm + wm + mf * 16 + (lane >> 2) + half * 8;
            const bool mok = (m < M) && (m < nact);
            #pragma unroll
            for (int nf = 0; nf < NFR; ++nf) {
                const int n0 = bn + wn + nf * 8 + (lane & 3) * 2;
                float v0 = c[mf][nf][half * 2 + 0];
                float v1 = c[mf][nf][half * 2 + 1];
                if (EPI == 0) {
                    if (mok) {
                        int mrow = rowmap ? rowmap[m] : m;
                        #pragma unroll
                        for (int e = 0; e < 2; ++e) {
                            int n = n0 + e;
                            if (n >= N) break;
                            float v = (e == 0) ? v0 : v1;
                            if (bias) v += bias[n];
                            if (Cinit) v += Cinit[(size_t)m * initLd + n];
                            C[(size_t)mrow * N + n] = v;
                        }
                    }
                } else {
                    if (Cinit && mok) {
                        v0 += Cinit[(size_t)m * initLd + n0];
                        v1 += Cinit[(size_t)m * initLd + n0 + 1];
                    }
                    if (bias) { v0 += bias[n0]; v1 += bias[n0 + 1]; }
                    float o0 = __shfl_xor_sync(0xffffffffu, v0, 1);
                    float o1 = __shfl_xor_sync(0xffffffffu, v1, 1);
                    if (EPI == 3 && n0 >= 4096) {
                        if (mok) {
                            g_q[(size_t)m * A_ + (n0 - 4096)] = v0;
                            g_q[(size_t)m * A_ + (n0 - 4095)] = v1;
                        }
                    } else if ((lane & 1) == 0 && mok) {
                        int d = n0 >> 2;
                        int idx = m * D_ + d;
                        int r = m * T_ + t;
                        float ig = sigm(v0), fg = sigm(v1);
                        float gg = tanhf(o0), og = sigm(o1);
                        unsigned char act = g_act[r];
                        if (EPI == 1) {
                            float cn = fg * g_c1[idx] + ig * gg;
                            float h = og * tanhf(cn);
                            hf h16 = __float2half(h);
                            X2b[par][(size_t)m * 4096 + 2048 + d] = h16;
                            X3b[par][(size_t)m * 2048 + d] = h16;
                            if (act) {
                                g_PREVc[(size_t)g_cidx[r] * D_ + d] = g_prevh1[idx];
                                g_c1[idx] = cn; g_prevh1[idx] = h;
                                X1b[nxt][(size_t)m * 2048 + 1024 + d] = h16;
                            }
                        } else if (EPI == 2) {
                            float cn = fg * g_c2[idx] + ig * gg;
                            float h = og * tanhf(cn);
                            hf h16 = __float2half(h);
                            if (act) {
                                g_c2[idx] = cn;
                                X1b[nxt][(size_t)m * 2048 + d] = h16;
                                X2b[nxt][(size_t)m * 4096 + 3072 + d] = h16;
                                H2c[(size_t)g_cidx[r] * D_ + d] = h16;
                            }
                        } else {  // EPI == 3
                            float cn = fg * g_arc[idx] + ig * gg;
                            float h = og * tanhf(cn);
                            hf h16 = __float2half(h);
                            if (act) {
                                g_arc[idx] = cn;
                                ARNc[(size_t)g_cidx[r] * D_ + d] = h16;
                                X3b[nxt][(size_t)m * 2048 + 1024 + d] = h16;
                            }
                        }
                    }
                }
            }
        }
    }
}

// ---------------- weight fp16 conversion (opt gate interleave) ----------------
__global__ void convw_k(hf* __restrict__ dst, int Ktot, int dstOff, int rowOff,
                        const float* __restrict__ src, int lds, int segK, int nrows, int perm) {
    size_t total = (size_t)nrows * segK;
    for (size_t i = (size_t)blockIdx.x * blockDim.x + threadIdx.x; i < total;
         i += (size_t)gridDim.x * blockDim.x) {
        int n = (int)(i / segK), k = (int)(i - (size_t)n * segK);
        int nd = perm ? (4 * (n & 1023) + (n >> 10)) : n;
        dst[(size_t)(nd + rowOff) * Ktot + dstOff + k] = __float2half(src[(size_t)n * lds + k]);
    }
}
__global__ void zeroh_k(hf* p, size_t n) {
    for (size_t i = (size_t)blockIdx.x * blockDim.x + threadIdx.x; i < n;
         i += (size_t)gridDim.x * blockDim.x) p[i] = __float2half(0.f);
}
// zero a strided 2D region: rows [r0, r0+nr), cols [c0, c0+nc) of pitch-ld array
__global__ void zeroh2d_k(hf* p, int ld, int r0, int c0, int nr, int nc) {
    size_t total = (size_t)nr * nc;
    for (size_t i = (size_t)blockIdx.x * blockDim.x + threadIdx.x; i < total;
         i += (size_t)gridDim.x * blockDim.x) {
        int r = (int)(i / nc), cc = (int)(i - (size_t)r * nc);
        p[(size_t)(r0 + r) * ld + c0 + cc] = __float2half(0.f);
    }
}
__global__ void zero_out_k(float* p, size_t n) {
    size_t n4 = n >> 2;
    for (size_t i = (size_t)blockIdx.x * blockDim.x + threadIdx.x; i < n4;
         i += (size_t)gridDim.x * blockDim.x) ((float4*)p)[i] = make_float4(0, 0, 0, 0);
}
__global__ void permb_k(const float* __restrict__ tdb, const float* __restrict__ langb,
                        const float* __restrict__ arb, const float* __restrict__ attdb) {
    int i = blockIdx.x * blockDim.x + threadIdx.x;
    if (i < G_) {
        int pd = 4 * (i & 1023) + (i >> 10);
        g_tdb_p[pd] = tdb[i];
        g_langb_p[pd] = langb[i];
        g_b3q[pd] = arb[i];
    } else if (i < 4608) {
        g_b3q[i] = attdb[i - G_];
    }
}

// ---------------- setup ----------------
__global__ void sort_k(const int* __restrict__ sizes) {
    __shared__ int s[B_];
    int i = threadIdx.x;
    s[i] = sizes[i];
    __syncthreads();
    int my = s[i], rank = 0;
    for (int j = 0; j < B_; ++j) { int sj = s[j]; if (sj > my || (sj == my && j < i)) rank++; }
    g_order[rank] = i;
    g_declen[rank] = my - 1;
}
__global__ void init_misc_k() {
    int idx = blockIdx.x * blockDim.x + threadIdx.x;
    if (idx < B_ * T_) {
        int b = idx / T_, t = idx - b * T_;
        g_act[idx] = (t < g_declen[b]) ? 1 : 0;
        g_rowss[idx] = 0.f;
    }
    if (idx < B_ * D_) { g_c1[idx] = 0.f; g_c2[idx] = 0.f; g_arc[idx] = 0.f; g_prevh1[idx] = 0.f; }
}
__global__ void scan_k() {
    if (threadIdx.x != 0) return;
    int j = 0;
    for (int r = 0; r < B_ * T_; ++r) {
        if (g_act[r]) { g_cidx[r] = j; g_actrow[j] = r; j++; }
        else g_cidx[r] = -1;
    }
    g_meta[T_] = j;
    for (int t = 0; t < T_; ++t) {
        int cnt = 0;
        for (int b = 0; b < B_; ++b) cnt += g_act[b * T_ + t];
        g_meta[t] = cnt;
    }
}
__global__ void gather_fs_k(const float* __restrict__ feats) {
    const size_t NF_ = (size_t)N_ * F_;
    size_t total = (size_t)B_ * NF_ / 2;
    for (size_t i = (size_t)blockIdx.x * blockDim.x + threadIdx.x; i < total;
         i += (size_t)gridDim.x * blockDim.x) {
        int b = (int)(i / (NF_ / 2));
        size_t rem = i - (size_t)b * (NF_ / 2);
        const float2 v = ((const float2*)(feats + (size_t)g_order[b] * NF_))[rem];
        ((half2*)Xfs)[i] = __floats2half2_rn(v.x, v.y);
    }
}
__global__ void favg_k(const float* __restrict__ feats) {
    int idx = blockIdx.x * blockDim.x + threadIdx.x;
    if (idx < B_ * F_) {
        int b = idx / F_, f = idx - b * F_;
        const float* base = feats + (size_t)g_order[b] * N_ * F_ + f;
        float s = 0.f;
        #pragma unroll
        for (int n = 0; n < N_; ++n) s += base[(size_t)n * F_];
        Xfavg[idx] = __float2half(s * (1.f / N_));
    }
}
__global__ void gather_ebd_k(const int* __restrict__ seqs, const float* __restrict__ emb) {
    size_t total = (size_t)B_ * T_ * E_;
    for (size_t i = (size_t)blockIdx.x * blockDim.x + threadIdx.x; i < total;
         i += (size_t)gridDim.x * blockDim.x) {
        int r = (int)(i / E_), e = (int)(i - (size_t)r * E_);
        int b = r / T_, t = r - b * T_;
        Xebd[i] = __float2half(emb[(size_t)seqs[g_order[b] * L_ + t] * E_ + e]);
    }
}
__global__ void add_favg_k() {
    const int per_r = G_ / 4;
    size_t total = (size_t)B_ * T_ * per_r;
    for (size_t i = (size_t)blockIdx.x * blockDim.x + threadIdx.x; i < total;
         i += (size_t)gridDim.x * blockDim.x) {
        int r = (int)(i / per_r), g4 = (int)(i - (size_t)r * per_r);
        float4 x = ((float4*)g_xe1)[i];
        float4 a = ((const float4*)g_favgW)[(size_t)(r / T_) * per_r + g4];
        x.x += a.x; x.y += a.y; x.z += a.z; x.w += a.w;
        ((float4*)g_xe1)[i] = x;
    }
}

// ---------------- attention (fp16 feature reads, fp32 accumulate) ----------------
__global__ void attn_k(const float* __restrict__ attw, const float* __restrict__ attb, int t) {
    int b = blockIdx.x;
    int tid = threadIdx.x, warp = tid >> 5, lane = tid & 31;
    __shared__ float s_q[A_], s_w[A_], s_sc[N_], s_alpha[N_];
    for (int i = tid; i < A_; i += 256) { s_q[i] = g_q[b * A_ + i]; s_w[i] = attw[i]; }
    __syncthreads();
    for (int n = warp; n < N_; n += 8) {
        const float* row = g_imgatt + ((size_t)b * N_ + n) * A_;
        float p = 0.f;
        for (int a = lane; a < A_; a += 32) { float v = s_q[a] + row[a]; p += fmaxf(v, 0.f) * s_w[a]; }
        #pragma unroll
        for (int o = 16; o; o >>= 1) p += __shfl_xor_sync(0xffffffffu, p, o);
        if (lane == 0) s_sc[n] = p + attb[0];
    }
    __syncthreads();
    if (warp == 0) {
        float v0 = s_sc[lane], v1 = (lane + 32 < N_) ? s_sc[lane + 32] : -1e30f;
        float mx = fmaxf(v0, v1);
        #pragma unroll
        for (int o = 16; o; o >>= 1) mx = fmaxf(mx, __shfl_xor_sync(0xffffffffu, mx, o));
        float e0 = expf(v0 - mx), e1 = (lane + 32 < N_) ? expf(v1 - mx) : 0.f;
        float s = e0 + e1;
        #pragma unroll
        for (int o = 16; o; o >>= 1) s += __shfl_xor_sync(0xffffffffu, s, o);
        s_alpha[lane] = e0 / s;
        if (lane + 32 < N_) s_alpha[lane + 32] = e1 / s;
    }
    __syncthreads();
    half2* x2 = (half2*)(X2b[t & 1] + (size_t)b * 4096);
    const half2* fb = (const half2*)(Xfs + (size_t)b * N_ * F_);
    for (int f2 = tid; f2 < F_ / 2; f2 += 256) {
        float a0 = 0.f, a1 = 0.f;
        #pragma unroll
        for (int n = 0; n < N_; ++n) {
            float2 vf = __half22float2(fb[(size_t)n * (F_ / 2) + f2]);
            a0 += s_alpha[n] * vf.x;
            a1 += s_alpha[n] * vf.y;
        }
        x2[f2] = __floats2half2_rn(a0, a1);
    }
}

// ---------------- loss (compacted rows) ----------------
__global__ void loss_rows_k() {
    int j = blockIdx.x;
    if (j >= g_meta[T_]) return;
    int r = g_actrow[j], t = r % T_;
    if (t == 0) return;
    int tid = threadIdx.x;
    float p = 0.f;
    const float* a = g_ARLc + (size_t)j * D_;
    const float* pv = g_PREVc + (size_t)j * D_;
    for (int d = tid; d < D_; d += 256) { float df = a[d] - pv[d]; p += df * df; }
    __shared__ float sred[256];
    sred[tid] = p;
    __syncthreads();
    for (int o = 128; o; o >>= 1) { if (tid < o) sred[tid] += sred[tid + o]; __syncthreads(); }
    if (tid == 0) g_rowss[r] = sred[0];
}
__global__ void loss_final_k(float* __restrict__ out) {
    __shared__ float ss[256], sc[256];
    int tid = threadIdx.x;
    float total = 0.f;
    for (int t = 1; t < T_; ++t) {
        float s = 0.f, c = 0.f;
        for (int b = tid; b < B_; b += 256) {
            s += g_rowss[b * T_ + t];
            c += g_act[b * T_ + t] ? 1.f : 0.f;
        }
        ss[tid] = s; sc[tid] = c;
        __syncthreads();
        for (int o = 128; o; o >>= 1) { if (tid < o) { ss[tid] += ss[tid + o]; sc[tid] += sc[tid + o]; } __syncthreads(); }
        if (tid == 0) total += ss[0] / fmaxf(sc[0], 1.f) * 0.005f;
        __syncthreads();
    }
    if (tid == 0) out[(size_t)B_ * T_ * V_] = total;
}

// ---------------- host ----------------
static inline float* fsym(const void* s) { void* p = nullptr; cudaGetSymbolAddress(&p, s); return (float*)p; }
static inline hf* hsym(const void* s) { void* p = nullptr; cudaGetSymbolAddress(&p, s); return (hf*)p; }
static inline int* isym(const void* s) { void* p = nullptr; cudaGetSymbolAddress(&p, s); return (int*)p; }

template <int EPI>
static inline void bgemm(float* C, const float* Cinit, int initLd,
                         const hf* A, int lda, const hf* W, int ldw,
                         const float* bias, const int* rowmap, const int* cntp,
                         int M, int N, int K, int t) {
    dim3 grid((N + 63) / 64, (M + 127) / 128);
    bgemm_k<EPI><<<grid, 256>>>(C, Cinit, initLd, A, lda, W, ldw, bias, rowmap, cntp, M, N, K, t);
}
static inline void convw(hf* dst, int Ktot, int dstOff, int rowOff,
                         const float* src, int lds, int segK, int nrows, int perm) {
    convw_k<<<2048, 256>>>(dst, Ktot, dstOff, rowOff, src, lds, segK, nrows, perm);
}

extern "C" void kernel_launch(void* const* d_in, const int* in_sizes, int n_in,
                              void* d_out, int out_size) {
    const float* feats     = (const float*)d_in[0];
    const int*   sequences = (const int*)d_in[1];
    const int*   sizes     = (const int*)d_in[2];
    const float* emb       = (const float*)d_in[3];
    const float* td_wih    = (const float*)d_in[4];
    const float* td_whh    = (const float*)d_in[5];
    const float* td_b      = (const float*)d_in[6];
    const float* lang_wih  = (const float*)d_in[7];
    const float* lang_whh  = (const float*)d_in[8];
    const float* lang_b    = (const float*)d_in[9];
    const float* attf_w    = (const float*)d_in[10];
    const float* attf_b    = (const float*)d_in[11];
    const float* attd_w    = (const float*)d_in[12];
    const float* attd_b    = (const float*)d_in[13];
    const float* att_w     = (const float*)d_in[14];
    const float* att_b     = (const float*)d_in[15];
    const float* out_w     = (const float*)d_in[16];
    const float* out_b     = (const float*)d_in[17];
    const float* ar_wih    = (const float*)d_in[18];
    const float* ar_whh    = (const float*)d_in[19];
    const float* ar_b      = (const float*)d_in[20];
    const float* arl_w     = (const float*)d_in[21];
    const float* arl_b     = (const float*)d_in[22];
    float* out = (float*)d_out;

    float* p_favgW  = fsym(g_favgW);
    float* p_xe1    = fsym(g_xe1);
    float* p_imgatt = fsym(g_imgatt);
    float* p_ARLc   = fsym(g_ARLc);
    float* p_b3q    = fsym(g_b3q);
    float* p_tdbp   = fsym(g_tdb_p);
    float* p_langbp = fsym(g_langb_p);
    hf *pXfs = hsym(Xfs), *pXfavg = hsym(Xfavg), *pXebd = hsym(Xebd);
    hf *pX1 = hsym(X1b), *pX2 = hsym(X2b), *pX3 = hsym(X3b);
    hf *pH2c = hsym(H2c), *pARNc = hsym(ARNc);
    hf *pWfavg = hsym(Wfavg), *pWxe = hsym(Wxe), *pW1 = hsym(W1p), *pW2 = hsym(W2p), *pW3 = hsym(W3p);
    hf *pWattf = hsym(Wattf), *pWout = hsym(Wout), *pWarl = hsym(Warl);
    int* p_meta   = isym(g_meta);
    int* p_actrow = isym(g_actrow);

    // ---- setup (launch #4 = imgatt GEMM, the slot ncu captures) ----
    sort_k<<<1, B_>>>(sizes);                                   // 1
    gather_fs_k<<<4096, 256>>>(feats);                          // 2
    convw(pWattf, 2048, 0, 0, attf_w, 2048, 2048, A_, 0);       // 3
    bgemm<0>(p_imgatt, nullptr, 0, pXfs, 2048, pWattf, 2048, attf_b,
             nullptr, nullptr, B_ * N_, A_, 2048, 0);           // 4 (profiled)
    init_misc_k<<<(B_ * D_ + 255) / 256, 256>>>();
    scan_k<<<1, 32>>>();
    zeroh_k<<<2048, 256>>>(pX1, (size_t)2 * B_ * 2048);
    zeroh_k<<<2048, 256>>>(pX2, (size_t)2 * B_ * 4096);
    zeroh_k<<<2048, 256>>>(pX3, (size_t)2 * B_ * 2048);
    zeroh2d_k<<<512, 256>>>(pW3, 2048, 4096, 1024, 512, 1024);  // q-rows arh seg only
    favg_k<<<(B_ * F_ + 255) / 256, 256>>>(feats);
    gather_ebd_k<<<4096, 256>>>(sequences, emb);
    permb_k<<<(4608 + 255) / 256, 256>>>(td_b, lang_b, ar_b, attd_b);

    // weights (gate-interleaved where epilogue-fused)
    convw(pWfavg, 2048, 0, 0, td_wih + 1024, 4096, 2048, G_, 1);
    convw(pWxe,   1024, 0, 0, td_wih + 3072, 4096, 1024, G_, 1);
    convw(pW1, 2048, 0,    0, td_wih, 4096, 1024, G_, 1);
    convw(pW1, 2048, 1024, 0, td_whh, 1024, 1024, G_, 1);
    convw(pW2, 4096, 0,    0, lang_wih, 3072, 2048, G_, 1);
    convw(pW2, 4096, 2048, 0, lang_wih + 2048, 3072, 1024, G_, 1);
    convw(pW2, 4096, 3072, 0, lang_whh, 1024, 1024, G_, 1);
    convw(pW3, 2048, 0,    0, ar_wih, 1024, 1024, G_, 1);
    convw(pW3, 2048, 1024, 0, ar_whh, 1024, 1024, G_, 1);
    convw(pW3, 2048, 0, 4096, attd_w, 1024, 1024, A_, 0);
    convw(pWout, 1024, 0, 0, out_w, 1024, 1024, V_, 0);
    convw(pWarl, 1024, 0, 0, arl_w, 1024, 1024, D_, 0);

    // setup GEMMs
    bgemm<0>(p_favgW, nullptr, 0, pXfavg, 2048, pWfavg, 2048, p_tdbp,
             nullptr, nullptr, B_, G_, 2048, 0);
    bgemm<0>(p_xe1, nullptr, 0, pXebd, 1024, pWxe, 1024, nullptr,
             nullptr, nullptr, B_ * T_, G_, 1024, 0);
    add_favg_k<<<4096, 256>>>();
    zero_out_k<<<4096, 256>>>(out, (size_t)B_ * T_ * V_);

    // ---- sequential decode: 4 launches/step (ping-pong recurrent buffers) ----
    for (int t = 0; t < T_; ++t) {
        const int par = t & 1;
        bgemm<1>(nullptr, p_xe1 + (size_t)t * G_, T_ * G_,
                 pX1 + (size_t)par * B_ * 2048, 2048, pW1, 2048,
                 nullptr, nullptr, p_meta + t, B_, G_, 2048, t);
        bgemm<3>(nullptr, nullptr, 0,
                 pX3 + (size_t)par * B_ * 2048, 2048, pW3, 2048, p_b3q,
                 nullptr, p_meta + t, B_, 4608, 2048, t);
        attn_k<<<B_, 256>>>(att_w, att_b, t);
        bgemm<2>(nullptr, nullptr, 0,
                 pX2 + (size_t)par * B_ * 4096, 4096, pW2, 4096, p_langbp,
                 nullptr, p_meta + t, B_, G_, 4096, t);
    }

    // ---- batched tail (compacted rows) ----
    bgemm<0>(out, nullptr, 0, pH2c, 1024, pWout, 1024, out_b,
             p_actrow, p_meta + T_, B_ * T_, V_, 1024, 0);
    bgemm<0>(p_ARLc, nullptr, 0, pARNc, 1024, pWarl, 1024, arl_b,
             nullptr, p_meta + T_, B_ * T_, D_, 1024, 0);
    loss_rows_k<<<B_ * T_, 256>>>();
    loss_final_k<<<1, 256>>>(out);
}